// round 1
// baseline (speedup 1.0000x reference)
#include <cuda_runtime.h>

#define N_ROWS   4096
#define N_FEAT   512
#define N_HID    64
#define N_CLASS  16
#define N_HEADS  8

// ---------------- scratch (static device memory; no allocations) ----------------
__device__ float g_h1   [N_HEADS*N_ROWS*N_HID];
__device__ float g_ssrc1[N_HEADS*N_ROWS];
__device__ float g_sdst1[N_HEADS*N_ROWS];
__device__ float g_sorted1[N_HEADS*N_ROWS];
__device__ int   g_idx1 [N_HEADS*N_ROWS];
__device__ float g_ew1  [N_HEADS*N_ROWS];
__device__ float g_gw1  [N_HEADS*N_ROWS];
__device__ float g_Zhi1 [N_HEADS*(N_ROWS+1)];
__device__ float g_Zlo1 [N_HEADS*(N_ROWS+1)];
__device__ float g_hperm1[N_HEADS*N_ROWS*N_HID];
__device__ float g_Phi1 [N_HEADS*N_HID*(N_ROWS+1)];
__device__ float g_Plo1 [N_HEADS*N_HID*(N_ROWS+1)];
__device__ float g_xc   [N_ROWS*N_FEAT];

__device__ float g_h2   [N_ROWS*N_CLASS];
__device__ float g_ssrc2[N_ROWS];
__device__ float g_sdst2[N_ROWS];
__device__ float g_sorted2[N_ROWS];
__device__ int   g_idx2 [N_ROWS];
__device__ float g_ew2  [N_ROWS];
__device__ float g_gw2  [N_ROWS];
__device__ float g_Zhi2 [N_ROWS+1];
__device__ float g_Zlo2 [N_ROWS+1];
__device__ float g_hperm2[N_ROWS*N_CLASS];
__device__ float g_Phi2 [N_CLASS*(N_ROWS+1)];
__device__ float g_Plo2 [N_CLASS*(N_ROWS+1)];

// ---------------- block scan helper ----------------
// Exclusive prefix (rev=false) or exclusive suffix (rev=true) over per-thread
// partials. NT = blockDim.x. sh must hold NT floats.
template<int NT>
__device__ __forceinline__ float blk_excl_scan(float v, float* sh, bool rev) {
    int t = rev ? (NT - 1 - (int)threadIdx.x) : (int)threadIdx.x;
    sh[t] = v;
    __syncthreads();
    for (int off = 1; off < NT; off <<= 1) {
        float add = (t >= off) ? sh[t - off] : 0.f;
        __syncthreads();
        sh[t] += add;
        __syncthreads();
    }
    float incl = sh[t];
    __syncthreads();
    return incl - v;
}

// ---------------- GEMM1: h1[h][i][f] = sum_k x[i][k] * Wh[h][k][f] ----------------
// BM=128 rows, full F=64 cols, BK=16; 256 threads; 8x4 per thread.
__global__ __launch_bounds__(256) void gemm1_kernel(
    const float* __restrict__ x, const float* __restrict__ Wh, float* __restrict__ h1)
{
    const int BM = 128, BK = 16;
    __shared__ float As[BK][BM + 4];   // [k][i], padded
    __shared__ float Bs[BK][N_HID];    // [k][f]
    int h = blockIdx.y;
    int row0 = blockIdx.x * BM;
    const float* W = Wh + (size_t)h * N_FEAT * N_HID;
    int tid = threadIdx.x;
    int tx = tid & 15, ty = tid >> 4;

    float acc[8][4];
#pragma unroll
    for (int m = 0; m < 8; m++)
#pragma unroll
        for (int n = 0; n < 4; n++) acc[m][n] = 0.f;

    for (int k0 = 0; k0 < N_FEAT; k0 += BK) {
#pragma unroll
        for (int rep = 0; rep < 8; rep++) {
            int i = (tid >> 4) + rep * 16;
            int kk = tid & 15;
            As[kk][i] = x[(size_t)(row0 + i) * N_FEAT + k0 + kk];
        }
#pragma unroll
        for (int rep = 0; rep < 4; rep++) {
            int kk = (tid >> 6) + rep * 4;
            int f = tid & 63;
            Bs[kk][f] = W[(size_t)(k0 + kk) * N_HID + f];
        }
        __syncthreads();
#pragma unroll
        for (int kk = 0; kk < BK; kk++) {
            float4 b4  = *reinterpret_cast<const float4*>(&Bs[kk][tx * 4]);
            float4 a4l = *reinterpret_cast<const float4*>(&As[kk][ty * 8]);
            float4 a4h = *reinterpret_cast<const float4*>(&As[kk][ty * 8 + 4]);
            float av[8] = {a4l.x, a4l.y, a4l.z, a4l.w, a4h.x, a4h.y, a4h.z, a4h.w};
            float bv[4] = {b4.x, b4.y, b4.z, b4.w};
#pragma unroll
            for (int m = 0; m < 8; m++)
#pragma unroll
                for (int n = 0; n < 4; n++) acc[m][n] += av[m] * bv[n];
        }
        __syncthreads();
    }
#pragma unroll
    for (int m = 0; m < 8; m++) {
        int row = row0 + ty * 8 + m;
        float4 o = make_float4(acc[m][0], acc[m][1], acc[m][2], acc[m][3]);
        *reinterpret_cast<float4*>(&h1[((size_t)h * N_ROWS + row) * N_HID + tx * 4]) = o;
    }
}

// ---------------- scores1: s_src/s_dst per (head,row) ----------------
__global__ void scores1_kernel(const float* __restrict__ h1, const float* __restrict__ ah,
                               float* __restrict__ ssrc, float* __restrict__ sdst)
{
    int h = blockIdx.y;
    int warp = threadIdx.x >> 5, lane = threadIdx.x & 31;
    int i = blockIdx.x * 8 + warp;
    const float* row = h1 + ((size_t)h * N_ROWS + i) * N_HID;
    const float* a = ah + (size_t)h * 2 * N_HID;
    float v1 = row[lane], v2 = row[lane + 32];
    float ps = v1 * a[lane] + v2 * a[lane + 32];
    float pd = v1 * a[N_HID + lane] + v2 * a[N_HID + lane + 32];
#pragma unroll
    for (int off = 16; off; off >>= 1) {
        ps += __shfl_xor_sync(0xffffffffu, ps, off);
        pd += __shfl_xor_sync(0xffffffffu, pd, off);
    }
    if (lane == 0) {
        ssrc[(size_t)h * N_ROWS + i] = ps;
        sdst[(size_t)h * N_ROWS + i] = pd;
    }
}

// ---------------- bitonic sort (descending) of 4096 per block ----------------
__global__ __launch_bounds__(1024) void sort_kernel(
    const float* __restrict__ sdst, float* __restrict__ sorted, int* __restrict__ idx)
{
    int h = blockIdx.x;
    __shared__ float v[N_ROWS];
    __shared__ int   id[N_ROWS];
    for (int t = threadIdx.x; t < N_ROWS; t += blockDim.x) {
        v[t] = sdst[(size_t)h * N_ROWS + t];
        id[t] = t;
    }
    __syncthreads();
    for (int k = 2; k <= N_ROWS; k <<= 1) {
        for (int j = k >> 1; j > 0; j >>= 1) {
            for (int t = threadIdx.x; t < N_ROWS; t += blockDim.x) {
                int ixj = t ^ j;
                if (ixj > t) {
                    float a = v[t], b = v[ixj];
                    bool descRegion = ((t & k) == 0);  // overall descending
                    if (descRegion ? (a < b) : (a > b)) {
                        v[t] = b; v[ixj] = a;
                        int ta = id[t]; id[t] = id[ixj]; id[ixj] = ta;
                    }
                }
            }
            __syncthreads();
        }
    }
    for (int t = threadIdx.x; t < N_ROWS; t += blockDim.x) {
        sorted[(size_t)h * N_ROWS + t] = v[t];
        idx[(size_t)h * N_ROWS + t] = id[t];
    }
}

// ---------------- scalar scan: exp weights + Zhi prefix / Zlo suffix ----------------
__global__ __launch_bounds__(1024) void scalar_scan_kernel(
    const float* __restrict__ sorted, float* __restrict__ ew, float* __restrict__ gw,
    float* __restrict__ Zhi, float* __restrict__ Zlo)
{
    int h = blockIdx.x;
    const float* d = sorted + (size_t)h * N_ROWS;
    float M = d[0];
    __shared__ float sh[1024];
    int t = threadIdx.x;
    float e[4], g[4];
    float se = 0.f, sg = 0.f;
#pragma unroll
    for (int j = 0; j < 4; j++) {
        int r = t * 4 + j;
        float xv = d[r] - M;
        e[j] = expf(xv);
        g[j] = expf(0.2f * xv);
        se += e[j]; sg += g[j];
        ew[(size_t)h * N_ROWS + r] = e[j];
        gw[(size_t)h * N_ROWS + r] = g[j];
    }
    float excl = blk_excl_scan<1024>(se, sh, false);
    float suff = blk_excl_scan<1024>(sg, sh, true);
    float run = excl;
#pragma unroll
    for (int j = 0; j < 4; j++) {
        Zhi[(size_t)h * (N_ROWS + 1) + t * 4 + j] = run;
        run += e[j];
    }
    if (t == 1023) Zhi[(size_t)h * (N_ROWS + 1) + N_ROWS] = run;
    float run2 = suff;
#pragma unroll
    for (int j = 3; j >= 0; j--) {
        run2 += g[j];
        Zlo[(size_t)h * (N_ROWS + 1) + t * 4 + j] = run2;
    }
    if (t == 0) Zlo[(size_t)h * (N_ROWS + 1) + N_ROWS] = 0.f;
}

// ---------------- permute rows of h into sorted order ----------------
__global__ void permute_kernel(const float* __restrict__ hsrc, const int* __restrict__ idx,
                               float* __restrict__ hperm, int F)
{
    int h = blockIdx.y;
    int rpb = blockDim.x / F;
    int r = blockIdx.x * rpb + threadIdx.x / F;
    int f = threadIdx.x % F;
    int src = idx[(size_t)h * N_ROWS + r];
    hperm[((size_t)h * N_ROWS + r) * F + f] = hsrc[((size_t)h * N_ROWS + src) * F + f];
}

// ---------------- per-feature scans: Phi prefix / Plo suffix ----------------
__global__ __launch_bounds__(256) void feat_scan_kernel(
    const float* __restrict__ hperm, const float* __restrict__ ew, const float* __restrict__ gw,
    float* __restrict__ Phi, float* __restrict__ Plo, int F)
{
    int f = blockIdx.x, h = blockIdx.y;
    const float* hp = hperm + (size_t)h * N_ROWS * F + f;
    const float* E = ew + (size_t)h * N_ROWS;
    const float* G = gw + (size_t)h * N_ROWS;
    float* PH = Phi + (size_t)(h * F + f) * (N_ROWS + 1);
    float* PL = Plo + (size_t)(h * F + f) * (N_ROWS + 1);
    __shared__ float sh[256];
    int t = threadIdx.x;
    float vh[16], vl[16];
    float shi = 0.f, slo = 0.f;
#pragma unroll
    for (int j = 0; j < 16; j++) {
        int r = t * 16 + j;
        float a = hp[(size_t)r * F];
        vh[j] = a * E[r];
        vl[j] = a * G[r];
        shi += vh[j]; slo += vl[j];
    }
    float excl = blk_excl_scan<256>(shi, sh, false);
    float suff = blk_excl_scan<256>(slo, sh, true);
    float run = excl;
#pragma unroll
    for (int j = 0; j < 16; j++) {
        PH[t * 16 + j] = run;
        run += vh[j];
    }
    if (t == 255) PH[N_ROWS] = run;
    float run2 = suff;
#pragma unroll
    for (int j = 15; j >= 0; j--) {
        run2 += vl[j];
        PL[t * 16 + j] = run2;
    }
    if (t == 0) PL[N_ROWS] = 0.f;
}

// ---------------- combine layer1: per-row gather + ELU, write xc ----------------
__global__ void combine1_kernel(
    const float* __restrict__ ssrc, const float* __restrict__ sorted,
    const float* __restrict__ Zhi, const float* __restrict__ Zlo,
    const float* __restrict__ Phi, const float* __restrict__ Plo,
    float* __restrict__ xc)
{
    int h = blockIdx.y;
    int warp = threadIdx.x >> 5, lane = threadIdx.x & 31;
    int i = blockIdx.x * 8 + warp;
    const float* d = sorted + (size_t)h * N_ROWS;
    float s = ssrc[(size_t)h * N_ROWS + i];
    float thr = -s;
    int lo = 0, hi = N_ROWS;
    while (lo < hi) {
        int mid = (lo + hi) >> 1;
        if (d[mid] >= thr) lo = mid + 1; else hi = mid;
    }
    int k = lo;
    float M = d[0];
    float rho = expf(-0.8f * (s + M));  // k>0 implies s+M>=0 -> rho<=1
    float den;
    if (k == 0) den = Zlo[(size_t)h * (N_ROWS + 1)];
    else        den = Zhi[(size_t)h * (N_ROWS + 1) + k] + rho * Zlo[(size_t)h * (N_ROWS + 1) + k];
    float inv = 1.f / den;
#pragma unroll
    for (int u = 0; u < 2; u++) {
        int f = lane + 32 * u;
        size_t base = (size_t)(h * N_HID + f) * (N_ROWS + 1);
        float num = (k == 0) ? Plo[base] : (Phi[base + k] + rho * Plo[base + k]);
        float feat = num * inv;
        float v = feat > 0.f ? feat : expm1f(feat);  // ELU
        xc[(size_t)i * N_FEAT + h * N_HID + f] = v;
    }
}

// ---------------- GEMM2: h2 = xc @ Wo ----------------
__global__ __launch_bounds__(256) void gemm2_kernel(
    const float* __restrict__ xc, const float* __restrict__ Wo, float* __restrict__ h2)
{
    __shared__ float xs[16][64];
    __shared__ float ws[64][16];
    int ir = threadIdx.x >> 4, fc = threadIdx.x & 15;
    int row0 = blockIdx.x * 16;
    float acc = 0.f;
    for (int k0 = 0; k0 < N_FEAT; k0 += 64) {
#pragma unroll
        for (int rep = 0; rep < 4; rep++) {
            int t = threadIdx.x + rep * 256;
            int r = t >> 6, kk = t & 63;
            xs[r][kk] = xc[(size_t)(row0 + r) * N_FEAT + k0 + kk];
        }
#pragma unroll
        for (int rep = 0; rep < 4; rep++) {
            int t = threadIdx.x + rep * 256;
            int kk = t >> 4, f = t & 15;
            ws[kk][f] = Wo[(size_t)(k0 + kk) * N_CLASS + f];
        }
        __syncthreads();
#pragma unroll
        for (int kk = 0; kk < 64; kk++) acc += xs[ir][kk] * ws[kk][fc];
        __syncthreads();
    }
    h2[(size_t)(row0 + ir) * N_CLASS + fc] = acc;
}

// ---------------- scores2 ----------------
__global__ void scores2_kernel(const float* __restrict__ h2, const float* __restrict__ ao,
                               float* __restrict__ ssrc, float* __restrict__ sdst)
{
    int i = blockIdx.x * blockDim.x + threadIdx.x;
    const float* row = h2 + (size_t)i * N_CLASS;
    float ps = 0.f, pd = 0.f;
#pragma unroll
    for (int f = 0; f < N_CLASS; f++) {
        float v = row[f];
        ps += v * ao[f];
        pd += v * ao[N_CLASS + f];
    }
    ssrc[i] = ps;
    sdst[i] = pd;
}

// ---------------- combine2 + ELU + log_softmax (16 classes per 16-lane group) ----------------
__global__ void combine2_kernel(
    const float* __restrict__ ssrc, const float* __restrict__ sorted,
    const float* __restrict__ Zhi, const float* __restrict__ Zlo,
    const float* __restrict__ Phi, const float* __restrict__ Plo,
    float* __restrict__ out)
{
    int warp = threadIdx.x >> 5, lane = threadIdx.x & 31;
    int sub = lane >> 4, f = lane & 15;
    int i = (blockIdx.x * 8 + warp) * 2 + sub;
    float s = ssrc[i];
    float thr = -s;
    int lo = 0, hi = N_ROWS;
    while (lo < hi) {
        int mid = (lo + hi) >> 1;
        if (sorted[mid] >= thr) lo = mid + 1; else hi = mid;
    }
    int k = lo;
    float M = sorted[0];
    float rho = expf(-0.8f * (s + M));
    float den = (k == 0) ? Zlo[0] : (Zhi[k] + rho * Zlo[k]);
    size_t base = (size_t)f * (N_ROWS + 1);
    float num = (k == 0) ? Plo[base] : (Phi[base + k] + rho * Plo[base + k]);
    float feat = num / den;
    float v = feat > 0.f ? feat : expm1f(feat);  // outer ELU
    // log_softmax over the 16-lane group
    float m = v;
#pragma unroll
    for (int off = 8; off; off >>= 1) m = fmaxf(m, __shfl_xor_sync(0xffffffffu, m, off));
    float ex = expf(v - m);
    float ssum = ex;
#pragma unroll
    for (int off = 8; off; off >>= 1) ssum += __shfl_xor_sync(0xffffffffu, ssum, off);
    out[(size_t)i * N_CLASS + f] = v - m - logf(ssum);
}

// ---------------- launch ----------------
extern "C" void kernel_launch(void* const* d_in, const int* in_sizes, int n_in,
                              void* d_out, int out_size)
{
    const float* x  = (const float*)d_in[0];
    const float* Wh = (const float*)d_in[1];
    const float* ah = (const float*)d_in[2];
    const float* Wo = (const float*)d_in[3];
    const float* ao = (const float*)d_in[4];
    float* out = (float*)d_out;

    float *p_h1, *p_ssrc1, *p_sdst1, *p_sorted1, *p_ew1, *p_gw1, *p_Zhi1, *p_Zlo1;
    float *p_hperm1, *p_Phi1, *p_Plo1, *p_xc;
    int *p_idx1;
    float *p_h2, *p_ssrc2, *p_sdst2, *p_sorted2, *p_ew2, *p_gw2, *p_Zhi2, *p_Zlo2;
    float *p_hperm2, *p_Phi2, *p_Plo2;
    int *p_idx2;

    cudaGetSymbolAddress((void**)&p_h1, g_h1);
    cudaGetSymbolAddress((void**)&p_ssrc1, g_ssrc1);
    cudaGetSymbolAddress((void**)&p_sdst1, g_sdst1);
    cudaGetSymbolAddress((void**)&p_sorted1, g_sorted1);
    cudaGetSymbolAddress((void**)&p_idx1, g_idx1);
    cudaGetSymbolAddress((void**)&p_ew1, g_ew1);
    cudaGetSymbolAddress((void**)&p_gw1, g_gw1);
    cudaGetSymbolAddress((void**)&p_Zhi1, g_Zhi1);
    cudaGetSymbolAddress((void**)&p_Zlo1, g_Zlo1);
    cudaGetSymbolAddress((void**)&p_hperm1, g_hperm1);
    cudaGetSymbolAddress((void**)&p_Phi1, g_Phi1);
    cudaGetSymbolAddress((void**)&p_Plo1, g_Plo1);
    cudaGetSymbolAddress((void**)&p_xc, g_xc);
    cudaGetSymbolAddress((void**)&p_h2, g_h2);
    cudaGetSymbolAddress((void**)&p_ssrc2, g_ssrc2);
    cudaGetSymbolAddress((void**)&p_sdst2, g_sdst2);
    cudaGetSymbolAddress((void**)&p_sorted2, g_sorted2);
    cudaGetSymbolAddress((void**)&p_idx2, g_idx2);
    cudaGetSymbolAddress((void**)&p_ew2, g_ew2);
    cudaGetSymbolAddress((void**)&p_gw2, g_gw2);
    cudaGetSymbolAddress((void**)&p_Zhi2, g_Zhi2);
    cudaGetSymbolAddress((void**)&p_Zlo2, g_Zlo2);
    cudaGetSymbolAddress((void**)&p_hperm2, g_hperm2);
    cudaGetSymbolAddress((void**)&p_Phi2, g_Phi2);
    cudaGetSymbolAddress((void**)&p_Plo2, g_Plo2);

    // ---- layer 1 ----
    gemm1_kernel<<<dim3(N_ROWS / 128, N_HEADS), 256>>>(x, Wh, p_h1);
    scores1_kernel<<<dim3(N_ROWS / 8, N_HEADS), 256>>>(p_h1, ah, p_ssrc1, p_sdst1);
    sort_kernel<<<N_HEADS, 1024>>>(p_sdst1, p_sorted1, p_idx1);
    scalar_scan_kernel<<<N_HEADS, 1024>>>(p_sorted1, p_ew1, p_gw1, p_Zhi1, p_Zlo1);
    permute_kernel<<<dim3(N_ROWS / (256 / N_HID), N_HEADS), 256>>>(p_h1, p_idx1, p_hperm1, N_HID);
    feat_scan_kernel<<<dim3(N_HID, N_HEADS), 256>>>(p_hperm1, p_ew1, p_gw1, p_Phi1, p_Plo1, N_HID);
    combine1_kernel<<<dim3(N_ROWS / 8, N_HEADS), 256>>>(p_ssrc1, p_sorted1, p_Zhi1, p_Zlo1,
                                                        p_Phi1, p_Plo1, p_xc);
    // ---- layer 2 ----
    gemm2_kernel<<<N_ROWS / 16, 256>>>(p_xc, Wo, p_h2);
    scores2_kernel<<<N_ROWS / 256, 256>>>(p_h2, ao, p_ssrc2, p_sdst2);
    sort_kernel<<<1, 1024>>>(p_sdst2, p_sorted2, p_idx2);
    scalar_scan_kernel<<<1, 1024>>>(p_sorted2, p_ew2, p_gw2, p_Zhi2, p_Zlo2);
    permute_kernel<<<dim3(N_ROWS / (256 / N_CLASS), 1), 256>>>(p_h2, p_idx2, p_hperm2, N_CLASS);
    feat_scan_kernel<<<dim3(N_CLASS, 1), 256>>>(p_hperm2, p_ew2, p_gw2, p_Phi2, p_Plo2, N_CLASS);
    combine2_kernel<<<N_ROWS / 16, 256>>>(p_ssrc2, p_sorted2, p_Zhi2, p_Zlo2,
                                          p_Phi2, p_Plo2, out);

    (void)in_sizes; (void)n_in; (void)out_size;
}

// round 2
// speedup vs baseline: 1.3060x; 1.3060x over previous
#include <cuda_runtime.h>

#define N_ROWS   4096
#define N_FEAT   512
#define N_HID    64
#define N_CLASS  16
#define N_HEADS  8
#define PS       (N_ROWS + 4)   // padded scan stride (16B-aligned)

// ---------------- scratch (static device memory; no allocations) ----------------
__device__ float g_h1   [N_HEADS*N_ROWS*N_HID];
__device__ float g_ssrc1[N_HEADS*N_ROWS];
__device__ float g_sdst1[N_HEADS*N_ROWS];
__device__ float g_sorted1[N_HEADS*N_ROWS];
__device__ int   g_idx1 [N_HEADS*N_ROWS];
__device__ float g_ew1  [N_HEADS*N_ROWS];
__device__ float g_gw1  [N_HEADS*N_ROWS];
__device__ float g_Zhi1 [N_HEADS*PS];
__device__ float g_Zlo1 [N_HEADS*PS];
__device__ float g_Phi1 [N_HEADS*N_HID*PS];
__device__ float g_Plo1 [N_HEADS*N_HID*PS];
__device__ float g_xc   [N_ROWS*N_FEAT];

__device__ float g_h2   [N_ROWS*N_CLASS];
__device__ float g_ssrc2[N_ROWS];
__device__ float g_sdst2[N_ROWS];
__device__ float g_sorted2[N_ROWS];
__device__ int   g_idx2 [N_ROWS];
__device__ float g_ew2  [N_ROWS];
__device__ float g_gw2  [N_ROWS];
__device__ float g_Zhi2 [PS];
__device__ float g_Zlo2 [PS];
__device__ float g_Phi2 [N_CLASS*PS];
__device__ float g_Plo2 [N_CLASS*PS];

// ---------------- warp-shuffle block exclusive scan ----------------
// Returns exclusive prefix over thread order; total via out-param.
// sh must hold >= NW+1 floats. Safe for back-to-back calls (syncs at entry).
template<int NW>
__device__ __forceinline__ float blk_exscan(float v, float* sh, float& total) {
    __syncthreads();
    int lane = threadIdx.x & 31, warp = threadIdx.x >> 5;
    float x = v;
#pragma unroll
    for (int off = 1; off < 32; off <<= 1) {
        float n = __shfl_up_sync(0xffffffffu, x, off);
        if (lane >= off) x += n;
    }
    if (lane == 31) sh[warp] = x;
    __syncthreads();
    if (warp == 0) {
        float w = (lane < NW) ? sh[lane] : 0.f;
#pragma unroll
        for (int off = 1; off < 32; off <<= 1) {
            float n = __shfl_up_sync(0xffffffffu, w, off);
            if (lane >= off) w += n;
        }
        if (lane < NW) sh[lane] = w;
    }
    __syncthreads();
    float base = warp ? sh[warp - 1] : 0.f;
    total = sh[NW - 1];
    return base + x - v;
}

// ---------------- GEMM1: h1[h][i][f] = sum_k x[i][k] * Wh[h][k][f] ----------------
__global__ __launch_bounds__(256) void gemm1_kernel(
    const float* __restrict__ x, const float* __restrict__ Wh, float* __restrict__ h1)
{
    const int BM = 128, BK = 16;
    __shared__ float As[BK][BM + 4];
    __shared__ float Bs[BK][N_HID];
    int h = blockIdx.y;
    int row0 = blockIdx.x * BM;
    const float* W = Wh + (size_t)h * N_FEAT * N_HID;
    int tid = threadIdx.x;
    int tx = tid & 15, ty = tid >> 4;

    float acc[8][4];
#pragma unroll
    for (int m = 0; m < 8; m++)
#pragma unroll
        for (int n = 0; n < 4; n++) acc[m][n] = 0.f;

    for (int k0 = 0; k0 < N_FEAT; k0 += BK) {
#pragma unroll
        for (int rep = 0; rep < 8; rep++) {
            int i = (tid >> 4) + rep * 16;
            int kk = tid & 15;
            As[kk][i] = x[(size_t)(row0 + i) * N_FEAT + k0 + kk];
        }
#pragma unroll
        for (int rep = 0; rep < 4; rep++) {
            int kk = (tid >> 6) + rep * 4;
            int f = tid & 63;
            Bs[kk][f] = W[(size_t)(k0 + kk) * N_HID + f];
        }
        __syncthreads();
#pragma unroll
        for (int kk = 0; kk < BK; kk++) {
            float4 b4  = *reinterpret_cast<const float4*>(&Bs[kk][tx * 4]);
            float4 a4l = *reinterpret_cast<const float4*>(&As[kk][ty * 8]);
            float4 a4h = *reinterpret_cast<const float4*>(&As[kk][ty * 8 + 4]);
            float av[8] = {a4l.x, a4l.y, a4l.z, a4l.w, a4h.x, a4h.y, a4h.z, a4h.w};
            float bv[4] = {b4.x, b4.y, b4.z, b4.w};
#pragma unroll
            for (int m = 0; m < 8; m++)
#pragma unroll
                for (int n = 0; n < 4; n++) acc[m][n] += av[m] * bv[n];
        }
        __syncthreads();
    }
#pragma unroll
    for (int m = 0; m < 8; m++) {
        int row = row0 + ty * 8 + m;
        float4 o = make_float4(acc[m][0], acc[m][1], acc[m][2], acc[m][3]);
        *reinterpret_cast<float4*>(&h1[((size_t)h * N_ROWS + row) * N_HID + tx * 4]) = o;
    }
}

// ---------------- scores1: s_src/s_dst per (head,row) ----------------
__global__ void scores1_kernel(const float* __restrict__ h1, const float* __restrict__ ah,
                               float* __restrict__ ssrc, float* __restrict__ sdst)
{
    int h = blockIdx.y;
    int warp = threadIdx.x >> 5, lane = threadIdx.x & 31;
    int i = blockIdx.x * 8 + warp;
    const float* row = h1 + ((size_t)h * N_ROWS + i) * N_HID;
    const float* a = ah + (size_t)h * 2 * N_HID;
    float v1 = row[lane], v2 = row[lane + 32];
    float ps = v1 * a[lane] + v2 * a[lane + 32];
    float pd = v1 * a[N_HID + lane] + v2 * a[N_HID + lane + 32];
#pragma unroll
    for (int off = 16; off; off >>= 1) {
        ps += __shfl_xor_sync(0xffffffffu, ps, off);
        pd += __shfl_xor_sync(0xffffffffu, pd, off);
    }
    if (lane == 0) {
        ssrc[(size_t)h * N_ROWS + i] = ps;
        sdst[(size_t)h * N_ROWS + i] = pd;
    }
}

// ---------------- fused hybrid bitonic sort (descending) + scalar scans ----------------
// 1024 threads; 4 elements/thread held in registers (e = tid*4+q).
// strides 1,2: register compare-exchange; 4..64: shfl_xor; >=128: smem.
__global__ __launch_bounds__(1024) void sortscan_kernel(
    const float* __restrict__ sdst, float* __restrict__ sorted, int* __restrict__ idx,
    float* __restrict__ ew, float* __restrict__ gw,
    float* __restrict__ Zhi, float* __restrict__ Zlo)
{
    int h = blockIdx.x;
    __shared__ unsigned long long buf[N_ROWS];   // 32KB
    __shared__ float sh[40];
    int tid = threadIdx.x;

    float key[4]; int id[4];
    float4 v4 = *reinterpret_cast<const float4*>(sdst + (size_t)h * N_ROWS + tid * 4);
    key[0] = v4.x; key[1] = v4.y; key[2] = v4.z; key[3] = v4.w;
    id[0] = tid * 4; id[1] = tid * 4 + 1; id[2] = tid * 4 + 2; id[3] = tid * 4 + 3;

    for (int k = 2; k <= N_ROWS; k <<= 1) {
        for (int j = k >> 1; j > 0; j >>= 1) {
            if (j == 1) {
#pragma unroll
                for (int q = 0; q < 4; q += 2) {
                    int e = tid * 4 + q;
                    bool desc = ((e & k) == 0);
                    bool sw = desc ? (key[q] < key[q + 1]) : (key[q] > key[q + 1]);
                    if (sw) {
                        float tk = key[q]; key[q] = key[q + 1]; key[q + 1] = tk;
                        int ti = id[q]; id[q] = id[q + 1]; id[q + 1] = ti;
                    }
                }
            } else if (j == 2) {
#pragma unroll
                for (int q = 0; q < 2; q++) {
                    int e = tid * 4 + q;
                    bool desc = ((e & k) == 0);
                    bool sw = desc ? (key[q] < key[q + 2]) : (key[q] > key[q + 2]);
                    if (sw) {
                        float tk = key[q]; key[q] = key[q + 2]; key[q + 2] = tk;
                        int ti = id[q]; id[q] = id[q + 2]; id[q + 2] = ti;
                    }
                }
            } else if (j <= 64) {
                int m = j >> 2;   // lane xor mask (1..16)
#pragma unroll
                for (int q = 0; q < 4; q++) {
                    float ok = __shfl_xor_sync(0xffffffffu, key[q], m);
                    int   oi = __shfl_xor_sync(0xffffffffu, id[q], m);
                    int e = tid * 4 + q;
                    bool lower = ((e & j) == 0);
                    bool desc = ((e & k) == 0);
                    float a = lower ? key[q] : ok;
                    float b = lower ? ok : key[q];
                    bool sw = desc ? (a < b) : (a > b);
                    if (sw) { key[q] = ok; id[q] = oi; }
                }
            } else {
                __syncthreads();
#pragma unroll
                for (int q = 0; q < 4; q++) {
                    int e = tid * 4 + q;
                    buf[e] = ((unsigned long long)__float_as_uint(key[q]) << 32)
                             | (unsigned int)id[q];
                }
                __syncthreads();
#pragma unroll
                for (int q = 0; q < 4; q++) {
                    int e = tid * 4 + q;
                    unsigned long long o = buf[e ^ j];
                    float ok = __uint_as_float((unsigned int)(o >> 32));
                    int oi = (int)(unsigned int)(o & 0xffffffffu);
                    bool lower = ((e & j) == 0);
                    bool desc = ((e & k) == 0);
                    float a = lower ? key[q] : ok;
                    float b = lower ? ok : key[q];
                    bool sw = desc ? (a < b) : (a > b);
                    if (sw) { key[q] = ok; id[q] = oi; }
                }
            }
        }
    }
    __syncthreads();

    // write sorted + idx (vectorized: elements are thread-consecutive)
    *reinterpret_cast<float4*>(sorted + (size_t)h * N_ROWS + tid * 4) =
        make_float4(key[0], key[1], key[2], key[3]);
    *reinterpret_cast<int4*>(idx + (size_t)h * N_ROWS + tid * 4) =
        make_int4(id[0], id[1], id[2], id[3]);

    // broadcast M = max element
    if (tid == 0) sh[36] = key[0];
    __syncthreads();
    float M = sh[36];

    float e4[4], g4[4];
    float se = 0.f, sg = 0.f;
#pragma unroll
    for (int q = 0; q < 4; q++) {
        float xv = key[q] - M;
        e4[q] = expf(xv);
        g4[q] = expf(0.2f * xv);
        se += e4[q]; sg += g4[q];
    }
    *reinterpret_cast<float4*>(ew + (size_t)h * N_ROWS + tid * 4) =
        make_float4(e4[0], e4[1], e4[2], e4[3]);
    *reinterpret_cast<float4*>(gw + (size_t)h * N_ROWS + tid * 4) =
        make_float4(g4[0], g4[1], g4[2], g4[3]);

    float tote, totg;
    float pe = blk_exscan<32>(se, sh, tote);
    float pg = blk_exscan<32>(sg, sh, totg);

    float* ZH = Zhi + (size_t)h * PS;
    float* ZL = Zlo + (size_t)h * PS;
    float run = pe;
#pragma unroll
    for (int q = 0; q < 4; q++) { ZH[tid * 4 + q] = run; run += e4[q]; }
    float run2 = pg;
#pragma unroll
    for (int q = 0; q < 4; q++) { ZL[tid * 4 + q] = totg - run2; run2 += g4[q]; }
    if (tid == 1023) { ZH[N_ROWS] = run; ZL[N_ROWS] = 0.f; }
}

// ---------------- per-feature scans (gather via idx): Phi prefix / Plo suffix ----------------
__global__ __launch_bounds__(256) void featscan_kernel(
    const float* __restrict__ hsrc, const int* __restrict__ idx,
    const float* __restrict__ ew, const float* __restrict__ gw,
    float* __restrict__ Phi, float* __restrict__ Plo, int F)
{
    int f = blockIdx.x, h = blockIdx.y;
    const float* hb = hsrc + (size_t)h * N_ROWS * F;
    const int* ib = idx + (size_t)h * N_ROWS;
    const float* E = ew + (size_t)h * N_ROWS;
    const float* G = gw + (size_t)h * N_ROWS;
    float* PH = Phi + (size_t)(h * F + f) * PS;
    float* PL = Plo + (size_t)(h * F + f) * PS;
    __shared__ float sh[12];
    int t = threadIdx.x;

    float vh[16], vl[16];
    float shi = 0.f, slo = 0.f;
#pragma unroll
    for (int j4 = 0; j4 < 4; j4++) {
        int4   i4 = *reinterpret_cast<const int4*>(ib + t * 16 + j4 * 4);
        float4 E4 = *reinterpret_cast<const float4*>(E + t * 16 + j4 * 4);
        float4 G4 = *reinterpret_cast<const float4*>(G + t * 16 + j4 * 4);
        float a0 = hb[(size_t)i4.x * F + f];
        float a1 = hb[(size_t)i4.y * F + f];
        float a2 = hb[(size_t)i4.z * F + f];
        float a3 = hb[(size_t)i4.w * F + f];
        vh[j4 * 4 + 0] = a0 * E4.x; vl[j4 * 4 + 0] = a0 * G4.x;
        vh[j4 * 4 + 1] = a1 * E4.y; vl[j4 * 4 + 1] = a1 * G4.y;
        vh[j4 * 4 + 2] = a2 * E4.z; vl[j4 * 4 + 2] = a2 * G4.z;
        vh[j4 * 4 + 3] = a3 * E4.w; vl[j4 * 4 + 3] = a3 * G4.w;
        shi += vh[j4*4] + vh[j4*4+1] + vh[j4*4+2] + vh[j4*4+3];
        slo += vl[j4*4] + vl[j4*4+1] + vl[j4*4+2] + vl[j4*4+3];
    }
    float toth, totl;
    float ph = blk_exscan<8>(shi, sh, toth);
    float pl = blk_exscan<8>(slo, sh, totl);

    float runh = ph, runl = pl;
#pragma unroll
    for (int j4 = 0; j4 < 4; j4++) {
        float4 oh, ol;
        oh.x = runh; runh += vh[j4*4+0];
        oh.y = runh; runh += vh[j4*4+1];
        oh.z = runh; runh += vh[j4*4+2];
        oh.w = runh; runh += vh[j4*4+3];
        ol.x = totl - runl; runl += vl[j4*4+0];
        ol.y = totl - runl; runl += vl[j4*4+1];
        ol.z = totl - runl; runl += vl[j4*4+2];
        ol.w = totl - runl; runl += vl[j4*4+3];
        *reinterpret_cast<float4*>(PH + t * 16 + j4 * 4) = oh;
        *reinterpret_cast<float4*>(PL + t * 16 + j4 * 4) = ol;
    }
    if (t == 255) { PH[N_ROWS] = runh; PL[N_ROWS] = 0.f; }
}

// ---------------- combine layer1: smem-cached binary search + ELU, write xc ----------------
__global__ __launch_bounds__(256) void combine1_kernel(
    const float* __restrict__ ssrc, const float* __restrict__ sorted,
    const float* __restrict__ Zhi, const float* __restrict__ Zlo,
    const float* __restrict__ Phi, const float* __restrict__ Plo,
    float* __restrict__ xc)
{
    int h = blockIdx.y;
    __shared__ float ss[N_ROWS];
    const float* sb = sorted + (size_t)h * N_ROWS;
#pragma unroll
    for (int r = 0; r < 4; r++) {
        int off = (threadIdx.x + r * 256) * 4;
        *reinterpret_cast<float4*>(ss + off) = *reinterpret_cast<const float4*>(sb + off);
    }
    __syncthreads();
    int warp = threadIdx.x >> 5, lane = threadIdx.x & 31;
    float M = ss[0];
    const float* ZH = Zhi + (size_t)h * PS;
    const float* ZL = Zlo + (size_t)h * PS;
#pragma unroll
    for (int rr = 0; rr < 4; rr++) {
        int i = blockIdx.x * 32 + warp * 4 + rr;
        float s = ssrc[(size_t)h * N_ROWS + i];
        float thr = -s;
        int lo = 0, hi = N_ROWS;
        while (lo < hi) {
            int mid = (lo + hi) >> 1;
            if (ss[mid] >= thr) lo = mid + 1; else hi = mid;
        }
        int k = lo;
        float rho = expf(-0.8f * (s + M));
        float den = (k == 0) ? ZL[0] : (ZH[k] + rho * ZL[k]);
        float inv = 1.f / den;
#pragma unroll
        for (int u = 0; u < 2; u++) {
            int f = lane + 32 * u;
            size_t base = (size_t)(h * N_HID + f) * PS;
            float num = (k == 0) ? Plo[base] : (Phi[base + k] + rho * Plo[base + k]);
            float feat = num * inv;
            float v = feat > 0.f ? feat : expm1f(feat);
            xc[(size_t)i * N_FEAT + h * N_HID + f] = v;
        }
    }
}

// ---------------- GEMM2: h2 = xc @ Wo ----------------
__global__ __launch_bounds__(256) void gemm2_kernel(
    const float* __restrict__ xc, const float* __restrict__ Wo, float* __restrict__ h2)
{
    __shared__ float xs[16][64];
    __shared__ float ws[64][16];
    int ir = threadIdx.x >> 4, fc = threadIdx.x & 15;
    int row0 = blockIdx.x * 16;
    float acc = 0.f;
    for (int k0 = 0; k0 < N_FEAT; k0 += 64) {
#pragma unroll
        for (int rep = 0; rep < 4; rep++) {
            int t = threadIdx.x + rep * 256;
            int r = t >> 6, kk = t & 63;
            xs[r][kk] = xc[(size_t)(row0 + r) * N_FEAT + k0 + kk];
        }
#pragma unroll
        for (int rep = 0; rep < 4; rep++) {
            int t = threadIdx.x + rep * 256;
            int kk = t >> 4, f = t & 15;
            ws[kk][f] = Wo[(size_t)(k0 + kk) * N_CLASS + f];
        }
        __syncthreads();
#pragma unroll
        for (int kk = 0; kk < 64; kk++) acc += xs[ir][kk] * ws[kk][fc];
        __syncthreads();
    }
    h2[(size_t)(row0 + ir) * N_CLASS + fc] = acc;
}

// ---------------- scores2 ----------------
__global__ void scores2_kernel(const float* __restrict__ h2, const float* __restrict__ ao,
                               float* __restrict__ ssrc, float* __restrict__ sdst)
{
    int i = blockIdx.x * blockDim.x + threadIdx.x;
    const float* row = h2 + (size_t)i * N_CLASS;
    float ps = 0.f, pd = 0.f;
#pragma unroll
    for (int f = 0; f < N_CLASS; f++) {
        float v = row[f];
        ps += v * ao[f];
        pd += v * ao[N_CLASS + f];
    }
    ssrc[i] = ps;
    sdst[i] = pd;
}

// ---------------- combine2 + ELU + log_softmax ----------------
__global__ __launch_bounds__(256) void combine2_kernel(
    const float* __restrict__ ssrc, const float* __restrict__ sorted,
    const float* __restrict__ Zhi, const float* __restrict__ Zlo,
    const float* __restrict__ Phi, const float* __restrict__ Plo,
    float* __restrict__ out)
{
    __shared__ float ss[N_ROWS];
#pragma unroll
    for (int r = 0; r < 4; r++) {
        int off = (threadIdx.x + r * 256) * 4;
        *reinterpret_cast<float4*>(ss + off) = *reinterpret_cast<const float4*>(sorted + off);
    }
    __syncthreads();
    int warp = threadIdx.x >> 5, lane = threadIdx.x & 31;
    int sub = lane >> 4, f = lane & 15;
    float M = ss[0];
#pragma unroll
    for (int rr = 0; rr < 4; rr++) {
        int i = blockIdx.x * 64 + warp * 8 + rr * 2 + sub;
        float s = ssrc[i];
        float thr = -s;
        int lo = 0, hi = N_ROWS;
        while (lo < hi) {
            int mid = (lo + hi) >> 1;
            if (ss[mid] >= thr) lo = mid + 1; else hi = mid;
        }
        int k = lo;
        float rho = expf(-0.8f * (s + M));
        float den = (k == 0) ? Zlo[0] : (Zhi[k] + rho * Zlo[k]);
        size_t base = (size_t)f * PS;
        float num = (k == 0) ? Plo[base] : (Phi[base + k] + rho * Plo[base + k]);
        float feat = num / den;
        float v = feat > 0.f ? feat : expm1f(feat);
        // log_softmax over 16-lane group
        float m = v;
#pragma unroll
        for (int off = 8; off; off >>= 1) m = fmaxf(m, __shfl_xor_sync(0xffffffffu, m, off));
        float ex = expf(v - m);
        float ssum = ex;
#pragma unroll
        for (int off = 8; off; off >>= 1) ssum += __shfl_xor_sync(0xffffffffu, ssum, off);
        out[(size_t)i * N_CLASS + f] = v - m - logf(ssum);
    }
}

// ---------------- launch ----------------
extern "C" void kernel_launch(void* const* d_in, const int* in_sizes, int n_in,
                              void* d_out, int out_size)
{
    const float* x  = (const float*)d_in[0];
    const float* Wh = (const float*)d_in[1];
    const float* ah = (const float*)d_in[2];
    const float* Wo = (const float*)d_in[3];
    const float* ao = (const float*)d_in[4];
    float* out = (float*)d_out;

    float *p_h1, *p_ssrc1, *p_sdst1, *p_sorted1, *p_ew1, *p_gw1, *p_Zhi1, *p_Zlo1;
    float *p_Phi1, *p_Plo1, *p_xc;
    int *p_idx1;
    float *p_h2, *p_ssrc2, *p_sdst2, *p_sorted2, *p_ew2, *p_gw2, *p_Zhi2, *p_Zlo2;
    float *p_Phi2, *p_Plo2;
    int *p_idx2;

    cudaGetSymbolAddress((void**)&p_h1, g_h1);
    cudaGetSymbolAddress((void**)&p_ssrc1, g_ssrc1);
    cudaGetSymbolAddress((void**)&p_sdst1, g_sdst1);
    cudaGetSymbolAddress((void**)&p_sorted1, g_sorted1);
    cudaGetSymbolAddress((void**)&p_idx1, g_idx1);
    cudaGetSymbolAddress((void**)&p_ew1, g_ew1);
    cudaGetSymbolAddress((void**)&p_gw1, g_gw1);
    cudaGetSymbolAddress((void**)&p_Zhi1, g_Zhi1);
    cudaGetSymbolAddress((void**)&p_Zlo1, g_Zlo1);
    cudaGetSymbolAddress((void**)&p_Phi1, g_Phi1);
    cudaGetSymbolAddress((void**)&p_Plo1, g_Plo1);
    cudaGetSymbolAddress((void**)&p_xc, g_xc);
    cudaGetSymbolAddress((void**)&p_h2, g_h2);
    cudaGetSymbolAddress((void**)&p_ssrc2, g_ssrc2);
    cudaGetSymbolAddress((void**)&p_sdst2, g_sdst2);
    cudaGetSymbolAddress((void**)&p_sorted2, g_sorted2);
    cudaGetSymbolAddress((void**)&p_idx2, g_idx2);
    cudaGetSymbolAddress((void**)&p_ew2, g_ew2);
    cudaGetSymbolAddress((void**)&p_gw2, g_gw2);
    cudaGetSymbolAddress((void**)&p_Zhi2, g_Zhi2);
    cudaGetSymbolAddress((void**)&p_Zlo2, g_Zlo2);
    cudaGetSymbolAddress((void**)&p_Phi2, g_Phi2);
    cudaGetSymbolAddress((void**)&p_Plo2, g_Plo2);

    // ---- layer 1 ----
    gemm1_kernel<<<dim3(N_ROWS / 128, N_HEADS), 256>>>(x, Wh, p_h1);
    scores1_kernel<<<dim3(N_ROWS / 8, N_HEADS), 256>>>(p_h1, ah, p_ssrc1, p_sdst1);
    sortscan_kernel<<<N_HEADS, 1024>>>(p_sdst1, p_sorted1, p_idx1, p_ew1, p_gw1, p_Zhi1, p_Zlo1);
    featscan_kernel<<<dim3(N_HID, N_HEADS), 256>>>(p_h1, p_idx1, p_ew1, p_gw1, p_Phi1, p_Plo1, N_HID);
    combine1_kernel<<<dim3(N_ROWS / 32, N_HEADS), 256>>>(p_ssrc1, p_sorted1, p_Zhi1, p_Zlo1,
                                                         p_Phi1, p_Plo1, p_xc);
    // ---- layer 2 ----
    gemm2_kernel<<<N_ROWS / 16, 256>>>(p_xc, Wo, p_h2);
    scores2_kernel<<<N_ROWS / 256, 256>>>(p_h2, ao, p_ssrc2, p_sdst2);
    sortscan_kernel<<<1, 1024>>>(p_sdst2, p_sorted2, p_idx2, p_ew2, p_gw2, p_Zhi2, p_Zlo2);
    featscan_kernel<<<dim3(N_CLASS, 1), 256>>>(p_h2, p_idx2, p_ew2, p_gw2, p_Phi2, p_Plo2, N_CLASS);
    combine2_kernel<<<N_ROWS / 64, 256>>>(p_ssrc2, p_sorted2, p_Zhi2, p_Zlo2,
                                          p_Phi2, p_Plo2, out);

    (void)in_sizes; (void)n_in; (void)out_size;
}

// round 3
// speedup vs baseline: 1.3467x; 1.0312x over previous
#include <cuda_runtime.h>
#include <cuda_bf16.h>
#include <cstdint>

#define N_ROWS   4096
#define N_FEAT   512
#define N_HID    64
#define N_CLASS  16
#define N_HEADS  8
#define PS       (N_ROWS + 4)   // Zhi/Zlo padded stride
#define KR       (N_ROWS + 1)   // Phi/Plo k-rows

// ---------------- scratch (static device memory; no allocations) ----------------
__device__ __nv_bfloat16 g_xh [N_ROWS*N_FEAT];
__device__ __nv_bfloat16 g_xl [N_ROWS*N_FEAT];
__device__ __nv_bfloat16 g_whh[N_HEADS*N_FEAT*N_HID];
__device__ __nv_bfloat16 g_whl[N_HEADS*N_FEAT*N_HID];

__device__ float g_h1   [N_HEADS*N_ROWS*N_HID];
__device__ float g_ssrc1[N_HEADS*N_ROWS];
__device__ float g_sdst1[N_HEADS*N_ROWS];
__device__ float g_sorted1[N_HEADS*N_ROWS];
__device__ int   g_idx1 [N_HEADS*N_ROWS];
__device__ float g_ew1  [N_HEADS*N_ROWS];
__device__ float g_gw1  [N_HEADS*N_ROWS];
__device__ float g_Zhi1 [N_HEADS*PS];
__device__ float g_Zlo1 [N_HEADS*PS];
__device__ float g_Shi1 [N_HEADS*N_HID*(N_ROWS/N_HID)];
__device__ float g_Slo1 [N_HEADS*N_HID*(N_ROWS/N_HID)];
__device__ float g_Phi1 [N_HEADS*KR*N_HID];
__device__ float g_Plo1 [N_HEADS*KR*N_HID];
__device__ float g_xc   [N_ROWS*N_FEAT];

__device__ float g_h2   [N_ROWS*N_CLASS];
__device__ float g_ssrc2[N_ROWS];
__device__ float g_sdst2[N_ROWS];
__device__ float g_sorted2[N_ROWS];
__device__ int   g_idx2 [N_ROWS];
__device__ float g_ew2  [N_ROWS];
__device__ float g_gw2  [N_ROWS];
__device__ float g_Zhi2 [PS];
__device__ float g_Zlo2 [PS];
__device__ float g_Shi2 [N_CLASS*(N_ROWS/N_CLASS)];
__device__ float g_Slo2 [N_CLASS*(N_ROWS/N_CLASS)];
__device__ float g_Phi2 [KR*N_CLASS];
__device__ float g_Plo2 [KR*N_CLASS];

// ---------------- warp-shuffle block exclusive scan ----------------
template<int NW>
__device__ __forceinline__ float blk_exscan(float v, float* sh, float& total) {
    __syncthreads();
    int lane = threadIdx.x & 31, warp = threadIdx.x >> 5;
    float x = v;
#pragma unroll
    for (int off = 1; off < 32; off <<= 1) {
        float n = __shfl_up_sync(0xffffffffu, x, off);
        if (lane >= off) x += n;
    }
    if (lane == 31) sh[warp] = x;
    __syncthreads();
    if (warp == 0) {
        float w = (lane < NW) ? sh[lane] : 0.f;
#pragma unroll
        for (int off = 1; off < 32; off <<= 1) {
            float n = __shfl_up_sync(0xffffffffu, w, off);
            if (lane >= off) w += n;
        }
        if (lane < NW) sh[lane] = w;
    }
    __syncthreads();
    float base = warp ? sh[warp - 1] : 0.f;
    total = sh[NW - 1];
    return base + x - v;
}

// ---------------- split fp32 -> bf16 hi/lo ----------------
__global__ void split_kernel(const float* __restrict__ src,
                             __nv_bfloat16* __restrict__ hi, __nv_bfloat16* __restrict__ lo)
{
    int i = blockIdx.x * blockDim.x + threadIdx.x;
    float4 v = reinterpret_cast<const float4*>(src)[i];
    __nv_bfloat16 h0 = __float2bfloat16_rn(v.x);
    __nv_bfloat16 h1 = __float2bfloat16_rn(v.y);
    __nv_bfloat16 h2 = __float2bfloat16_rn(v.z);
    __nv_bfloat16 h3 = __float2bfloat16_rn(v.w);
    __nv_bfloat16 l0 = __float2bfloat16_rn(v.x - __bfloat162float(h0));
    __nv_bfloat16 l1 = __float2bfloat16_rn(v.y - __bfloat162float(h1));
    __nv_bfloat16 l2 = __float2bfloat16_rn(v.z - __bfloat162float(h2));
    __nv_bfloat16 l3 = __float2bfloat16_rn(v.w - __bfloat162float(h3));
    __nv_bfloat162* hp = reinterpret_cast<__nv_bfloat162*>(hi) + i * 2;
    __nv_bfloat162* lp = reinterpret_cast<__nv_bfloat162*>(lo) + i * 2;
    hp[0] = __nv_bfloat162(h0, h1); hp[1] = __nv_bfloat162(h2, h3);
    lp[0] = __nv_bfloat162(l0, l1); lp[1] = __nv_bfloat162(l2, l3);
}

// ---------------- GEMM1 via bf16 mma.sync, 3-term compensated ----------------
__device__ __forceinline__ void mma16816(float* c, const uint32_t* a, const uint32_t* b) {
    asm volatile(
        "mma.sync.aligned.m16n8k16.row.col.f32.bf16.bf16.f32 "
        "{%0,%1,%2,%3}, {%4,%5,%6,%7}, {%8,%9}, {%0,%1,%2,%3};\n"
        : "+f"(c[0]), "+f"(c[1]), "+f"(c[2]), "+f"(c[3])
        : "r"(a[0]), "r"(a[1]), "r"(a[2]), "r"(a[3]), "r"(b[0]), "r"(b[1]));
}

__global__ __launch_bounds__(256) void gemm1_mma_kernel(
    const __nv_bfloat16* __restrict__ xh, const __nv_bfloat16* __restrict__ xl,
    const __nv_bfloat16* __restrict__ whh, const __nv_bfloat16* __restrict__ whl,
    float* __restrict__ h1)
{
    const int BM = 128, BKT = 64, SA = 72, SB = 72;
    __shared__ __nv_bfloat16 As[BM * SA];    // [m][k]
    __shared__ __nv_bfloat16 Bs[BKT * SB];   // [k][f]
    int h = blockIdx.y;
    int row0 = blockIdx.x * BM;
    int tid = threadIdx.x;
    int wid = tid >> 5, lane = tid & 31;
    int wm = wid & 3, wn = wid >> 2;
    int lr = lane >> 2, lc = lane & 3;

    const __nv_bfloat16* Wb0 = whh + (size_t)h * N_FEAT * N_HID;
    const __nv_bfloat16* Wb1 = whl + (size_t)h * N_FEAT * N_HID;
    const __nv_bfloat16* Aph[3] = { xh, xl, xh };
    const __nv_bfloat16* Bph[3] = { Wb0, Wb0, Wb1 };

    float acc[2][4][4];
#pragma unroll
    for (int mm = 0; mm < 2; mm++)
#pragma unroll
        for (int nn = 0; nn < 4; nn++)
#pragma unroll
            for (int q = 0; q < 4; q++) acc[mm][nn][q] = 0.f;

    for (int p = 0; p < 3; p++) {
        const __nv_bfloat16* Ag = Aph[p];
        const __nv_bfloat16* Bg = Bph[p];
        for (int k0 = 0; k0 < N_FEAT; k0 += BKT) {
            __syncthreads();
#pragma unroll
            for (int i = 0; i < 4; i++) {
                int id4 = tid + i * 256;
                int r = id4 >> 3, kk = (id4 & 7) * 8;
                uint4 v = *reinterpret_cast<const uint4*>(
                    Ag + (size_t)(row0 + r) * N_FEAT + k0 + kk);
                *reinterpret_cast<uint4*>(As + r * SA + kk) = v;
            }
#pragma unroll
            for (int i = 0; i < 2; i++) {
                int id4 = tid + i * 256;
                int kk = id4 >> 3, ff = (id4 & 7) * 8;
                uint4 v = *reinterpret_cast<const uint4*>(
                    Bg + (size_t)(k0 + kk) * N_HID + ff);
                *reinterpret_cast<uint4*>(Bs + kk * SB + ff) = v;
            }
            __syncthreads();
#pragma unroll
            for (int ks = 0; ks < 4; ks++) {
                int kb = ks * 16;
                uint32_t afr[2][4];
#pragma unroll
                for (int mm = 0; mm < 2; mm++) {
                    const __nv_bfloat16* ap = As + (wm * 32 + mm * 16 + lr) * SA + kb + lc * 2;
                    afr[mm][0] = *reinterpret_cast<const uint32_t*>(ap);
                    afr[mm][1] = *reinterpret_cast<const uint32_t*>(ap + 8 * SA);
                    afr[mm][2] = *reinterpret_cast<const uint32_t*>(ap + 8);
                    afr[mm][3] = *reinterpret_cast<const uint32_t*>(ap + 8 * SA + 8);
                }
                uint32_t bfr[4][2];
#pragma unroll
                for (int nn = 0; nn < 4; nn++) {
                    int n = wn * 32 + nn * 8 + lr;
                    const __nv_bfloat16* bp = Bs + (kb + lc * 2) * SB + n;
                    unsigned short s0 = *reinterpret_cast<const unsigned short*>(bp);
                    unsigned short s1 = *reinterpret_cast<const unsigned short*>(bp + SB);
                    unsigned short s2 = *reinterpret_cast<const unsigned short*>(bp + 8 * SB);
                    unsigned short s3 = *reinterpret_cast<const unsigned short*>(bp + 9 * SB);
                    bfr[nn][0] = (uint32_t)s0 | ((uint32_t)s1 << 16);
                    bfr[nn][1] = (uint32_t)s2 | ((uint32_t)s3 << 16);
                }
#pragma unroll
                for (int mm = 0; mm < 2; mm++)
#pragma unroll
                    for (int nn = 0; nn < 4; nn++)
                        mma16816(acc[mm][nn], afr[mm], bfr[nn]);
            }
        }
    }
#pragma unroll
    for (int mm = 0; mm < 2; mm++)
#pragma unroll
        for (int nn = 0; nn < 4; nn++) {
            int r = row0 + wm * 32 + mm * 16 + lr;
            int c = wn * 32 + nn * 8 + lc * 2;
            float* o = h1 + ((size_t)h * N_ROWS + r) * N_HID + c;
            *reinterpret_cast<float2*>(o) = make_float2(acc[mm][nn][0], acc[mm][nn][1]);
            *reinterpret_cast<float2*>(o + 8 * N_HID) = make_float2(acc[mm][nn][2], acc[mm][nn][3]);
        }
}

// ---------------- scores1 ----------------
__global__ void scores1_kernel(const float* __restrict__ h1, const float* __restrict__ ah,
                               float* __restrict__ ssrc, float* __restrict__ sdst)
{
    int h = blockIdx.y;
    int warp = threadIdx.x >> 5, lane = threadIdx.x & 31;
    int i = blockIdx.x * 8 + warp;
    const float* row = h1 + ((size_t)h * N_ROWS + i) * N_HID;
    const float* a = ah + (size_t)h * 2 * N_HID;
    float v1 = row[lane], v2 = row[lane + 32];
    float ps = v1 * a[lane] + v2 * a[lane + 32];
    float pd = v1 * a[N_HID + lane] + v2 * a[N_HID + lane + 32];
#pragma unroll
    for (int off = 16; off; off >>= 1) {
        ps += __shfl_xor_sync(0xffffffffu, ps, off);
        pd += __shfl_xor_sync(0xffffffffu, pd, off);
    }
    if (lane == 0) {
        ssrc[(size_t)h * N_ROWS + i] = ps;
        sdst[(size_t)h * N_ROWS + i] = pd;
    }
}

// ---------------- fused hybrid bitonic sort (descending) + scalar scans ----------------
__global__ __launch_bounds__(1024) void sortscan_kernel(
    const float* __restrict__ sdst, float* __restrict__ sorted, int* __restrict__ idx,
    float* __restrict__ ew, float* __restrict__ gw,
    float* __restrict__ Zhi, float* __restrict__ Zlo)
{
    int h = blockIdx.x;
    __shared__ unsigned long long buf[N_ROWS];
    __shared__ float sh[40];
    int tid = threadIdx.x;

    float key[4]; int id[4];
    float4 v4 = *reinterpret_cast<const float4*>(sdst + (size_t)h * N_ROWS + tid * 4);
    key[0] = v4.x; key[1] = v4.y; key[2] = v4.z; key[3] = v4.w;
    id[0] = tid * 4; id[1] = tid * 4 + 1; id[2] = tid * 4 + 2; id[3] = tid * 4 + 3;

    for (int k = 2; k <= N_ROWS; k <<= 1) {
        for (int j = k >> 1; j > 0; j >>= 1) {
            if (j == 1) {
#pragma unroll
                for (int q = 0; q < 4; q += 2) {
                    int e = tid * 4 + q;
                    bool desc = ((e & k) == 0);
                    bool sw = desc ? (key[q] < key[q + 1]) : (key[q] > key[q + 1]);
                    if (sw) {
                        float tk = key[q]; key[q] = key[q + 1]; key[q + 1] = tk;
                        int ti = id[q]; id[q] = id[q + 1]; id[q + 1] = ti;
                    }
                }
            } else if (j == 2) {
#pragma unroll
                for (int q = 0; q < 2; q++) {
                    int e = tid * 4 + q;
                    bool desc = ((e & k) == 0);
                    bool sw = desc ? (key[q] < key[q + 2]) : (key[q] > key[q + 2]);
                    if (sw) {
                        float tk = key[q]; key[q] = key[q + 2]; key[q + 2] = tk;
                        int ti = id[q]; id[q] = id[q + 2]; id[q + 2] = ti;
                    }
                }
            } else if (j <= 64) {
                int m = j >> 2;
#pragma unroll
                for (int q = 0; q < 4; q++) {
                    float ok = __shfl_xor_sync(0xffffffffu, key[q], m);
                    int   oi = __shfl_xor_sync(0xffffffffu, id[q], m);
                    int e = tid * 4 + q;
                    bool lower = ((e & j) == 0);
                    bool desc = ((e & k) == 0);
                    float a = lower ? key[q] : ok;
                    float b = lower ? ok : key[q];
                    bool sw = desc ? (a < b) : (a > b);
                    if (sw) { key[q] = ok; id[q] = oi; }
                }
            } else {
                __syncthreads();
#pragma unroll
                for (int q = 0; q < 4; q++) {
                    int e = tid * 4 + q;
                    buf[e] = ((unsigned long long)__float_as_uint(key[q]) << 32)
                             | (unsigned int)id[q];
                }
                __syncthreads();
#pragma unroll
                for (int q = 0; q < 4; q++) {
                    int e = tid * 4 + q;
                    unsigned long long o = buf[e ^ j];
                    float ok = __uint_as_float((unsigned int)(o >> 32));
                    int oi = (int)(unsigned int)(o & 0xffffffffu);
                    bool lower = ((e & j) == 0);
                    bool desc = ((e & k) == 0);
                    float a = lower ? key[q] : ok;
                    float b = lower ? ok : key[q];
                    bool sw = desc ? (a < b) : (a > b);
                    if (sw) { key[q] = ok; id[q] = oi; }
                }
            }
        }
    }
    __syncthreads();

    *reinterpret_cast<float4*>(sorted + (size_t)h * N_ROWS + tid * 4) =
        make_float4(key[0], key[1], key[2], key[3]);
    *reinterpret_cast<int4*>(idx + (size_t)h * N_ROWS + tid * 4) =
        make_int4(id[0], id[1], id[2], id[3]);

    if (tid == 0) sh[36] = key[0];
    __syncthreads();
    float M = sh[36];

    float e4[4], g4[4];
    float se = 0.f, sg = 0.f;
#pragma unroll
    for (int q = 0; q < 4; q++) {
        float xv = key[q] - M;
        e4[q] = expf(xv);
        g4[q] = expf(0.2f * xv);
        se += e4[q]; sg += g4[q];
    }
    *reinterpret_cast<float4*>(ew + (size_t)h * N_ROWS + tid * 4) =
        make_float4(e4[0], e4[1], e4[2], e4[3]);
    *reinterpret_cast<float4*>(gw + (size_t)h * N_ROWS + tid * 4) =
        make_float4(g4[0], g4[1], g4[2], g4[3]);

    float tote, totg;
    float pe = blk_exscan<32>(se, sh, tote);
    float pg = blk_exscan<32>(sg, sh, totg);

    float* ZH = Zhi + (size_t)h * PS;
    float* ZL = Zlo + (size_t)h * PS;
    float run = pe;
#pragma unroll
    for (int q = 0; q < 4; q++) { ZH[tid * 4 + q] = run; run += e4[q]; }
    float run2 = pg;
#pragma unroll
    for (int q = 0; q < 4; q++) { ZL[tid * 4 + q] = totg - run2; run2 += g4[q]; }
    if (tid == 1023) { ZH[N_ROWS] = run; ZL[N_ROWS] = 0.f; }
}

// ---------------- featA: per-segment weighted sums (coalesced gather) ----------------
// Block: 256 threads = F feats x SEGS segments; chunk = 256 rows; rows/seg = F.
template<int F>
__global__ __launch_bounds__(256) void featA_kernel(
    const float* __restrict__ hsrc, const int* __restrict__ idx,
    const float* __restrict__ ew, const float* __restrict__ gw,
    float* __restrict__ Shi, float* __restrict__ Slo)
{
    const int SEGS = 256 / F;
    const int SEGTOT = N_ROWS / F;
    __shared__ int   sidx[256];
    __shared__ float sew[256], sgw[256];
    int h = blockIdx.y, chunk = blockIdx.x;
    int t = threadIdx.x;
    int base = h * N_ROWS + chunk * 256;
    sidx[t] = idx[base + t];
    sew[t] = ew[base + t];
    sgw[t] = gw[base + t];
    __syncthreads();
    int ft = t % F, rg = t / F;
    const float* hb = hsrc + (size_t)h * N_ROWS * F + ft;
    float shi = 0.f, slo = 0.f;
#pragma unroll 4
    for (int j = 0; j < F; j++) {
        int rl = rg * F + j;
        float v = hb[(size_t)sidx[rl] * F];
        shi += v * sew[rl];
        slo += v * sgw[rl];
    }
    int seg = chunk * SEGS + rg;
    Shi[(size_t)(h * F + ft) * SEGTOT + seg] = shi;
    Slo[(size_t)(h * F + ft) * SEGTOT + seg] = slo;
}

// ---------------- featC: final scan, output Phi[h][k][f] (coalesced) ----------------
template<int F>
__global__ __launch_bounds__(256) void featC_kernel(
    const float* __restrict__ hsrc, const int* __restrict__ idx,
    const float* __restrict__ ew, const float* __restrict__ gw,
    const float* __restrict__ Shi, const float* __restrict__ Slo,
    float* __restrict__ Phi, float* __restrict__ Plo)
{
    const int SEGS = 256 / F;
    const int SEGTOT = N_ROWS / F;       // F*SEGTOT == 4096
    __shared__ int   sidx[256];
    __shared__ float sew[256], sgw[256];
    __shared__ float sSh[4096], sSl[4096];
    int h = blockIdx.y, chunk = blockIdx.x;
    int t = threadIdx.x;
    int base = h * N_ROWS + chunk * 256;
    sidx[t] = idx[base + t];
    sew[t] = ew[base + t];
    sgw[t] = gw[base + t];
    const float* ShB = Shi + (size_t)h * F * SEGTOT;
    const float* SlB = Slo + (size_t)h * F * SEGTOT;
#pragma unroll
    for (int i = 0; i < 4096 / 256; i++) {
        sSh[t + i * 256] = ShB[t + i * 256];
        sSl[t + i * 256] = SlB[t + i * 256];
    }
    __syncthreads();
    int ft = t % F, rg = t / F;
    int myseg = chunk * SEGS + rg;
    float offh = 0.f, offl = 0.f, totl = 0.f;
    const float* rh = sSh + ft * SEGTOT;
    const float* rl = sSl + ft * SEGTOT;
    for (int s = 0; s < SEGTOT; s++) {
        float a = rh[s], b = rl[s];
        if (s < myseg) { offh += a; offl += b; }
        totl += b;
    }
    const float* hb = hsrc + (size_t)h * N_ROWS * F + ft;
    float* PH = Phi + ((size_t)h * KR) * F + ft;
    float* PL = Plo + ((size_t)h * KR) * F + ft;
    float runh = offh, runl = offl;
    int r0 = chunk * 256 + rg * F;
#pragma unroll 4
    for (int j = 0; j < F; j++) {
        int rl_ = rg * F + j;
        int r = r0 + j;
        float v = hb[(size_t)sidx[rl_] * F];
        PH[(size_t)r * F] = runh;
        PL[(size_t)r * F] = totl - runl;
        runh += v * sew[rl_];
        runl += v * sgw[rl_];
    }
    if (myseg == SEGTOT - 1) {
        PH[(size_t)N_ROWS * F] = runh;
        PL[(size_t)N_ROWS * F] = totl - runl;   // == 0
    }
}

// ---------------- combine layer1 (Phi[h][k][f] layout) ----------------
__global__ __launch_bounds__(256) void combine1_kernel(
    const float* __restrict__ ssrc, const float* __restrict__ sorted,
    const float* __restrict__ Zhi, const float* __restrict__ Zlo,
    const float* __restrict__ Phi, const float* __restrict__ Plo,
    float* __restrict__ xc)
{
    int h = blockIdx.y;
    __shared__ float ss[N_ROWS];
    const float* sb = sorted + (size_t)h * N_ROWS;
#pragma unroll
    for (int r = 0; r < 4; r++) {
        int off = (threadIdx.x + r * 256) * 4;
        *reinterpret_cast<float4*>(ss + off) = *reinterpret_cast<const float4*>(sb + off);
    }
    __syncthreads();
    int warp = threadIdx.x >> 5, lane = threadIdx.x & 31;
    float M = ss[0];
    const float* ZH = Zhi + (size_t)h * PS;
    const float* ZL = Zlo + (size_t)h * PS;
    const float* PHb = Phi + (size_t)h * KR * N_HID;
    const float* PLb = Plo + (size_t)h * KR * N_HID;
#pragma unroll
    for (int rr = 0; rr < 4; rr++) {
        int i = blockIdx.x * 32 + warp * 4 + rr;
        float s = ssrc[(size_t)h * N_ROWS + i];
        float thr = -s;
        int lo = 0, hi = N_ROWS;
        while (lo < hi) {
            int mid = (lo + hi) >> 1;
            if (ss[mid] >= thr) lo = mid + 1; else hi = mid;
        }
        int k = lo;
        float rho = expf(-0.8f * (s + M));
        float den = (k == 0) ? ZL[0] : (ZH[k] + rho * ZL[k]);
        float inv = 1.f / den;
        const float* ph = PHb + (size_t)k * N_HID;
        const float* pl = PLb + (size_t)k * N_HID;
#pragma unroll
        for (int u = 0; u < 2; u++) {
            int f = lane + 32 * u;
            float num = (k == 0) ? pl[f] : (ph[f] + rho * pl[f]);
            float feat = num * inv;
            float v = feat > 0.f ? feat : expm1f(feat);
            xc[(size_t)i * N_FEAT + h * N_HID + f] = v;
        }
    }
}

// ---------------- GEMM2: h2 = xc @ Wo ----------------
__global__ __launch_bounds__(256) void gemm2_kernel(
    const float* __restrict__ xc, const float* __restrict__ Wo, float* __restrict__ h2)
{
    __shared__ float xs[16][64];
    __shared__ float ws[64][16];
    int ir = threadIdx.x >> 4, fc = threadIdx.x & 15;
    int row0 = blockIdx.x * 16;
    float acc = 0.f;
    for (int k0 = 0; k0 < N_FEAT; k0 += 64) {
#pragma unroll
        for (int rep = 0; rep < 4; rep++) {
            int t = threadIdx.x + rep * 256;
            int r = t >> 6, kk = t & 63;
            xs[r][kk] = xc[(size_t)(row0 + r) * N_FEAT + k0 + kk];
        }
#pragma unroll
        for (int rep = 0; rep < 4; rep++) {
            int t = threadIdx.x + rep * 256;
            int kk = t >> 4, f = t & 15;
            ws[kk][f] = Wo[(size_t)(k0 + kk) * N_CLASS + f];
        }
        __syncthreads();
#pragma unroll
        for (int kk = 0; kk < 64; kk++) acc += xs[ir][kk] * ws[kk][fc];
        __syncthreads();
    }
    h2[(size_t)(row0 + ir) * N_CLASS + fc] = acc;
}

// ---------------- scores2 ----------------
__global__ void scores2_kernel(const float* __restrict__ h2, const float* __restrict__ ao,
                               float* __restrict__ ssrc, float* __restrict__ sdst)
{
    int i = blockIdx.x * blockDim.x + threadIdx.x;
    const float* row = h2 + (size_t)i * N_CLASS;
    float ps = 0.f, pd = 0.f;
#pragma unroll
    for (int f = 0; f < N_CLASS; f++) {
        float v = row[f];
        ps += v * ao[f];
        pd += v * ao[N_CLASS + f];
    }
    ssrc[i] = ps;
    sdst[i] = pd;
}

// ---------------- combine2 + ELU + log_softmax (Phi2[k][16] layout) ----------------
__global__ __launch_bounds__(256) void combine2_kernel(
    const float* __restrict__ ssrc, const float* __restrict__ sorted,
    const float* __restrict__ Zhi, const float* __restrict__ Zlo,
    const float* __restrict__ Phi, const float* __restrict__ Plo,
    float* __restrict__ out)
{
    __shared__ float ss[N_ROWS];
#pragma unroll
    for (int r = 0; r < 4; r++) {
        int off = (threadIdx.x + r * 256) * 4;
        *reinterpret_cast<float4*>(ss + off) = *reinterpret_cast<const float4*>(sorted + off);
    }
    __syncthreads();
    int warp = threadIdx.x >> 5, lane = threadIdx.x & 31;
    int sub = lane >> 4, f = lane & 15;
    float M = ss[0];
#pragma unroll
    for (int rr = 0; rr < 4; rr++) {
        int i = blockIdx.x * 64 + warp * 8 + rr * 2 + sub;
        float s = ssrc[i];
        float thr = -s;
        int lo = 0, hi = N_ROWS;
        while (lo < hi) {
            int mid = (lo + hi) >> 1;
            if (ss[mid] >= thr) lo = mid + 1; else hi = mid;
        }
        int k = lo;
        float rho = expf(-0.8f * (s + M));
        float den = (k == 0) ? Zlo[0] : (Zhi[k] + rho * Zlo[k]);
        float num = (k == 0) ? Plo[f] : (Phi[(size_t)k * N_CLASS + f] + rho * Plo[(size_t)k * N_CLASS + f]);
        float feat = num / den;
        float v = feat > 0.f ? feat : expm1f(feat);
        float m = v;
#pragma unroll
        for (int off = 8; off; off >>= 1) m = fmaxf(m, __shfl_xor_sync(0xffffffffu, m, off));
        float ex = expf(v - m);
        float ssum = ex;
#pragma unroll
        for (int off = 8; off; off >>= 1) ssum += __shfl_xor_sync(0xffffffffu, ssum, off);
        out[(size_t)i * N_CLASS + f] = v - m - logf(ssum);
    }
}

// ---------------- launch ----------------
extern "C" void kernel_launch(void* const* d_in, const int* in_sizes, int n_in,
                              void* d_out, int out_size)
{
    const float* x  = (const float*)d_in[0];
    const float* Wh = (const float*)d_in[1];
    const float* ah = (const float*)d_in[2];
    const float* Wo = (const float*)d_in[3];
    const float* ao = (const float*)d_in[4];
    float* out = (float*)d_out;

    __nv_bfloat16 *p_xh, *p_xl, *p_whh, *p_whl;
    float *p_h1, *p_ssrc1, *p_sdst1, *p_sorted1, *p_ew1, *p_gw1, *p_Zhi1, *p_Zlo1;
    float *p_Shi1, *p_Slo1, *p_Phi1, *p_Plo1, *p_xc;
    int *p_idx1;
    float *p_h2, *p_ssrc2, *p_sdst2, *p_sorted2, *p_ew2, *p_gw2, *p_Zhi2, *p_Zlo2;
    float *p_Shi2, *p_Slo2, *p_Phi2, *p_Plo2;
    int *p_idx2;

    cudaGetSymbolAddress((void**)&p_xh, g_xh);
    cudaGetSymbolAddress((void**)&p_xl, g_xl);
    cudaGetSymbolAddress((void**)&p_whh, g_whh);
    cudaGetSymbolAddress((void**)&p_whl, g_whl);
    cudaGetSymbolAddress((void**)&p_h1, g_h1);
    cudaGetSymbolAddress((void**)&p_ssrc1, g_ssrc1);
    cudaGetSymbolAddress((void**)&p_sdst1, g_sdst1);
    cudaGetSymbolAddress((void**)&p_sorted1, g_sorted1);
    cudaGetSymbolAddress((void**)&p_idx1, g_idx1);
    cudaGetSymbolAddress((void**)&p_ew1, g_ew1);
    cudaGetSymbolAddress((void**)&p_gw1, g_gw1);
    cudaGetSymbolAddress((void**)&p_Zhi1, g_Zhi1);
    cudaGetSymbolAddress((void**)&p_Zlo1, g_Zlo1);
    cudaGetSymbolAddress((void**)&p_Shi1, g_Shi1);
    cudaGetSymbolAddress((void**)&p_Slo1, g_Slo1);
    cudaGetSymbolAddress((void**)&p_Phi1, g_Phi1);
    cudaGetSymbolAddress((void**)&p_Plo1, g_Plo1);
    cudaGetSymbolAddress((void**)&p_xc, g_xc);
    cudaGetSymbolAddress((void**)&p_h2, g_h2);
    cudaGetSymbolAddress((void**)&p_ssrc2, g_ssrc2);
    cudaGetSymbolAddress((void**)&p_sdst2, g_sdst2);
    cudaGetSymbolAddress((void**)&p_sorted2, g_sorted2);
    cudaGetSymbolAddress((void**)&p_idx2, g_idx2);
    cudaGetSymbolAddress((void**)&p_ew2, g_ew2);
    cudaGetSymbolAddress((void**)&p_gw2, g_gw2);
    cudaGetSymbolAddress((void**)&p_Zhi2, g_Zhi2);
    cudaGetSymbolAddress((void**)&p_Zlo2, g_Zlo2);
    cudaGetSymbolAddress((void**)&p_Shi2, g_Shi2);
    cudaGetSymbolAddress((void**)&p_Slo2, g_Slo2);
    cudaGetSymbolAddress((void**)&p_Phi2, g_Phi2);
    cudaGetSymbolAddress((void**)&p_Plo2, g_Plo2);

    // ---- splits ----
    split_kernel<<<(N_ROWS * N_FEAT / 4) / 256, 256>>>(x, p_xh, p_xl);
    split_kernel<<<(N_HEADS * N_FEAT * N_HID / 4) / 256, 256>>>(Wh, p_whh, p_whl);

    // ---- layer 1 ----
    gemm1_mma_kernel<<<dim3(N_ROWS / 128, N_HEADS), 256>>>(p_xh, p_xl, p_whh, p_whl, p_h1);
    scores1_kernel<<<dim3(N_ROWS / 8, N_HEADS), 256>>>(p_h1, ah, p_ssrc1, p_sdst1);
    sortscan_kernel<<<N_HEADS, 1024>>>(p_sdst1, p_sorted1, p_idx1, p_ew1, p_gw1, p_Zhi1, p_Zlo1);
    featA_kernel<N_HID><<<dim3(16, N_HEADS), 256>>>(p_h1, p_idx1, p_ew1, p_gw1, p_Shi1, p_Slo1);
    featC_kernel<N_HID><<<dim3(16, N_HEADS), 256>>>(p_h1, p_idx1, p_ew1, p_gw1,
                                                    p_Shi1, p_Slo1, p_Phi1, p_Plo1);
    combine1_kernel<<<dim3(N_ROWS / 32, N_HEADS), 256>>>(p_ssrc1, p_sorted1, p_Zhi1, p_Zlo1,
                                                         p_Phi1, p_Plo1, p_xc);
    // ---- layer 2 ----
    gemm2_kernel<<<N_ROWS / 16, 256>>>(p_xc, Wo, p_h2);
    scores2_kernel<<<N_ROWS / 256, 256>>>(p_h2, ao, p_ssrc2, p_sdst2);
    sortscan_kernel<<<1, 1024>>>(p_sdst2, p_sorted2, p_idx2, p_ew2, p_gw2, p_Zhi2, p_Zlo2);
    featA_kernel<N_CLASS><<<dim3(16, 1), 256>>>(p_h2, p_idx2, p_ew2, p_gw2, p_Shi2, p_Slo2);
    featC_kernel<N_CLASS><<<dim3(16, 1), 256>>>(p_h2, p_idx2, p_ew2, p_gw2,
                                                p_Shi2, p_Slo2, p_Phi2, p_Plo2);
    combine2_kernel<<<N_ROWS / 64, 256>>>(p_ssrc2, p_sorted2, p_Zhi2, p_Zlo2,
                                          p_Phi2, p_Plo2, out);

    (void)in_sizes; (void)n_in; (void)out_size;
}

// round 5
// speedup vs baseline: 1.3821x; 1.0262x over previous
#include <cuda_runtime.h>
#include <cuda_bf16.h>
#include <cstdint>

#define N_ROWS   4096
#define N_FEAT   512
#define N_HID    64
#define N_CLASS  16
#define N_HEADS  8
#define PS       (N_ROWS + 4)   // Zhi/Zlo padded stride
#define KR       (N_ROWS + 1)   // Phi/Plo k-rows

// ---------------- scratch (static device memory; no allocations) ----------------
__device__ __nv_bfloat16 g_xh [N_ROWS*N_FEAT];
__device__ __nv_bfloat16 g_xl [N_ROWS*N_FEAT];
__device__ __nv_bfloat16 g_whh[N_HEADS*N_FEAT*N_HID];
__device__ __nv_bfloat16 g_whl[N_HEADS*N_FEAT*N_HID];

__device__ float g_h1   [N_HEADS*N_ROWS*N_HID];
__device__ float g_ssrc1[N_HEADS*N_ROWS];
__device__ float g_sdst1[N_HEADS*N_ROWS];
__device__ float g_sorted1[N_HEADS*N_ROWS];
__device__ int   g_idx1 [N_HEADS*N_ROWS];
__device__ float g_ew1  [N_HEADS*N_ROWS];
__device__ float g_gw1  [N_HEADS*N_ROWS];
__device__ float g_Zhi1 [N_HEADS*PS];
__device__ float g_Zlo1 [N_HEADS*PS];
__device__ float g_Shi1 [N_HEADS*N_HID*(N_ROWS/N_HID)];
__device__ float g_Slo1 [N_HEADS*N_HID*(N_ROWS/N_HID)];
__device__ float g_Phi1 [N_HEADS*KR*N_HID];
__device__ float g_Plo1 [N_HEADS*KR*N_HID];
__device__ float g_xc   [N_ROWS*N_FEAT];

__device__ float g_h2   [N_ROWS*N_CLASS];
__device__ float g_ssrc2[N_ROWS];
__device__ float g_sdst2[N_ROWS];
__device__ float g_sorted2[N_ROWS];
__device__ int   g_idx2 [N_ROWS];
__device__ float g_ew2  [N_ROWS];
__device__ float g_gw2  [N_ROWS];
__device__ float g_Zhi2 [PS];
__device__ float g_Zlo2 [PS];
__device__ float g_Shi2 [N_CLASS*(N_ROWS/N_CLASS)];
__device__ float g_Slo2 [N_CLASS*(N_ROWS/N_CLASS)];
__device__ float g_Phi2 [KR*N_CLASS];
__device__ float g_Plo2 [KR*N_CLASS];

// ---------------- warp-shuffle block exclusive scan ----------------
template<int NW>
__device__ __forceinline__ float blk_exscan(float v, float* sh, float& total) {
    __syncthreads();
    int lane = threadIdx.x & 31, warp = threadIdx.x >> 5;
    float x = v;
#pragma unroll
    for (int off = 1; off < 32; off <<= 1) {
        float n = __shfl_up_sync(0xffffffffu, x, off);
        if (lane >= off) x += n;
    }
    if (lane == 31) sh[warp] = x;
    __syncthreads();
    if (warp == 0) {
        float w = (lane < NW) ? sh[lane] : 0.f;
#pragma unroll
        for (int off = 1; off < 32; off <<= 1) {
            float n = __shfl_up_sync(0xffffffffu, w, off);
            if (lane >= off) w += n;
        }
        if (lane < NW) sh[lane] = w;
    }
    __syncthreads();
    float base = warp ? sh[warp - 1] : 0.f;
    total = sh[NW - 1];
    return base + x - v;
}

// ---------------- combined split fp32 -> bf16 hi/lo for x and Wh ----------------
#define NX4  (N_ROWS * N_FEAT / 4)
#define NW4  (N_HEADS * N_FEAT * N_HID / 4)
__global__ void splitall_kernel(const float* __restrict__ x, const float* __restrict__ Wh,
                                __nv_bfloat16* __restrict__ xh, __nv_bfloat16* __restrict__ xl,
                                __nv_bfloat16* __restrict__ whh, __nv_bfloat16* __restrict__ whl)
{
    int i = blockIdx.x * blockDim.x + threadIdx.x;
    const float* src; __nv_bfloat16 *hi, *lo; int j;
    if (i < NX4) { src = x; hi = xh; lo = xl; j = i; }
    else         { src = Wh; hi = whh; lo = whl; j = i - NX4; if (j >= NW4) return; }
    float4 v = reinterpret_cast<const float4*>(src)[j];
    __nv_bfloat16 h0 = __float2bfloat16_rn(v.x);
    __nv_bfloat16 h1 = __float2bfloat16_rn(v.y);
    __nv_bfloat16 h2 = __float2bfloat16_rn(v.z);
    __nv_bfloat16 h3 = __float2bfloat16_rn(v.w);
    __nv_bfloat16 l0 = __float2bfloat16_rn(v.x - __bfloat162float(h0));
    __nv_bfloat16 l1 = __float2bfloat16_rn(v.y - __bfloat162float(h1));
    __nv_bfloat16 l2 = __float2bfloat16_rn(v.z - __bfloat162float(h2));
    __nv_bfloat16 l3 = __float2bfloat16_rn(v.w - __bfloat162float(h3));
    __nv_bfloat162* hp = reinterpret_cast<__nv_bfloat162*>(hi) + j * 2;
    __nv_bfloat162* lp = reinterpret_cast<__nv_bfloat162*>(lo) + j * 2;
    hp[0] = __nv_bfloat162(h0, h1); hp[1] = __nv_bfloat162(h2, h3);
    lp[0] = __nv_bfloat162(l0, l1); lp[1] = __nv_bfloat162(l2, l3);
}

// ---------------- GEMM1 via bf16 mma.sync + fused scores epilogue ----------------
__device__ __forceinline__ void mma16816(float* c, const uint32_t* a, const uint32_t* b) {
    asm volatile(
        "mma.sync.aligned.m16n8k16.row.col.f32.bf16.bf16.f32 "
        "{%0,%1,%2,%3}, {%4,%5,%6,%7}, {%8,%9}, {%0,%1,%2,%3};\n"
        : "+f"(c[0]), "+f"(c[1]), "+f"(c[2]), "+f"(c[3])
        : "r"(a[0]), "r"(a[1]), "r"(a[2]), "r"(a[3]), "r"(b[0]), "r"(b[1]));
}

__global__ __launch_bounds__(256) void gemm1_mma_kernel(
    const __nv_bfloat16* __restrict__ xh, const __nv_bfloat16* __restrict__ xl,
    const __nv_bfloat16* __restrict__ whh, const __nv_bfloat16* __restrict__ whl,
    const float* __restrict__ ah,
    float* __restrict__ h1, float* __restrict__ ssrc, float* __restrict__ sdst)
{
    const int BM = 128, BKT = 64, SA = 72, SB = 72;
    __shared__ __nv_bfloat16 As[BM * SA];    // [m][k]
    __shared__ __nv_bfloat16 Bs[BKT * SB];   // [k][f]
    __shared__ float sred[2][2][BM];         // [wn][src/dst][rowlocal]
    int h = blockIdx.y;
    int row0 = blockIdx.x * BM;
    int tid = threadIdx.x;
    int wid = tid >> 5, lane = tid & 31;
    int wm = wid & 3, wn = wid >> 2;
    int lr = lane >> 2, lc = lane & 3;

    const __nv_bfloat16* Wb0 = whh + (size_t)h * N_FEAT * N_HID;
    const __nv_bfloat16* Wb1 = whl + (size_t)h * N_FEAT * N_HID;
    const __nv_bfloat16* Aph[3] = { xh, xl, xh };
    const __nv_bfloat16* Bph[3] = { Wb0, Wb0, Wb1 };

    float acc[2][4][4];
#pragma unroll
    for (int mm = 0; mm < 2; mm++)
#pragma unroll
        for (int nn = 0; nn < 4; nn++)
#pragma unroll
            for (int q = 0; q < 4; q++) acc[mm][nn][q] = 0.f;

    for (int p = 0; p < 3; p++) {
        const __nv_bfloat16* Ag = Aph[p];
        const __nv_bfloat16* Bg = Bph[p];
        for (int k0 = 0; k0 < N_FEAT; k0 += BKT) {
            __syncthreads();
#pragma unroll
            for (int i = 0; i < 4; i++) {
                int id4 = tid + i * 256;
                int r = id4 >> 3, kk = (id4 & 7) * 8;
                uint4 v = *reinterpret_cast<const uint4*>(
                    Ag + (size_t)(row0 + r) * N_FEAT + k0 + kk);
                *reinterpret_cast<uint4*>(As + r * SA + kk) = v;
            }
#pragma unroll
            for (int i = 0; i < 2; i++) {
                int id4 = tid + i * 256;
                int kk = id4 >> 3, ff = (id4 & 7) * 8;
                uint4 v = *reinterpret_cast<const uint4*>(
                    Bg + (size_t)(k0 + kk) * N_HID + ff);
                *reinterpret_cast<uint4*>(Bs + kk * SB + ff) = v;
            }
            __syncthreads();
#pragma unroll
            for (int ks = 0; ks < 4; ks++) {
                int kb = ks * 16;
                uint32_t afr[2][4];
#pragma unroll
                for (int mm = 0; mm < 2; mm++) {
                    const __nv_bfloat16* ap = As + (wm * 32 + mm * 16 + lr) * SA + kb + lc * 2;
                    afr[mm][0] = *reinterpret_cast<const uint32_t*>(ap);
                    afr[mm][1] = *reinterpret_cast<const uint32_t*>(ap + 8 * SA);
                    afr[mm][2] = *reinterpret_cast<const uint32_t*>(ap + 8);
                    afr[mm][3] = *reinterpret_cast<const uint32_t*>(ap + 8 * SA + 8);
                }
                uint32_t bfr[4][2];
#pragma unroll
                for (int nn = 0; nn < 4; nn++) {
                    int n = wn * 32 + nn * 8 + lr;
                    const __nv_bfloat16* bp = Bs + (kb + lc * 2) * SB + n;
                    unsigned short s0 = *reinterpret_cast<const unsigned short*>(bp);
                    unsigned short s1 = *reinterpret_cast<const unsigned short*>(bp + SB);
                    unsigned short s2 = *reinterpret_cast<const unsigned short*>(bp + 8 * SB);
                    unsigned short s3 = *reinterpret_cast<const unsigned short*>(bp + 9 * SB);
                    bfr[nn][0] = (uint32_t)s0 | ((uint32_t)s1 << 16);
                    bfr[nn][1] = (uint32_t)s2 | ((uint32_t)s3 << 16);
                }
#pragma unroll
                for (int mm = 0; mm < 2; mm++)
#pragma unroll
                    for (int nn = 0; nn < 4; nn++)
                        mma16816(acc[mm][nn], afr[mm], bfr[nn]);
            }
        }
    }
    // store h1 tile
#pragma unroll
    for (int mm = 0; mm < 2; mm++)
#pragma unroll
        for (int nn = 0; nn < 4; nn++) {
            int r = row0 + wm * 32 + mm * 16 + lr;
            int c = wn * 32 + nn * 8 + lc * 2;
            float* o = h1 + ((size_t)h * N_ROWS + r) * N_HID + c;
            *reinterpret_cast<float2*>(o) = make_float2(acc[mm][nn][0], acc[mm][nn][1]);
            *reinterpret_cast<float2*>(o + 8 * N_HID) = make_float2(acc[mm][nn][2], acc[mm][nn][3]);
        }

    // fused scores epilogue: s_src/s_dst for the 128 rows of this tile
    const float* a = ah + (size_t)h * 2 * N_HID;
#pragma unroll
    for (int mm = 0; mm < 2; mm++) {
        float ps1 = 0.f, pd1 = 0.f, ps2 = 0.f, pd2 = 0.f;
#pragma unroll
        for (int nn = 0; nn < 4; nn++) {
            int c0 = wn * 32 + nn * 8 + lc * 2;
            float a0s = a[c0], a1s = a[c0 + 1];
            float a0d = a[N_HID + c0], a1d = a[N_HID + c0 + 1];
            ps1 += acc[mm][nn][0] * a0s + acc[mm][nn][1] * a1s;
            pd1 += acc[mm][nn][0] * a0d + acc[mm][nn][1] * a1d;
            ps2 += acc[mm][nn][2] * a0s + acc[mm][nn][3] * a1s;
            pd2 += acc[mm][nn][2] * a0d + acc[mm][nn][3] * a1d;
        }
#pragma unroll
        for (int off = 1; off <= 2; off <<= 1) {
            ps1 += __shfl_xor_sync(0xffffffffu, ps1, off);
            pd1 += __shfl_xor_sync(0xffffffffu, pd1, off);
            ps2 += __shfl_xor_sync(0xffffffffu, ps2, off);
            pd2 += __shfl_xor_sync(0xffffffffu, pd2, off);
        }
        if (lc == 0) {
            int rl = wm * 32 + mm * 16 + lr;
            sred[wn][0][rl] = ps1; sred[wn][1][rl] = pd1;
            sred[wn][0][rl + 8] = ps2; sred[wn][1][rl + 8] = pd2;
        }
    }
    __syncthreads();
    if (tid < BM) {
        int gi = h * N_ROWS + row0 + tid;
        ssrc[gi] = sred[0][0][tid] + sred[1][0][tid];
        sdst[gi] = sred[0][1][tid] + sred[1][1][tid];
    }
}

// ---------------- fused hybrid bitonic sort (descending) + scalar scans ----------------
__global__ __launch_bounds__(1024) void sortscan_kernel(
    const float* __restrict__ sdst, float* __restrict__ sorted, int* __restrict__ idx,
    float* __restrict__ ew, float* __restrict__ gw,
    float* __restrict__ Zhi, float* __restrict__ Zlo)
{
    int h = blockIdx.x;
    __shared__ unsigned long long buf[N_ROWS];
    __shared__ float sh[40];
    int tid = threadIdx.x;

    float key[4]; int id[4];
    float4 v4 = *reinterpret_cast<const float4*>(sdst + (size_t)h * N_ROWS + tid * 4);
    key[0] = v4.x; key[1] = v4.y; key[2] = v4.z; key[3] = v4.w;
    id[0] = tid * 4; id[1] = tid * 4 + 1; id[2] = tid * 4 + 2; id[3] = tid * 4 + 3;

    for (int k = 2; k <= N_ROWS; k <<= 1) {
        for (int j = k >> 1; j > 0; j >>= 1) {
            if (j == 1) {
#pragma unroll
                for (int q = 0; q < 4; q += 2) {
                    int e = tid * 4 + q;
                    bool desc = ((e & k) == 0);
                    bool sw = desc ? (key[q] < key[q + 1]) : (key[q] > key[q + 1]);
                    if (sw) {
                        float tk = key[q]; key[q] = key[q + 1]; key[q + 1] = tk;
                        int ti = id[q]; id[q] = id[q + 1]; id[q + 1] = ti;
                    }
                }
            } else if (j == 2) {
#pragma unroll
                for (int q = 0; q < 2; q++) {
                    int e = tid * 4 + q;
                    bool desc = ((e & k) == 0);
                    bool sw = desc ? (key[q] < key[q + 2]) : (key[q] > key[q + 2]);
                    if (sw) {
                        float tk = key[q]; key[q] = key[q + 2]; key[q + 2] = tk;
                        int ti = id[q]; id[q] = id[q + 2]; id[q + 2] = ti;
                    }
                }
            } else if (j <= 64) {
                int m = j >> 2;
#pragma unroll
                for (int q = 0; q < 4; q++) {
                    float ok = __shfl_xor_sync(0xffffffffu, key[q], m);
                    int   oi = __shfl_xor_sync(0xffffffffu, id[q], m);
                    int e = tid * 4 + q;
                    bool lower = ((e & j) == 0);
                    bool desc = ((e & k) == 0);
                    float a = lower ? key[q] : ok;
                    float b = lower ? ok : key[q];
                    bool sw = desc ? (a < b) : (a > b);
                    if (sw) { key[q] = ok; id[q] = oi; }
                }
            } else {
                __syncthreads();
#pragma unroll
                for (int q = 0; q < 4; q++) {
                    int e = tid * 4 + q;
                    buf[e] = ((unsigned long long)__float_as_uint(key[q]) << 32)
                             | (unsigned int)id[q];
                }
                __syncthreads();
#pragma unroll
                for (int q = 0; q < 4; q++) {
                    int e = tid * 4 + q;
                    unsigned long long o = buf[e ^ j];
                    float ok = __uint_as_float((unsigned int)(o >> 32));
                    int oi = (int)(unsigned int)(o & 0xffffffffu);
                    bool lower = ((e & j) == 0);
                    bool desc = ((e & k) == 0);
                    float a = lower ? key[q] : ok;
                    float b = lower ? ok : key[q];
                    bool sw = desc ? (a < b) : (a > b);
                    if (sw) { key[q] = ok; id[q] = oi; }
                }
            }
        }
    }
    __syncthreads();

    *reinterpret_cast<float4*>(sorted + (size_t)h * N_ROWS + tid * 4) =
        make_float4(key[0], key[1], key[2], key[3]);
    *reinterpret_cast<int4*>(idx + (size_t)h * N_ROWS + tid * 4) =
        make_int4(id[0], id[1], id[2], id[3]);

    if (tid == 0) sh[36] = key[0];
    __syncthreads();
    float M = sh[36];

    float e4[4], g4[4];
    float se = 0.f, sg = 0.f;
#pragma unroll
    for (int q = 0; q < 4; q++) {
        float xv = key[q] - M;
        e4[q] = expf(xv);
        g4[q] = expf(0.2f * xv);
        se += e4[q]; sg += g4[q];
    }
    *reinterpret_cast<float4*>(ew + (size_t)h * N_ROWS + tid * 4) =
        make_float4(e4[0], e4[1], e4[2], e4[3]);
    *reinterpret_cast<float4*>(gw + (size_t)h * N_ROWS + tid * 4) =
        make_float4(g4[0], g4[1], g4[2], g4[3]);

    float tote, totg;
    float pe = blk_exscan<32>(se, sh, tote);
    float pg = blk_exscan<32>(sg, sh, totg);

    float* ZH = Zhi + (size_t)h * PS;
    float* ZL = Zlo + (size_t)h * PS;
    float run = pe;
#pragma unroll
    for (int q = 0; q < 4; q++) { ZH[tid * 4 + q] = run; run += e4[q]; }
    float run2 = pg;
#pragma unroll
    for (int q = 0; q < 4; q++) { ZL[tid * 4 + q] = totg - run2; run2 += g4[q]; }
    if (tid == 1023) { ZH[N_ROWS] = run; ZL[N_ROWS] = 0.f; }
}

// ---------------- featA: per-segment weighted sums (coalesced gather) ----------------
template<int F>
__global__ __launch_bounds__(256) void featA_kernel(
    const float* __restrict__ hsrc, const int* __restrict__ idx,
    const float* __restrict__ ew, const float* __restrict__ gw,
    float* __restrict__ Shi, float* __restrict__ Slo)
{
    const int SEGS = 256 / F;
    const int SEGTOT = N_ROWS / F;
    __shared__ int   sidx[256];
    __shared__ float sew[256], sgw[256];
    int h = blockIdx.y, chunk = blockIdx.x;
    int t = threadIdx.x;
    int base = h * N_ROWS + chunk * 256;
    sidx[t] = idx[base + t];
    sew[t] = ew[base + t];
    sgw[t] = gw[base + t];
    __syncthreads();
    int ft = t % F, rg = t / F;
    const float* hb = hsrc + (size_t)h * N_ROWS * F + ft;
    float shi = 0.f, slo = 0.f;
#pragma unroll 4
    for (int j = 0; j < F; j++) {
        int rl = rg * F + j;
        float v = hb[(size_t)sidx[rl] * F];
        shi += v * sew[rl];
        slo += v * sgw[rl];
    }
    int seg = chunk * SEGS + rg;
    Shi[(size_t)(h * F + ft) * SEGTOT + seg] = shi;
    Slo[(size_t)(h * F + ft) * SEGTOT + seg] = slo;
}

// ---------------- featC: final scan, output Phi[h][k][f] (coalesced) ----------------
template<int F>
__global__ __launch_bounds__(256) void featC_kernel(
    const float* __restrict__ hsrc, const int* __restrict__ idx,
    const float* __restrict__ ew, const float* __restrict__ gw,
    const float* __restrict__ Shi, const float* __restrict__ Slo,
    float* __restrict__ Phi, float* __restrict__ Plo)
{
    const int SEGS = 256 / F;
    const int SEGTOT = N_ROWS / F;
    __shared__ int   sidx[256];
    __shared__ float sew[256], sgw[256];
    __shared__ float sSh[4096], sSl[4096];
    int h = blockIdx.y, chunk = blockIdx.x;
    int t = threadIdx.x;
    int base = h * N_ROWS + chunk * 256;
    sidx[t] = idx[base + t];
    sew[t] = ew[base + t];
    sgw[t] = gw[base + t];
    const float* ShB = Shi + (size_t)h * F * SEGTOT;
    const float* SlB = Slo + (size_t)h * F * SEGTOT;
#pragma unroll
    for (int i = 0; i < 4096 / 256; i++) {
        sSh[t + i * 256] = ShB[t + i * 256];
        sSl[t + i * 256] = SlB[t + i * 256];
    }
    __syncthreads();
    int ft = t % F, rg = t / F;
    int myseg = chunk * SEGS + rg;
    float offh = 0.f, offl = 0.f, totl = 0.f;
    const float* rh = sSh + ft * SEGTOT;
    const float* rl = sSl + ft * SEGTOT;
    for (int s = 0; s < SEGTOT; s++) {
        float a = rh[s], b = rl[s];
        if (s < myseg) { offh += a; offl += b; }
        totl += b;
    }
    const float* hb = hsrc + (size_t)h * N_ROWS * F + ft;
    float* PH = Phi + ((size_t)h * KR) * F + ft;
    float* PL = Plo + ((size_t)h * KR) * F + ft;
    float runh = offh, runl = offl;
    int r0 = chunk * 256 + rg * F;
#pragma unroll 4
    for (int j = 0; j < F; j++) {
        int rl_ = rg * F + j;
        int r = r0 + j;
        float v = hb[(size_t)sidx[rl_] * F];
        PH[(size_t)r * F] = runh;
        PL[(size_t)r * F] = totl - runl;
        runh += v * sew[rl_];
        runl += v * sgw[rl_];
    }
    if (myseg == SEGTOT - 1) {
        PH[(size_t)N_ROWS * F] = runh;
        PL[(size_t)N_ROWS * F] = totl - runl;
    }
}

// ---------------- combine layer1 (Phi[h][k][f] layout) ----------------
__global__ __launch_bounds__(256) void combine1_kernel(
    const float* __restrict__ ssrc, const float* __restrict__ sorted,
    const float* __restrict__ Zhi, const float* __restrict__ Zlo,
    const float* __restrict__ Phi, const float* __restrict__ Plo,
    float* __restrict__ xc)
{
    int h = blockIdx.y;
    __shared__ float ss[N_ROWS];
    const float* sb = sorted + (size_t)h * N_ROWS;
#pragma unroll
    for (int r = 0; r < 4; r++) {
        int off = (threadIdx.x + r * 256) * 4;
        *reinterpret_cast<float4*>(ss + off) = *reinterpret_cast<const float4*>(sb + off);
    }
    __syncthreads();
    int warp = threadIdx.x >> 5, lane = threadIdx.x & 31;
    float M = ss[0];
    const float* ZH = Zhi + (size_t)h * PS;
    const float* ZL = Zlo + (size_t)h * PS;
    const float* PHb = Phi + (size_t)h * KR * N_HID;
    const float* PLb = Plo + (size_t)h * KR * N_HID;
#pragma unroll
    for (int rr = 0; rr < 4; rr++) {
        int i = blockIdx.x * 32 + warp * 4 + rr;
        float s = ssrc[(size_t)h * N_ROWS + i];
        float thr = -s;
        int lo = 0, hi = N_ROWS;
        while (lo < hi) {
            int mid = (lo + hi) >> 1;
            if (ss[mid] >= thr) lo = mid + 1; else hi = mid;
        }
        int k = lo;
        float rho = expf(-0.8f * (s + M));
        float den = (k == 0) ? ZL[0] : (ZH[k] + rho * ZL[k]);
        float inv = 1.f / den;
        const float* ph = PHb + (size_t)k * N_HID;
        const float* pl = PLb + (size_t)k * N_HID;
#pragma unroll
        for (int u = 0; u < 2; u++) {
            int f = lane + 32 * u;
            float num = (k == 0) ? pl[f] : (ph[f] + rho * pl[f]);
            float feat = num * inv;
            float v = feat > 0.f ? feat : expm1f(feat);
            xc[(size_t)i * N_FEAT + h * N_HID + f] = v;
        }
    }
}

// ---------------- GEMM2: h2 = xc @ Wo + fused scores2 epilogue ----------------
__global__ __launch_bounds__(256) void gemm2_kernel(
    const float* __restrict__ xc, const float* __restrict__ Wo,
    const float* __restrict__ ao,
    float* __restrict__ h2, float* __restrict__ ssrc, float* __restrict__ sdst)
{
    __shared__ float xs[16][64];
    __shared__ float ws[64][16];
    int ir = threadIdx.x >> 4, fc = threadIdx.x & 15;
    int row0 = blockIdx.x * 16;
    float acc = 0.f;
    for (int k0 = 0; k0 < N_FEAT; k0 += 64) {
#pragma unroll
        for (int rep = 0; rep < 4; rep++) {
            int t = threadIdx.x + rep * 256;
            int r = t >> 6, kk = t & 63;
            xs[r][kk] = xc[(size_t)(row0 + r) * N_FEAT + k0 + kk];
        }
#pragma unroll
        for (int rep = 0; rep < 4; rep++) {
            int t = threadIdx.x + rep * 256;
            int kk = t >> 4, f = t & 15;
            ws[kk][f] = Wo[(size_t)(k0 + kk) * N_CLASS + f];
        }
        __syncthreads();
#pragma unroll
        for (int kk = 0; kk < 64; kk++) acc += xs[ir][kk] * ws[kk][fc];
        __syncthreads();
    }
    h2[(size_t)(row0 + ir) * N_CLASS + fc] = acc;
    // fused scores2: reduce over the 16 lanes of each row group
    float ps = acc * ao[fc];
    float pd = acc * ao[N_CLASS + fc];
#pragma unroll
    for (int off = 1; off < 16; off <<= 1) {
        ps += __shfl_xor_sync(0xffffffffu, ps, off);
        pd += __shfl_xor_sync(0xffffffffu, pd, off);
    }
    if (fc == 0) {
        ssrc[row0 + ir] = ps;
        sdst[row0 + ir] = pd;
    }
}

// ---------------- combine2 + ELU + log_softmax (Phi2[k][16] layout) ----------------
__global__ __launch_bounds__(256) void combine2_kernel(
    const float* __restrict__ ssrc, const float* __restrict__ sorted,
    const float* __restrict__ Zhi, const float* __restrict__ Zlo,
    const float* __restrict__ Phi, const float* __restrict__ Plo,
    float* __restrict__ out)
{
    __shared__ float ss[N_ROWS];
#pragma unroll
    for (int r = 0; r < 4; r++) {
        int off = (threadIdx.x + r * 256) * 4;
        *reinterpret_cast<float4*>(ss + off) = *reinterpret_cast<const float4*>(sorted + off);
    }
    __syncthreads();
    int warp = threadIdx.x >> 5, lane = threadIdx.x & 31;
    int sub = lane >> 4, f = lane & 15;
    float M = ss[0];
#pragma unroll
    for (int rr = 0; rr < 4; rr++) {
        int i = blockIdx.x * 64 + warp * 8 + rr * 2 + sub;
        float s = ssrc[i];
        float thr = -s;
        int lo = 0, hi = N_ROWS;
        while (lo < hi) {
            int mid = (lo + hi) >> 1;
            if (ss[mid] >= thr) lo = mid + 1; else hi = mid;
        }
        int k = lo;
        float rho = expf(-0.8f * (s + M));
        float den = (k == 0) ? Zlo[0] : (Zhi[k] + rho * Zlo[k]);
        float num = (k == 0) ? Plo[f] : (Phi[(size_t)k * N_CLASS + f] + rho * Plo[(size_t)k * N_CLASS + f]);
        float feat = num / den;
        float v = feat > 0.f ? feat : expm1f(feat);
        float m = v;
#pragma unroll
        for (int off = 8; off; off >>= 1) m = fmaxf(m, __shfl_xor_sync(0xffffffffu, m, off));
        float ex = expf(v - m);
        float ssum = ex;
#pragma unroll
        for (int off = 8; off; off >>= 1) ssum += __shfl_xor_sync(0xffffffffu, ssum, off);
        out[(size_t)i * N_CLASS + f] = v - m - logf(ssum);
    }
}

// ---------------- launch ----------------
extern "C" void kernel_launch(void* const* d_in, const int* in_sizes, int n_in,
                              void* d_out, int out_size)
{
    const float* x  = (const float*)d_in[0];
    const float* Wh = (const float*)d_in[1];
    const float* ah = (const float*)d_in[2];
    const float* Wo = (const float*)d_in[3];
    const float* ao = (const float*)d_in[4];
    float* out = (float*)d_out;

    __nv_bfloat16 *p_xh, *p_xl, *p_whh, *p_whl;
    float *p_h1, *p_ssrc1, *p_sdst1, *p_sorted1, *p_ew1, *p_gw1, *p_Zhi1, *p_Zlo1;
    float *p_Shi1, *p_Slo1, *p_Phi1, *p_Plo1, *p_xc;
    int *p_idx1;
    float *p_h2, *p_ssrc2, *p_sdst2, *p_sorted2, *p_ew2, *p_gw2, *p_Zhi2, *p_Zlo2;
    float *p_Shi2, *p_Slo2, *p_Phi2, *p_Plo2;
    int *p_idx2;

    cudaGetSymbolAddress((void**)&p_xh, g_xh);
    cudaGetSymbolAddress((void**)&p_xl, g_xl);
    cudaGetSymbolAddress((void**)&p_whh, g_whh);
    cudaGetSymbolAddress((void**)&p_whl, g_whl);
    cudaGetSymbolAddress((void**)&p_h1, g_h1);
    cudaGetSymbolAddress((void**)&p_ssrc1, g_ssrc1);
    cudaGetSymbolAddress((void**)&p_sdst1, g_sdst1);
    cudaGetSymbolAddress((void**)&p_sorted1, g_sorted1);
    cudaGetSymbolAddress((void**)&p_idx1, g_idx1);
    cudaGetSymbolAddress((void**)&p_ew1, g_ew1);
    cudaGetSymbolAddress((void**)&p_gw1, g_gw1);
    cudaGetSymbolAddress((void**)&p_Zhi1, g_Zhi1);
    cudaGetSymbolAddress((void**)&p_Zlo1, g_Zlo1);
    cudaGetSymbolAddress((void**)&p_Shi1, g_Shi1);
    cudaGetSymbolAddress((void**)&p_Slo1, g_Slo1);
    cudaGetSymbolAddress((void**)&p_Phi1, g_Phi1);
    cudaGetSymbolAddress((void**)&p_Plo1, g_Plo1);
    cudaGetSymbolAddress((void**)&p_xc, g_xc);
    cudaGetSymbolAddress((void**)&p_h2, g_h2);
    cudaGetSymbolAddress((void**)&p_ssrc2, g_ssrc2);
    cudaGetSymbolAddress((void**)&p_sdst2, g_sdst2);
    cudaGetSymbolAddress((void**)&p_sorted2, g_sorted2);
    cudaGetSymbolAddress((void**)&p_idx2, g_idx2);
    cudaGetSymbolAddress((void**)&p_ew2, g_ew2);
    cudaGetSymbolAddress((void**)&p_gw2, g_gw2);
    cudaGetSymbolAddress((void**)&p_Zhi2, g_Zhi2);
    cudaGetSymbolAddress((void**)&p_Zlo2, g_Zlo2);
    cudaGetSymbolAddress((void**)&p_Shi2, g_Shi2);
    cudaGetSymbolAddress((void**)&p_Slo2, g_Slo2);
    cudaGetSymbolAddress((void**)&p_Phi2, g_Phi2);
    cudaGetSymbolAddress((void**)&p_Plo2, g_Plo2);

    // ---- combined splits ----
    splitall_kernel<<<(NX4 + NW4 + 255) / 256, 256>>>(x, Wh, p_xh, p_xl, p_whh, p_whl);

    // ---- layer 1 ----
    gemm1_mma_kernel<<<dim3(N_ROWS / 128, N_HEADS), 256>>>(p_xh, p_xl, p_whh, p_whl, ah,
                                                           p_h1, p_ssrc1, p_sdst1);
    sortscan_kernel<<<N_HEADS, 1024>>>(p_sdst1, p_sorted1, p_idx1, p_ew1, p_gw1, p_Zhi1, p_Zlo1);
    featA_kernel<N_HID><<<dim3(16, N_HEADS), 256>>>(p_h1, p_idx1, p_ew1, p_gw1, p_Shi1, p_Slo1);
    featC_kernel<N_HID><<<dim3(16, N_HEADS), 256>>>(p_h1, p_idx1, p_ew1, p_gw1,
                                                    p_Shi1, p_Slo1, p_Phi1, p_Plo1);
    combine1_kernel<<<dim3(N_ROWS / 32, N_HEADS), 256>>>(p_ssrc1, p_sorted1, p_Zhi1, p_Zlo1,
                                                         p_Phi1, p_Plo1, p_xc);
    // ---- layer 2 ----
    gemm2_kernel<<<N_ROWS / 16, 256>>>(p_xc, Wo, ao, p_h2, p_ssrc2, p_sdst2);
    sortscan_kernel<<<1, 1024>>>(p_sdst2, p_sorted2, p_idx2, p_ew2, p_gw2, p_Zhi2, p_Zlo2);
    featA_kernel<N_CLASS><<<dim3(16, 1), 256>>>(p_h2, p_idx2, p_ew2, p_gw2, p_Shi2, p_Slo2);
    featC_kernel<N_CLASS><<<dim3(16, 1), 256>>>(p_h2, p_idx2, p_ew2, p_gw2,
                                                p_Shi2, p_Slo2, p_Phi2, p_Plo2);
    combine2_kernel<<<N_ROWS / 64, 256>>>(p_ssrc2, p_sorted2, p_Zhi2, p_Zlo2,
                                          p_Phi2, p_Plo2, out);

    (void)in_sizes; (void)n_in; (void)out_size;
}

// round 6
// speedup vs baseline: 1.4379x; 1.0404x over previous
#include <cuda_runtime.h>
#include <cuda_bf16.h>
#include <cstdint>

#define N_ROWS   4096
#define N_FEAT   512
#define N_HID    64
#define N_CLASS  16
#define N_HEADS  8
#define PS       (N_ROWS + 4)   // Zhi/Zlo padded stride
#define KR       (N_ROWS + 1)   // Phi/Plo k-rows

// ---------------- scratch (static device memory; no allocations) ----------------
__device__ __nv_bfloat16 g_xh [N_ROWS*N_FEAT];
__device__ __nv_bfloat16 g_xl [N_ROWS*N_FEAT];
__device__ __nv_bfloat16 g_whh[N_HEADS*N_FEAT*N_HID];
__device__ __nv_bfloat16 g_whl[N_HEADS*N_FEAT*N_HID];

__device__ float g_h1   [N_HEADS*N_ROWS*N_HID];
__device__ float g_ssrc1[N_HEADS*N_ROWS];
__device__ float g_sdst1[N_HEADS*N_ROWS];
__device__ float g_sorted1[N_HEADS*N_ROWS];
__device__ int   g_idx1 [N_HEADS*N_ROWS];
__device__ float g_ew1  [N_HEADS*N_ROWS];
__device__ float g_gw1  [N_HEADS*N_ROWS];
__device__ float g_Zhi1 [N_HEADS*PS];
__device__ float g_Zlo1 [N_HEADS*PS];
__device__ float g_Chi1 [N_HEADS*N_HID*16];
__device__ float g_Clo1 [N_HEADS*N_HID*16];
__device__ float g_Phi1 [N_HEADS*KR*N_HID];
__device__ float g_Plo1 [N_HEADS*KR*N_HID];
__device__ float g_xc   [N_ROWS*N_FEAT];

__device__ float g_h2   [N_ROWS*N_CLASS];
__device__ float g_ssrc2[N_ROWS];
__device__ float g_sdst2[N_ROWS];
__device__ float g_sorted2[N_ROWS];
__device__ int   g_idx2 [N_ROWS];
__device__ float g_ew2  [N_ROWS];
__device__ float g_gw2  [N_ROWS];
__device__ float g_Zhi2 [PS];
__device__ float g_Zlo2 [PS];
__device__ float g_Shi2 [N_CLASS*(N_ROWS/N_CLASS)];
__device__ float g_Slo2 [N_CLASS*(N_ROWS/N_CLASS)];
__device__ float g_Phi2 [KR*N_CLASS];
__device__ float g_Plo2 [KR*N_CLASS];

// ---------------- warp-shuffle block exclusive scan ----------------
template<int NW>
__device__ __forceinline__ float blk_exscan(float v, float* sh, float& total) {
    __syncthreads();
    int lane = threadIdx.x & 31, warp = threadIdx.x >> 5;
    float x = v;
#pragma unroll
    for (int off = 1; off < 32; off <<= 1) {
        float n = __shfl_up_sync(0xffffffffu, x, off);
        if (lane >= off) x += n;
    }
    if (lane == 31) sh[warp] = x;
    __syncthreads();
    if (warp == 0) {
        float w = (lane < NW) ? sh[lane] : 0.f;
#pragma unroll
        for (int off = 1; off < 32; off <<= 1) {
            float n = __shfl_up_sync(0xffffffffu, w, off);
            if (lane >= off) w += n;
        }
        if (lane < NW) sh[lane] = w;
    }
    __syncthreads();
    float base = warp ? sh[warp - 1] : 0.f;
    total = sh[NW - 1];
    return base + x - v;
}

// ---------------- combined split fp32 -> bf16 hi/lo for x and Wh ----------------
#define NX4  (N_ROWS * N_FEAT / 4)
#define NW4  (N_HEADS * N_FEAT * N_HID / 4)
__global__ void splitall_kernel(const float* __restrict__ x, const float* __restrict__ Wh,
                                __nv_bfloat16* __restrict__ xh, __nv_bfloat16* __restrict__ xl,
                                __nv_bfloat16* __restrict__ whh, __nv_bfloat16* __restrict__ whl)
{
    int i = blockIdx.x * blockDim.x + threadIdx.x;
    const float* src; __nv_bfloat16 *hi, *lo; int j;
    if (i < NX4) { src = x; hi = xh; lo = xl; j = i; }
    else         { src = Wh; hi = whh; lo = whl; j = i - NX4; if (j >= NW4) return; }
    float4 v = reinterpret_cast<const float4*>(src)[j];
    __nv_bfloat16 h0 = __float2bfloat16_rn(v.x);
    __nv_bfloat16 h1 = __float2bfloat16_rn(v.y);
    __nv_bfloat16 h2 = __float2bfloat16_rn(v.z);
    __nv_bfloat16 h3 = __float2bfloat16_rn(v.w);
    __nv_bfloat16 l0 = __float2bfloat16_rn(v.x - __bfloat162float(h0));
    __nv_bfloat16 l1 = __float2bfloat16_rn(v.y - __bfloat162float(h1));
    __nv_bfloat16 l2 = __float2bfloat16_rn(v.z - __bfloat162float(h2));
    __nv_bfloat16 l3 = __float2bfloat16_rn(v.w - __bfloat162float(h3));
    __nv_bfloat162* hp = reinterpret_cast<__nv_bfloat162*>(hi) + j * 2;
    __nv_bfloat162* lp = reinterpret_cast<__nv_bfloat162*>(lo) + j * 2;
    hp[0] = __nv_bfloat162(h0, h1); hp[1] = __nv_bfloat162(h2, h3);
    lp[0] = __nv_bfloat162(l0, l1); lp[1] = __nv_bfloat162(l2, l3);
}

// ---------------- GEMM1 via bf16 mma.sync + fused scores epilogue ----------------
__device__ __forceinline__ void mma16816(float* c, const uint32_t* a, const uint32_t* b) {
    asm volatile(
        "mma.sync.aligned.m16n8k16.row.col.f32.bf16.bf16.f32 "
        "{%0,%1,%2,%3}, {%4,%5,%6,%7}, {%8,%9}, {%0,%1,%2,%3};\n"
        : "+f"(c[0]), "+f"(c[1]), "+f"(c[2]), "+f"(c[3])
        : "r"(a[0]), "r"(a[1]), "r"(a[2]), "r"(a[3]), "r"(b[0]), "r"(b[1]));
}

__global__ __launch_bounds__(256) void gemm1_mma_kernel(
    const __nv_bfloat16* __restrict__ xh, const __nv_bfloat16* __restrict__ xl,
    const __nv_bfloat16* __restrict__ whh, const __nv_bfloat16* __restrict__ whl,
    const float* __restrict__ ah,
    float* __restrict__ h1, float* __restrict__ ssrc, float* __restrict__ sdst)
{
    const int BM = 128, BKT = 64, SA = 72, SB = 72;
    __shared__ __nv_bfloat16 As[BM * SA];    // [m][k]
    __shared__ __nv_bfloat16 Bs[BKT * SB];   // [k][f]
    __shared__ float sred[2][2][BM];         // [wn][src/dst][rowlocal]
    int h = blockIdx.y;
    int row0 = blockIdx.x * BM;
    int tid = threadIdx.x;
    int wid = tid >> 5, lane = tid & 31;
    int wm = wid & 3, wn = wid >> 2;
    int lr = lane >> 2, lc = lane & 3;

    const __nv_bfloat16* Wb0 = whh + (size_t)h * N_FEAT * N_HID;
    const __nv_bfloat16* Wb1 = whl + (size_t)h * N_FEAT * N_HID;
    const __nv_bfloat16* Aph[3] = { xh, xl, xh };
    const __nv_bfloat16* Bph[3] = { Wb0, Wb0, Wb1 };

    float acc[2][4][4];
#pragma unroll
    for (int mm = 0; mm < 2; mm++)
#pragma unroll
        for (int nn = 0; nn < 4; nn++)
#pragma unroll
            for (int q = 0; q < 4; q++) acc[mm][nn][q] = 0.f;

    for (int p = 0; p < 3; p++) {
        const __nv_bfloat16* Ag = Aph[p];
        const __nv_bfloat16* Bg = Bph[p];
        for (int k0 = 0; k0 < N_FEAT; k0 += BKT) {
            __syncthreads();
#pragma unroll
            for (int i = 0; i < 4; i++) {
                int id4 = tid + i * 256;
                int r = id4 >> 3, kk = (id4 & 7) * 8;
                uint4 v = *reinterpret_cast<const uint4*>(
                    Ag + (size_t)(row0 + r) * N_FEAT + k0 + kk);
                *reinterpret_cast<uint4*>(As + r * SA + kk) = v;
            }
#pragma unroll
            for (int i = 0; i < 2; i++) {
                int id4 = tid + i * 256;
                int kk = id4 >> 3, ff = (id4 & 7) * 8;
                uint4 v = *reinterpret_cast<const uint4*>(
                    Bg + (size_t)(k0 + kk) * N_HID + ff);
                *reinterpret_cast<uint4*>(Bs + kk * SB + ff) = v;
            }
            __syncthreads();
#pragma unroll
            for (int ks = 0; ks < 4; ks++) {
                int kb = ks * 16;
                uint32_t afr[2][4];
#pragma unroll
                for (int mm = 0; mm < 2; mm++) {
                    const __nv_bfloat16* ap = As + (wm * 32 + mm * 16 + lr) * SA + kb + lc * 2;
                    afr[mm][0] = *reinterpret_cast<const uint32_t*>(ap);
                    afr[mm][1] = *reinterpret_cast<const uint32_t*>(ap + 8 * SA);
                    afr[mm][2] = *reinterpret_cast<const uint32_t*>(ap + 8);
                    afr[mm][3] = *reinterpret_cast<const uint32_t*>(ap + 8 * SA + 8);
                }
                uint32_t bfr[4][2];
#pragma unroll
                for (int nn = 0; nn < 4; nn++) {
                    int n = wn * 32 + nn * 8 + lr;
                    const __nv_bfloat16* bp = Bs + (kb + lc * 2) * SB + n;
                    unsigned short s0 = *reinterpret_cast<const unsigned short*>(bp);
                    unsigned short s1 = *reinterpret_cast<const unsigned short*>(bp + SB);
                    unsigned short s2 = *reinterpret_cast<const unsigned short*>(bp + 8 * SB);
                    unsigned short s3 = *reinterpret_cast<const unsigned short*>(bp + 9 * SB);
                    bfr[nn][0] = (uint32_t)s0 | ((uint32_t)s1 << 16);
                    bfr[nn][1] = (uint32_t)s2 | ((uint32_t)s3 << 16);
                }
#pragma unroll
                for (int mm = 0; mm < 2; mm++)
#pragma unroll
                    for (int nn = 0; nn < 4; nn++)
                        mma16816(acc[mm][nn], afr[mm], bfr[nn]);
            }
        }
    }
    // store h1 tile
#pragma unroll
    for (int mm = 0; mm < 2; mm++)
#pragma unroll
        for (int nn = 0; nn < 4; nn++) {
            int r = row0 + wm * 32 + mm * 16 + lr;
            int c = wn * 32 + nn * 8 + lc * 2;
            float* o = h1 + ((size_t)h * N_ROWS + r) * N_HID + c;
            *reinterpret_cast<float2*>(o) = make_float2(acc[mm][nn][0], acc[mm][nn][1]);
            *reinterpret_cast<float2*>(o + 8 * N_HID) = make_float2(acc[mm][nn][2], acc[mm][nn][3]);
        }

    // fused scores epilogue
    const float* a = ah + (size_t)h * 2 * N_HID;
#pragma unroll
    for (int mm = 0; mm < 2; mm++) {
        float ps1 = 0.f, pd1 = 0.f, ps2 = 0.f, pd2 = 0.f;
#pragma unroll
        for (int nn = 0; nn < 4; nn++) {
            int c0 = wn * 32 + nn * 8 + lc * 2;
            float a0s = a[c0], a1s = a[c0 + 1];
            float a0d = a[N_HID + c0], a1d = a[N_HID + c0 + 1];
            ps1 += acc[mm][nn][0] * a0s + acc[mm][nn][1] * a1s;
            pd1 += acc[mm][nn][0] * a0d + acc[mm][nn][1] * a1d;
            ps2 += acc[mm][nn][2] * a0s + acc[mm][nn][3] * a1s;
            pd2 += acc[mm][nn][2] * a0d + acc[mm][nn][3] * a1d;
        }
#pragma unroll
        for (int off = 1; off <= 2; off <<= 1) {
            ps1 += __shfl_xor_sync(0xffffffffu, ps1, off);
            pd1 += __shfl_xor_sync(0xffffffffu, pd1, off);
            ps2 += __shfl_xor_sync(0xffffffffu, ps2, off);
            pd2 += __shfl_xor_sync(0xffffffffu, pd2, off);
        }
        if (lc == 0) {
            int rl = wm * 32 + mm * 16 + lr;
            sred[wn][0][rl] = ps1; sred[wn][1][rl] = pd1;
            sred[wn][0][rl + 8] = ps2; sred[wn][1][rl + 8] = pd2;
        }
    }
    __syncthreads();
    if (tid < BM) {
        int gi = h * N_ROWS + row0 + tid;
        ssrc[gi] = sred[0][0][tid] + sred[1][0][tid];
        sdst[gi] = sred[0][1][tid] + sred[1][1][tid];
    }
}

// ---------------- fused hybrid bitonic sort (descending) + scalar scans ----------------
__global__ __launch_bounds__(1024) void sortscan_kernel(
    const float* __restrict__ sdst, float* __restrict__ sorted, int* __restrict__ idx,
    float* __restrict__ ew, float* __restrict__ gw,
    float* __restrict__ Zhi, float* __restrict__ Zlo)
{
    int h = blockIdx.x;
    __shared__ unsigned long long buf[N_ROWS];
    __shared__ float sh[40];
    int tid = threadIdx.x;

    float key[4]; int id[4];
    float4 v4 = *reinterpret_cast<const float4*>(sdst + (size_t)h * N_ROWS + tid * 4);
    key[0] = v4.x; key[1] = v4.y; key[2] = v4.z; key[3] = v4.w;
    id[0] = tid * 4; id[1] = tid * 4 + 1; id[2] = tid * 4 + 2; id[3] = tid * 4 + 3;

    for (int k = 2; k <= N_ROWS; k <<= 1) {
        for (int j = k >> 1; j > 0; j >>= 1) {
            if (j == 1) {
#pragma unroll
                for (int q = 0; q < 4; q += 2) {
                    int e = tid * 4 + q;
                    bool desc = ((e & k) == 0);
                    bool sw = desc ? (key[q] < key[q + 1]) : (key[q] > key[q + 1]);
                    if (sw) {
                        float tk = key[q]; key[q] = key[q + 1]; key[q + 1] = tk;
                        int ti = id[q]; id[q] = id[q + 1]; id[q + 1] = ti;
                    }
                }
            } else if (j == 2) {
#pragma unroll
                for (int q = 0; q < 2; q++) {
                    int e = tid * 4 + q;
                    bool desc = ((e & k) == 0);
                    bool sw = desc ? (key[q] < key[q + 2]) : (key[q] > key[q + 2]);
                    if (sw) {
                        float tk = key[q]; key[q] = key[q + 2]; key[q + 2] = tk;
                        int ti = id[q]; id[q] = id[q + 2]; id[q + 2] = ti;
                    }
                }
            } else if (j <= 64) {
                int m = j >> 2;
#pragma unroll
                for (int q = 0; q < 4; q++) {
                    float ok = __shfl_xor_sync(0xffffffffu, key[q], m);
                    int   oi = __shfl_xor_sync(0xffffffffu, id[q], m);
                    int e = tid * 4 + q;
                    bool lower = ((e & j) == 0);
                    bool desc = ((e & k) == 0);
                    float a = lower ? key[q] : ok;
                    float b = lower ? ok : key[q];
                    bool sw = desc ? (a < b) : (a > b);
                    if (sw) { key[q] = ok; id[q] = oi; }
                }
            } else {
                __syncthreads();
#pragma unroll
                for (int q = 0; q < 4; q++) {
                    int e = tid * 4 + q;
                    buf[e] = ((unsigned long long)__float_as_uint(key[q]) << 32)
                             | (unsigned int)id[q];
                }
                __syncthreads();
#pragma unroll
                for (int q = 0; q < 4; q++) {
                    int e = tid * 4 + q;
                    unsigned long long o = buf[e ^ j];
                    float ok = __uint_as_float((unsigned int)(o >> 32));
                    int oi = (int)(unsigned int)(o & 0xffffffffu);
                    bool lower = ((e & j) == 0);
                    bool desc = ((e & k) == 0);
                    float a = lower ? key[q] : ok;
                    float b = lower ? ok : key[q];
                    bool sw = desc ? (a < b) : (a > b);
                    if (sw) { key[q] = ok; id[q] = oi; }
                }
            }
        }
    }
    __syncthreads();

    *reinterpret_cast<float4*>(sorted + (size_t)h * N_ROWS + tid * 4) =
        make_float4(key[0], key[1], key[2], key[3]);
    *reinterpret_cast<int4*>(idx + (size_t)h * N_ROWS + tid * 4) =
        make_int4(id[0], id[1], id[2], id[3]);

    if (tid == 0) sh[36] = key[0];
    __syncthreads();
    float M = sh[36];

    float e4[4], g4[4];
    float se = 0.f, sg = 0.f;
#pragma unroll
    for (int q = 0; q < 4; q++) {
        float xv = key[q] - M;
        e4[q] = expf(xv);
        g4[q] = expf(0.2f * xv);
        se += e4[q]; sg += g4[q];
    }
    *reinterpret_cast<float4*>(ew + (size_t)h * N_ROWS + tid * 4) =
        make_float4(e4[0], e4[1], e4[2], e4[3]);
    *reinterpret_cast<float4*>(gw + (size_t)h * N_ROWS + tid * 4) =
        make_float4(g4[0], g4[1], g4[2], g4[3]);

    float tote, totg;
    float pe = blk_exscan<32>(se, sh, tote);
    float pg = blk_exscan<32>(sg, sh, totg);

    float* ZH = Zhi + (size_t)h * PS;
    float* ZL = Zlo + (size_t)h * PS;
    float run = pe;
#pragma unroll
    for (int q = 0; q < 4; q++) { ZH[tid * 4 + q] = run; run += e4[q]; }
    float run2 = pg;
#pragma unroll
    for (int q = 0; q < 4; q++) { ZL[tid * 4 + q] = totg - run2; run2 += g4[q]; }
    if (tid == 1023) { ZH[N_ROWS] = run; ZL[N_ROWS] = 0.f; }
}

// ---------------- layer1 featA: chunk sums, 1024 threads, 16-row segments ----------------
__global__ __launch_bounds__(1024) void featA1_kernel(
    const float* __restrict__ hsrc, const int* __restrict__ idx,
    const float* __restrict__ ew, const float* __restrict__ gw,
    float* __restrict__ Chi, float* __restrict__ Clo)
{
    __shared__ int   sidx[256];
    __shared__ float sew[256], sgw[256];
    __shared__ float sH[16][N_HID], sL[16][N_HID];
    int h = blockIdx.y, chunk = blockIdx.x;
    int t = threadIdx.x;
    int ft = t & 63, rg = t >> 6;
    if (t < 256) {
        int base = h * N_ROWS + chunk * 256 + t;
        sidx[t] = idx[base]; sew[t] = ew[base]; sgw[t] = gw[base];
    }
    __syncthreads();
    const float* hb = hsrc + (size_t)h * N_ROWS * N_HID + ft;
    float sh_ = 0.f, sl_ = 0.f;
#pragma unroll
    for (int j = 0; j < 16; j++) {
        int rl = rg * 16 + j;
        float v = hb[(size_t)sidx[rl] * N_HID];
        sh_ += v * sew[rl];
        sl_ += v * sgw[rl];
    }
    sH[rg][ft] = sh_; sL[rg][ft] = sl_;
    __syncthreads();
    if (rg == 0) {
        float a = 0.f, b = 0.f;
#pragma unroll
        for (int r = 0; r < 16; r++) { a += sH[r][ft]; b += sL[r][ft]; }
        Chi[(h * N_HID + ft) * 16 + chunk] = a;
        Clo[(h * N_HID + ft) * 16 + chunk] = b;
    }
}

// ---------------- layer1 featC: final scan, 1024 threads ----------------
__global__ __launch_bounds__(1024) void featC1_kernel(
    const float* __restrict__ hsrc, const int* __restrict__ idx,
    const float* __restrict__ ew, const float* __restrict__ gw,
    const float* __restrict__ Chi, const float* __restrict__ Clo,
    float* __restrict__ Phi, float* __restrict__ Plo)
{
    __shared__ int   sidx[256];
    __shared__ float sew[256], sgw[256];
    __shared__ float sChi[N_HID * 16], sClo[N_HID * 16];   // [ft][chunk]
    __shared__ float sH[16][N_HID], sL[16][N_HID];
    int h = blockIdx.y, chunk = blockIdx.x;
    int t = threadIdx.x;
    int ft = t & 63, rg = t >> 6;
    if (t < 256) {
        int base = h * N_ROWS + chunk * 256 + t;
        sidx[t] = idx[base]; sew[t] = ew[base]; sgw[t] = gw[base];
    }
    sChi[t] = Chi[h * N_HID * 16 + t];
    sClo[t] = Clo[h * N_HID * 16 + t];
    __syncthreads();
    const float* hb = hsrc + (size_t)h * N_ROWS * N_HID + ft;
    float vh[16], vl[16];
    float sh_ = 0.f, sl_ = 0.f;
#pragma unroll
    for (int j = 0; j < 16; j++) {
        int rl = rg * 16 + j;
        float v = hb[(size_t)sidx[rl] * N_HID];
        vh[j] = v * sew[rl];
        vl[j] = v * sgw[rl];
        sh_ += vh[j]; sl_ += vl[j];
    }
    sH[rg][ft] = sh_; sL[rg][ft] = sl_;
    __syncthreads();
    float offh = 0.f, offl = 0.f, totl = 0.f;
#pragma unroll
    for (int c = 0; c < 16; c++) {
        float a = sChi[ft * 16 + c], b = sClo[ft * 16 + c];
        if (c < chunk) { offh += a; offl += b; }
        totl += b;
    }
    for (int r = 0; r < rg; r++) { offh += sH[r][ft]; offl += sL[r][ft]; }
    float* PH = Phi + (size_t)h * KR * N_HID + ft;
    float* PL = Plo + (size_t)h * KR * N_HID + ft;
    float runh = offh, runl = offl;
    int k0 = chunk * 256 + rg * 16;
#pragma unroll
    for (int j = 0; j < 16; j++) {
        PH[(size_t)(k0 + j) * N_HID] = runh;
        PL[(size_t)(k0 + j) * N_HID] = totl - runl;
        runh += vh[j];
        runl += vl[j];
    }
    if (chunk == 15 && rg == 15) {
        PH[(size_t)N_ROWS * N_HID] = runh;
        PL[(size_t)N_ROWS * N_HID] = totl - runl;
    }
}

// ---------------- layer2 featA (old style, F=16) ----------------
template<int F>
__global__ __launch_bounds__(256) void featA_kernel(
    const float* __restrict__ hsrc, const int* __restrict__ idx,
    const float* __restrict__ ew, const float* __restrict__ gw,
    float* __restrict__ Shi, float* __restrict__ Slo)
{
    const int SEGS = 256 / F;
    const int SEGTOT = N_ROWS / F;
    __shared__ int   sidx[256];
    __shared__ float sew[256], sgw[256];
    int h = blockIdx.y, chunk = blockIdx.x;
    int t = threadIdx.x;
    int base = h * N_ROWS + chunk * 256 + t;
    sidx[t] = idx[base];
    sew[t] = ew[base];
    sgw[t] = gw[base];
    __syncthreads();
    int ft = t % F, rg = t / F;
    const float* hb = hsrc + (size_t)h * N_ROWS * F + ft;
    float shi = 0.f, slo = 0.f;
#pragma unroll 4
    for (int j = 0; j < F; j++) {
        int rl = rg * F + j;
        float v = hb[(size_t)sidx[rl] * F];
        shi += v * sew[rl];
        slo += v * sgw[rl];
    }
    int seg = chunk * SEGS + rg;
    Shi[(size_t)(h * F + ft) * SEGTOT + seg] = shi;
    Slo[(size_t)(h * F + ft) * SEGTOT + seg] = slo;
}

template<int F>
__global__ __launch_bounds__(256) void featC_kernel(
    const float* __restrict__ hsrc, const int* __restrict__ idx,
    const float* __restrict__ ew, const float* __restrict__ gw,
    const float* __restrict__ Shi, const float* __restrict__ Slo,
    float* __restrict__ Phi, float* __restrict__ Plo)
{
    const int SEGS = 256 / F;
    const int SEGTOT = N_ROWS / F;
    __shared__ int   sidx[256];
    __shared__ float sew[256], sgw[256];
    __shared__ float sSh[4096], sSl[4096];
    int h = blockIdx.y, chunk = blockIdx.x;
    int t = threadIdx.x;
    int base = h * N_ROWS + chunk * 256 + t;
    sidx[t] = idx[base];
    sew[t] = ew[base];
    sgw[t] = gw[base];
    const float* ShB = Shi + (size_t)h * F * SEGTOT;
    const float* SlB = Slo + (size_t)h * F * SEGTOT;
#pragma unroll
    for (int i = 0; i < 4096 / 256; i++) {
        sSh[t + i * 256] = ShB[t + i * 256];
        sSl[t + i * 256] = SlB[t + i * 256];
    }
    __syncthreads();
    int ft = t % F, rg = t / F;
    int myseg = chunk * SEGS + rg;
    float offh = 0.f, offl = 0.f, totl = 0.f;
    const float* rh = sSh + ft * SEGTOT;
    const float* rl = sSl + ft * SEGTOT;
    for (int s = 0; s < SEGTOT; s++) {
        float a = rh[s], b = rl[s];
        if (s < myseg) { offh += a; offl += b; }
        totl += b;
    }
    const float* hb = hsrc + (size_t)h * N_ROWS * F + ft;
    float* PH = Phi + ((size_t)h * KR) * F + ft;
    float* PL = Plo + ((size_t)h * KR) * F + ft;
    float runh = offh, runl = offl;
    int r0 = chunk * 256 + rg * F;
#pragma unroll 4
    for (int j = 0; j < F; j++) {
        int rl_ = rg * F + j;
        int r = r0 + j;
        float v = hb[(size_t)sidx[rl_] * F];
        PH[(size_t)r * F] = runh;
        PL[(size_t)r * F] = totl - runl;
        runh += v * sew[rl_];
        runl += v * sgw[rl_];
    }
    if (myseg == SEGTOT - 1) {
        PH[(size_t)N_ROWS * F] = runh;
        PL[(size_t)N_ROWS * F] = totl - runl;
    }
}

// ---------------- combine layer1 (Phi[h][k][f] layout) ----------------
__global__ __launch_bounds__(256) void combine1_kernel(
    const float* __restrict__ ssrc, const float* __restrict__ sorted,
    const float* __restrict__ Zhi, const float* __restrict__ Zlo,
    const float* __restrict__ Phi, const float* __restrict__ Plo,
    float* __restrict__ xc)
{
    int h = blockIdx.y;
    __shared__ float ss[N_ROWS];
    const float* sb = sorted + (size_t)h * N_ROWS;
#pragma unroll
    for (int r = 0; r < 4; r++) {
        int off = (threadIdx.x + r * 256) * 4;
        *reinterpret_cast<float4*>(ss + off) = *reinterpret_cast<const float4*>(sb + off);
    }
    __syncthreads();
    int warp = threadIdx.x >> 5, lane = threadIdx.x & 31;
    float M = ss[0];
    const float* ZH = Zhi + (size_t)h * PS;
    const float* ZL = Zlo + (size_t)h * PS;
    const float* PHb = Phi + (size_t)h * KR * N_HID;
    const float* PLb = Plo + (size_t)h * KR * N_HID;
#pragma unroll
    for (int rr = 0; rr < 4; rr++) {
        int i = blockIdx.x * 32 + warp * 4 + rr;
        float s = ssrc[(size_t)h * N_ROWS + i];
        float thr = -s;
        int lo = 0, hi = N_ROWS;
        while (lo < hi) {
            int mid = (lo + hi) >> 1;
            if (ss[mid] >= thr) lo = mid + 1; else hi = mid;
        }
        int k = lo;
        float rho = expf(-0.8f * (s + M));
        float den = (k == 0) ? ZL[0] : (ZH[k] + rho * ZL[k]);
        float inv = 1.f / den;
        const float* ph = PHb + (size_t)k * N_HID;
        const float* pl = PLb + (size_t)k * N_HID;
#pragma unroll
        for (int u = 0; u < 2; u++) {
            int f = lane + 32 * u;
            float num = (k == 0) ? pl[f] : (ph[f] + rho * pl[f]);
            float feat = num * inv;
            float v = feat > 0.f ? feat : expm1f(feat);
            xc[(size_t)i * N_FEAT + h * N_HID + f] = v;
        }
    }
}

// ---------------- GEMM2: h2 = xc @ Wo + fused scores2 epilogue ----------------
__global__ __launch_bounds__(256) void gemm2_kernel(
    const float* __restrict__ xc, const float* __restrict__ Wo,
    const float* __restrict__ ao,
    float* __restrict__ h2, float* __restrict__ ssrc, float* __restrict__ sdst)
{
    __shared__ float xs[16][64];
    __shared__ float ws[64][16];
    int ir = threadIdx.x >> 4, fc = threadIdx.x & 15;
    int row0 = blockIdx.x * 16;
    float acc = 0.f;
    for (int k0 = 0; k0 < N_FEAT; k0 += 64) {
#pragma unroll
        for (int rep = 0; rep < 4; rep++) {
            int t = threadIdx.x + rep * 256;
            int r = t >> 6, kk = t & 63;
            xs[r][kk] = xc[(size_t)(row0 + r) * N_FEAT + k0 + kk];
        }
#pragma unroll
        for (int rep = 0; rep < 4; rep++) {
            int t = threadIdx.x + rep * 256;
            int kk = t >> 4, f = t & 15;
            ws[kk][f] = Wo[(size_t)(k0 + kk) * N_CLASS + f];
        }
        __syncthreads();
#pragma unroll
        for (int kk = 0; kk < 64; kk++) acc += xs[ir][kk] * ws[kk][fc];
        __syncthreads();
    }
    h2[(size_t)(row0 + ir) * N_CLASS + fc] = acc;
    float ps = acc * ao[fc];
    float pd = acc * ao[N_CLASS + fc];
#pragma unroll
    for (int off = 1; off < 16; off <<= 1) {
        ps += __shfl_xor_sync(0xffffffffu, ps, off);
        pd += __shfl_xor_sync(0xffffffffu, pd, off);
    }
    if (fc == 0) {
        ssrc[row0 + ir] = ps;
        sdst[row0 + ir] = pd;
    }
}

// ---------------- combine2 + ELU + log_softmax (Phi2[k][16] layout) ----------------
__global__ __launch_bounds__(256) void combine2_kernel(
    const float* __restrict__ ssrc, const float* __restrict__ sorted,
    const float* __restrict__ Zhi, const float* __restrict__ Zlo,
    const float* __restrict__ Phi, const float* __restrict__ Plo,
    float* __restrict__ out)
{
    __shared__ float ss[N_ROWS];
#pragma unroll
    for (int r = 0; r < 4; r++) {
        int off = (threadIdx.x + r * 256) * 4;
        *reinterpret_cast<float4*>(ss + off) = *reinterpret_cast<const float4*>(sorted + off);
    }
    __syncthreads();
    int warp = threadIdx.x >> 5, lane = threadIdx.x & 31;
    int sub = lane >> 4, f = lane & 15;
    float M = ss[0];
#pragma unroll
    for (int rr = 0; rr < 4; rr++) {
        int i = blockIdx.x * 64 + warp * 8 + rr * 2 + sub;
        float s = ssrc[i];
        float thr = -s;
        int lo = 0, hi = N_ROWS;
        while (lo < hi) {
            int mid = (lo + hi) >> 1;
            if (ss[mid] >= thr) lo = mid + 1; else hi = mid;
        }
        int k = lo;
        float rho = expf(-0.8f * (s + M));
        float den = (k == 0) ? Zlo[0] : (Zhi[k] + rho * Zlo[k]);
        float num = (k == 0) ? Plo[f] : (Phi[(size_t)k * N_CLASS + f] + rho * Plo[(size_t)k * N_CLASS + f]);
        float feat = num / den;
        float v = feat > 0.f ? feat : expm1f(feat);
        float m = v;
#pragma unroll
        for (int off = 8; off; off >>= 1) m = fmaxf(m, __shfl_xor_sync(0xffffffffu, m, off));
        float ex = expf(v - m);
        float ssum = ex;
#pragma unroll
        for (int off = 8; off; off >>= 1) ssum += __shfl_xor_sync(0xffffffffu, ssum, off);
        out[(size_t)i * N_CLASS + f] = v - m - logf(ssum);
    }
}

// ---------------- launch ----------------
extern "C" void kernel_launch(void* const* d_in, const int* in_sizes, int n_in,
                              void* d_out, int out_size)
{
    const float* x  = (const float*)d_in[0];
    const float* Wh = (const float*)d_in[1];
    const float* ah = (const float*)d_in[2];
    const float* Wo = (const float*)d_in[3];
    const float* ao = (const float*)d_in[4];
    float* out = (float*)d_out;

    __nv_bfloat16 *p_xh, *p_xl, *p_whh, *p_whl;
    float *p_h1, *p_ssrc1, *p_sdst1, *p_sorted1, *p_ew1, *p_gw1, *p_Zhi1, *p_Zlo1;
    float *p_Chi1, *p_Clo1, *p_Phi1, *p_Plo1, *p_xc;
    int *p_idx1;
    float *p_h2, *p_ssrc2, *p_sdst2, *p_sorted2, *p_ew2, *p_gw2, *p_Zhi2, *p_Zlo2;
    float *p_Shi2, *p_Slo2, *p_Phi2, *p_Plo2;
    int *p_idx2;

    cudaGetSymbolAddress((void**)&p_xh, g_xh);
    cudaGetSymbolAddress((void**)&p_xl, g_xl);
    cudaGetSymbolAddress((void**)&p_whh, g_whh);
    cudaGetSymbolAddress((void**)&p_whl, g_whl);
    cudaGetSymbolAddress((void**)&p_h1, g_h1);
    cudaGetSymbolAddress((void**)&p_ssrc1, g_ssrc1);
    cudaGetSymbolAddress((void**)&p_sdst1, g_sdst1);
    cudaGetSymbolAddress((void**)&p_sorted1, g_sorted1);
    cudaGetSymbolAddress((void**)&p_idx1, g_idx1);
    cudaGetSymbolAddress((void**)&p_ew1, g_ew1);
    cudaGetSymbolAddress((void**)&p_gw1, g_gw1);
    cudaGetSymbolAddress((void**)&p_Zhi1, g_Zhi1);
    cudaGetSymbolAddress((void**)&p_Zlo1, g_Zlo1);
    cudaGetSymbolAddress((void**)&p_Chi1, g_Chi1);
    cudaGetSymbolAddress((void**)&p_Clo1, g_Clo1);
    cudaGetSymbolAddress((void**)&p_Phi1, g_Phi1);
    cudaGetSymbolAddress((void**)&p_Plo1, g_Plo1);
    cudaGetSymbolAddress((void**)&p_xc, g_xc);
    cudaGetSymbolAddress((void**)&p_h2, g_h2);
    cudaGetSymbolAddress((void**)&p_ssrc2, g_ssrc2);
    cudaGetSymbolAddress((void**)&p_sdst2, g_sdst2);
    cudaGetSymbolAddress((void**)&p_sorted2, g_sorted2);
    cudaGetSymbolAddress((void**)&p_idx2, g_idx2);
    cudaGetSymbolAddress((void**)&p_ew2, g_ew2);
    cudaGetSymbolAddress((void**)&p_gw2, g_gw2);
    cudaGetSymbolAddress((void**)&p_Zhi2, g_Zhi2);
    cudaGetSymbolAddress((void**)&p_Zlo2, g_Zlo2);
    cudaGetSymbolAddress((void**)&p_Shi2, g_Shi2);
    cudaGetSymbolAddress((void**)&p_Slo2, g_Slo2);
    cudaGetSymbolAddress((void**)&p_Phi2, g_Phi2);
    cudaGetSymbolAddress((void**)&p_Plo2, g_Plo2);

    // ---- combined splits ----
    splitall_kernel<<<(NX4 + NW4 + 255) / 256, 256>>>(x, Wh, p_xh, p_xl, p_whh, p_whl);

    // ---- layer 1 ----
    gemm1_mma_kernel<<<dim3(N_ROWS / 128, N_HEADS), 256>>>(p_xh, p_xl, p_whh, p_whl, ah,
                                                           p_h1, p_ssrc1, p_sdst1);
    sortscan_kernel<<<N_HEADS, 1024>>>(p_sdst1, p_sorted1, p_idx1, p_ew1, p_gw1, p_Zhi1, p_Zlo1);
    featA1_kernel<<<dim3(16, N_HEADS), 1024>>>(p_h1, p_idx1, p_ew1, p_gw1, p_Chi1, p_Clo1);
    featC1_kernel<<<dim3(16, N_HEADS), 1024>>>(p_h1, p_idx1, p_ew1, p_gw1,
                                               p_Chi1, p_Clo1, p_Phi1, p_Plo1);
    combine1_kernel<<<dim3(N_ROWS / 32, N_HEADS), 256>>>(p_ssrc1, p_sorted1, p_Zhi1, p_Zlo1,
                                                         p_Phi1, p_Plo1, p_xc);
    // ---- layer 2 ----
    gemm2_kernel<<<N_ROWS / 16, 256>>>(p_xc, Wo, ao, p_h2, p_ssrc2, p_sdst2);
    sortscan_kernel<<<1, 1024>>>(p_sdst2, p_sorted2, p_idx2, p_ew2, p_gw2, p_Zhi2, p_Zlo2);
    featA_kernel<N_CLASS><<<dim3(16, 1), 256>>>(p_h2, p_idx2, p_ew2, p_gw2, p_Shi2, p_Slo2);
    featC_kernel<N_CLASS><<<dim3(16, 1), 256>>>(p_h2, p_idx2, p_ew2, p_gw2,
                                                p_Shi2, p_Slo2, p_Phi2, p_Plo2);
    combine2_kernel<<<N_ROWS / 64, 256>>>(p_ssrc2, p_sorted2, p_Zhi2, p_Zlo2,
                                          p_Phi2, p_Plo2, out);

    (void)in_sizes; (void)n_in; (void)out_size;
}

// round 7
// speedup vs baseline: 1.4984x; 1.0421x over previous
#include <cuda_runtime.h>
#include <cuda_bf16.h>
#include <cstdint>

#define N_ROWS   4096
#define N_FEAT   512
#define N_HID    64
#define N_CLASS  16
#define N_HEADS  8
#define PS       (N_ROWS + 4)   // Zhi/Zlo padded stride
#define KR       (N_ROWS + 1)   // Phi/Plo k-rows

// ---------------- scratch (static device memory; no allocations) ----------------
__device__ __nv_bfloat16 g_xh [N_ROWS*N_FEAT];
__device__ __nv_bfloat16 g_xl [N_ROWS*N_FEAT];
__device__ __nv_bfloat16 g_whh[N_HEADS*N_FEAT*N_HID];
__device__ __nv_bfloat16 g_whl[N_HEADS*N_FEAT*N_HID];

__device__ float g_h1   [N_HEADS*N_ROWS*N_HID];
__device__ float g_ssrc1[N_HEADS*N_ROWS];
__device__ float g_sdst1[N_HEADS*N_ROWS];
__device__ float g_sorted1[N_HEADS*N_ROWS];
__device__ int   g_idx1 [N_HEADS*N_ROWS];
__device__ float g_ew1  [N_HEADS*N_ROWS];
__device__ float g_gw1  [N_HEADS*N_ROWS];
__device__ float g_Zhi1 [N_HEADS*PS];
__device__ float g_Zlo1 [N_HEADS*PS];
__device__ float g_Chi1 [N_HEADS*N_HID*16];
__device__ float g_Clo1 [N_HEADS*N_HID*16];
__device__ float g_Phi1 [N_HEADS*KR*N_HID];
__device__ float g_Plo1 [N_HEADS*KR*N_HID];
__device__ float g_xc   [N_ROWS*N_FEAT];

__device__ float g_h2   [N_ROWS*N_CLASS];
__device__ float g_ssrc2[N_ROWS];
__device__ float g_sdst2[N_ROWS];
__device__ float g_sorted2[N_ROWS];
__device__ int   g_idx2 [N_ROWS];
__device__ float g_ew2  [N_ROWS];
__device__ float g_gw2  [N_ROWS];
__device__ float g_Zhi2 [PS];
__device__ float g_Zlo2 [PS];
__device__ float g_Shi2 [N_CLASS*(N_ROWS/N_CLASS)];
__device__ float g_Slo2 [N_CLASS*(N_ROWS/N_CLASS)];
__device__ float g_Phi2 [KR*N_CLASS];
__device__ float g_Plo2 [KR*N_CLASS];

// ---------------- warp-shuffle block exclusive scan ----------------
template<int NW>
__device__ __forceinline__ float blk_exscan(float v, float* sh, float& total) {
    __syncthreads();
    int lane = threadIdx.x & 31, warp = threadIdx.x >> 5;
    float x = v;
#pragma unroll
    for (int off = 1; off < 32; off <<= 1) {
        float n = __shfl_up_sync(0xffffffffu, x, off);
        if (lane >= off) x += n;
    }
    if (lane == 31) sh[warp] = x;
    __syncthreads();
    if (warp == 0) {
        float w = (lane < NW) ? sh[lane] : 0.f;
#pragma unroll
        for (int off = 1; off < 32; off <<= 1) {
            float n = __shfl_up_sync(0xffffffffu, w, off);
            if (lane >= off) w += n;
        }
        if (lane < NW) sh[lane] = w;
    }
    __syncthreads();
    float base = warp ? sh[warp - 1] : 0.f;
    total = sh[NW - 1];
    return base + x - v;
}

// ---------------- combined split fp32 -> bf16 hi/lo for x and Wh ----------------
#define NX4  (N_ROWS * N_FEAT / 4)
#define NW4  (N_HEADS * N_FEAT * N_HID / 4)
__global__ void splitall_kernel(const float* __restrict__ x, const float* __restrict__ Wh,
                                __nv_bfloat16* __restrict__ xh, __nv_bfloat16* __restrict__ xl,
                                __nv_bfloat16* __restrict__ whh, __nv_bfloat16* __restrict__ whl)
{
    int i = blockIdx.x * blockDim.x + threadIdx.x;
    const float* src; __nv_bfloat16 *hi, *lo; int j;
    if (i < NX4) { src = x; hi = xh; lo = xl; j = i; }
    else         { src = Wh; hi = whh; lo = whl; j = i - NX4; if (j >= NW4) return; }
    float4 v = reinterpret_cast<const float4*>(src)[j];
    __nv_bfloat16 h0 = __float2bfloat16_rn(v.x);
    __nv_bfloat16 h1 = __float2bfloat16_rn(v.y);
    __nv_bfloat16 h2 = __float2bfloat16_rn(v.z);
    __nv_bfloat16 h3 = __float2bfloat16_rn(v.w);
    __nv_bfloat16 l0 = __float2bfloat16_rn(v.x - __bfloat162float(h0));
    __nv_bfloat16 l1 = __float2bfloat16_rn(v.y - __bfloat162float(h1));
    __nv_bfloat16 l2 = __float2bfloat16_rn(v.z - __bfloat162float(h2));
    __nv_bfloat16 l3 = __float2bfloat16_rn(v.w - __bfloat162float(h3));
    __nv_bfloat162* hp = reinterpret_cast<__nv_bfloat162*>(hi) + j * 2;
    __nv_bfloat162* lp = reinterpret_cast<__nv_bfloat162*>(lo) + j * 2;
    hp[0] = __nv_bfloat162(h0, h1); hp[1] = __nv_bfloat162(h2, h3);
    lp[0] = __nv_bfloat162(l0, l1); lp[1] = __nv_bfloat162(l2, l3);
}

// ---------------- GEMM1 via bf16 mma.sync + ldmatrix + fused scores epilogue ----------------
__device__ __forceinline__ void mma16816(float* c, const uint32_t* a, const uint32_t* b) {
    asm volatile(
        "mma.sync.aligned.m16n8k16.row.col.f32.bf16.bf16.f32 "
        "{%0,%1,%2,%3}, {%4,%5,%6,%7}, {%8,%9}, {%0,%1,%2,%3};\n"
        : "+f"(c[0]), "+f"(c[1]), "+f"(c[2]), "+f"(c[3])
        : "r"(a[0]), "r"(a[1]), "r"(a[2]), "r"(a[3]), "r"(b[0]), "r"(b[1]));
}

__device__ __forceinline__ void ldmat_x4(uint32_t* r, uint32_t addr) {
    asm volatile("ldmatrix.sync.aligned.m8n8.x4.shared.b16 {%0,%1,%2,%3}, [%4];"
        : "=r"(r[0]), "=r"(r[1]), "=r"(r[2]), "=r"(r[3]) : "r"(addr));
}
__device__ __forceinline__ void ldmat_x4_t(uint32_t* r, uint32_t addr) {
    asm volatile("ldmatrix.sync.aligned.m8n8.x4.trans.shared.b16 {%0,%1,%2,%3}, [%4];"
        : "=r"(r[0]), "=r"(r[1]), "=r"(r[2]), "=r"(r[3]) : "r"(addr));
}

__global__ __launch_bounds__(256) void gemm1_mma_kernel(
    const __nv_bfloat16* __restrict__ xh, const __nv_bfloat16* __restrict__ xl,
    const __nv_bfloat16* __restrict__ whh, const __nv_bfloat16* __restrict__ whl,
    const float* __restrict__ ah,
    float* __restrict__ h1, float* __restrict__ ssrc, float* __restrict__ sdst)
{
    const int BM = 128, BKT = 64, SA = 72, SB = 72;
    __shared__ __nv_bfloat16 As[BM * SA];    // [m][k]
    __shared__ __nv_bfloat16 Bs[BKT * SB];   // [k][f]
    __shared__ float sred[2][2][BM];         // [wn][src/dst][rowlocal]
    int h = blockIdx.y;
    int row0 = blockIdx.x * BM;
    int tid = threadIdx.x;
    int wid = tid >> 5, lane = tid & 31;
    int wm = wid & 3, wn = wid >> 2;
    int lr = lane >> 2, lc = lane & 3;
    int idx15 = lane & 15, hi8 = (lane >> 4) << 3;

    uint32_t sa_base = (uint32_t)__cvta_generic_to_shared(As);
    uint32_t sb_base = (uint32_t)__cvta_generic_to_shared(Bs);

    const __nv_bfloat16* Wb0 = whh + (size_t)h * N_FEAT * N_HID;
    const __nv_bfloat16* Wb1 = whl + (size_t)h * N_FEAT * N_HID;
    const __nv_bfloat16* Aph[3] = { xh, xl, xh };
    const __nv_bfloat16* Bph[3] = { Wb0, Wb0, Wb1 };

    float acc[2][4][4];
#pragma unroll
    for (int mm = 0; mm < 2; mm++)
#pragma unroll
        for (int nn = 0; nn < 4; nn++)
#pragma unroll
            for (int q = 0; q < 4; q++) acc[mm][nn][q] = 0.f;

    for (int p = 0; p < 3; p++) {
        const __nv_bfloat16* Ag = Aph[p];
        const __nv_bfloat16* Bg = Bph[p];
        for (int k0 = 0; k0 < N_FEAT; k0 += BKT) {
            __syncthreads();
#pragma unroll
            for (int i = 0; i < 4; i++) {
                int id4 = tid + i * 256;
                int r = id4 >> 3, kk = (id4 & 7) * 8;
                uint4 v = *reinterpret_cast<const uint4*>(
                    Ag + (size_t)(row0 + r) * N_FEAT + k0 + kk);
                *reinterpret_cast<uint4*>(As + r * SA + kk) = v;
            }
#pragma unroll
            for (int i = 0; i < 2; i++) {
                int id4 = tid + i * 256;
                int kk = id4 >> 3, ff = (id4 & 7) * 8;
                uint4 v = *reinterpret_cast<const uint4*>(
                    Bg + (size_t)(k0 + kk) * N_HID + ff);
                *reinterpret_cast<uint4*>(Bs + kk * SB + ff) = v;
            }
            __syncthreads();
#pragma unroll
            for (int ks = 0; ks < 4; ks++) {
                int kb = ks * 16;
                uint32_t afr[2][4];
#pragma unroll
                for (int mm = 0; mm < 2; mm++) {
                    uint32_t addr = sa_base +
                        (uint32_t)((wm * 32 + mm * 16 + idx15) * SA + kb + hi8) * 2u;
                    ldmat_x4(afr[mm], addr);
                }
                uint32_t bfr[4][2];
#pragma unroll
                for (int bp = 0; bp < 2; bp++) {
                    uint32_t bt[4];
                    uint32_t addr = sb_base +
                        (uint32_t)((kb + idx15) * SB + wn * 32 + bp * 16 + hi8) * 2u;
                    ldmat_x4_t(bt, addr);
                    bfr[bp * 2][0] = bt[0]; bfr[bp * 2][1] = bt[1];
                    bfr[bp * 2 + 1][0] = bt[2]; bfr[bp * 2 + 1][1] = bt[3];
                }
#pragma unroll
                for (int mm = 0; mm < 2; mm++)
#pragma unroll
                    for (int nn = 0; nn < 4; nn++)
                        mma16816(acc[mm][nn], afr[mm], bfr[nn]);
            }
        }
    }
    // store h1 tile
#pragma unroll
    for (int mm = 0; mm < 2; mm++)
#pragma unroll
        for (int nn = 0; nn < 4; nn++) {
            int r = row0 + wm * 32 + mm * 16 + lr;
            int c = wn * 32 + nn * 8 + lc * 2;
            float* o = h1 + ((size_t)h * N_ROWS + r) * N_HID + c;
            *reinterpret_cast<float2*>(o) = make_float2(acc[mm][nn][0], acc[mm][nn][1]);
            *reinterpret_cast<float2*>(o + 8 * N_HID) = make_float2(acc[mm][nn][2], acc[mm][nn][3]);
        }

    // fused scores epilogue
    const float* a = ah + (size_t)h * 2 * N_HID;
#pragma unroll
    for (int mm = 0; mm < 2; mm++) {
        float ps1 = 0.f, pd1 = 0.f, ps2 = 0.f, pd2 = 0.f;
#pragma unroll
        for (int nn = 0; nn < 4; nn++) {
            int c0 = wn * 32 + nn * 8 + lc * 2;
            float a0s = a[c0], a1s = a[c0 + 1];
            float a0d = a[N_HID + c0], a1d = a[N_HID + c0 + 1];
            ps1 += acc[mm][nn][0] * a0s + acc[mm][nn][1] * a1s;
            pd1 += acc[mm][nn][0] * a0d + acc[mm][nn][1] * a1d;
            ps2 += acc[mm][nn][2] * a0s + acc[mm][nn][3] * a1s;
            pd2 += acc[mm][nn][2] * a0d + acc[mm][nn][3] * a1d;
        }
#pragma unroll
        for (int off = 1; off <= 2; off <<= 1) {
            ps1 += __shfl_xor_sync(0xffffffffu, ps1, off);
            pd1 += __shfl_xor_sync(0xffffffffu, pd1, off);
            ps2 += __shfl_xor_sync(0xffffffffu, ps2, off);
            pd2 += __shfl_xor_sync(0xffffffffu, pd2, off);
        }
        if (lc == 0) {
            int rl = wm * 32 + mm * 16 + lr;
            sred[wn][0][rl] = ps1; sred[wn][1][rl] = pd1;
            sred[wn][0][rl + 8] = ps2; sred[wn][1][rl + 8] = pd2;
        }
    }
    __syncthreads();
    if (tid < BM) {
        int gi = h * N_ROWS + row0 + tid;
        ssrc[gi] = sred[0][0][tid] + sred[1][0][tid];
        sdst[gi] = sred[0][1][tid] + sred[1][1][tid];
    }
}

// ---------------- fused hybrid bitonic sort (descending) + scalar scans ----------------
__global__ __launch_bounds__(1024) void sortscan_kernel(
    const float* __restrict__ sdst, float* __restrict__ sorted, int* __restrict__ idx,
    float* __restrict__ ew, float* __restrict__ gw,
    float* __restrict__ Zhi, float* __restrict__ Zlo)
{
    int h = blockIdx.x;
    __shared__ unsigned long long buf[N_ROWS];
    __shared__ float sh[40];
    int tid = threadIdx.x;

    float key[4]; int id[4];
    float4 v4 = *reinterpret_cast<const float4*>(sdst + (size_t)h * N_ROWS + tid * 4);
    key[0] = v4.x; key[1] = v4.y; key[2] = v4.z; key[3] = v4.w;
    id[0] = tid * 4; id[1] = tid * 4 + 1; id[2] = tid * 4 + 2; id[3] = tid * 4 + 3;

    for (int k = 2; k <= N_ROWS; k <<= 1) {
        for (int j = k >> 1; j > 0; j >>= 1) {
            if (j == 1) {
#pragma unroll
                for (int q = 0; q < 4; q += 2) {
                    int e = tid * 4 + q;
                    bool desc = ((e & k) == 0);
                    bool sw = desc ? (key[q] < key[q + 1]) : (key[q] > key[q + 1]);
                    if (sw) {
                        float tk = key[q]; key[q] = key[q + 1]; key[q + 1] = tk;
                        int ti = id[q]; id[q] = id[q + 1]; id[q + 1] = ti;
                    }
                }
            } else if (j == 2) {
#pragma unroll
                for (int q = 0; q < 2; q++) {
                    int e = tid * 4 + q;
                    bool desc = ((e & k) == 0);
                    bool sw = desc ? (key[q] < key[q + 2]) : (key[q] > key[q + 2]);
                    if (sw) {
                        float tk = key[q]; key[q] = key[q + 2]; key[q + 2] = tk;
                        int ti = id[q]; id[q] = id[q + 2]; id[q + 2] = ti;
                    }
                }
            } else if (j <= 64) {
                int m = j >> 2;
#pragma unroll
                for (int q = 0; q < 4; q++) {
                    float ok = __shfl_xor_sync(0xffffffffu, key[q], m);
                    int   oi = __shfl_xor_sync(0xffffffffu, id[q], m);
                    int e = tid * 4 + q;
                    bool lower = ((e & j) == 0);
                    bool desc = ((e & k) == 0);
                    float a = lower ? key[q] : ok;
                    float b = lower ? ok : key[q];
                    bool sw = desc ? (a < b) : (a > b);
                    if (sw) { key[q] = ok; id[q] = oi; }
                }
            } else {
                __syncthreads();
#pragma unroll
                for (int q = 0; q < 4; q++) {
                    int e = tid * 4 + q;
                    buf[e] = ((unsigned long long)__float_as_uint(key[q]) << 32)
                             | (unsigned int)id[q];
                }
                __syncthreads();
#pragma unroll
                for (int q = 0; q < 4; q++) {
                    int e = tid * 4 + q;
                    unsigned long long o = buf[e ^ j];
                    float ok = __uint_as_float((unsigned int)(o >> 32));
                    int oi = (int)(unsigned int)(o & 0xffffffffu);
                    bool lower = ((e & j) == 0);
                    bool desc = ((e & k) == 0);
                    float a = lower ? key[q] : ok;
                    float b = lower ? ok : key[q];
                    bool sw = desc ? (a < b) : (a > b);
                    if (sw) { key[q] = ok; id[q] = oi; }
                }
            }
        }
    }
    __syncthreads();

    *reinterpret_cast<float4*>(sorted + (size_t)h * N_ROWS + tid * 4) =
        make_float4(key[0], key[1], key[2], key[3]);
    *reinterpret_cast<int4*>(idx + (size_t)h * N_ROWS + tid * 4) =
        make_int4(id[0], id[1], id[2], id[3]);

    if (tid == 0) sh[36] = key[0];
    __syncthreads();
    float M = sh[36];

    float e4[4], g4[4];
    float se = 0.f, sg = 0.f;
#pragma unroll
    for (int q = 0; q < 4; q++) {
        float xv = key[q] - M;
        e4[q] = expf(xv);
        g4[q] = expf(0.2f * xv);
        se += e4[q]; sg += g4[q];
    }
    *reinterpret_cast<float4*>(ew + (size_t)h * N_ROWS + tid * 4) =
        make_float4(e4[0], e4[1], e4[2], e4[3]);
    *reinterpret_cast<float4*>(gw + (size_t)h * N_ROWS + tid * 4) =
        make_float4(g4[0], g4[1], g4[2], g4[3]);

    float tote, totg;
    float pe = blk_exscan<32>(se, sh, tote);
    float pg = blk_exscan<32>(sg, sh, totg);

    float* ZH = Zhi + (size_t)h * PS;
    float* ZL = Zlo + (size_t)h * PS;
    float run = pe;
#pragma unroll
    for (int q = 0; q < 4; q++) { ZH[tid * 4 + q] = run; run += e4[q]; }
    float run2 = pg;
#pragma unroll
    for (int q = 0; q < 4; q++) { ZL[tid * 4 + q] = totg - run2; run2 += g4[q]; }
    if (tid == 1023) { ZH[N_ROWS] = run; ZL[N_ROWS] = 0.f; }
}

// ---------------- layer1 featA: chunk sums, 1024 threads, 16-row segments ----------------
__global__ __launch_bounds__(1024) void featA1_kernel(
    const float* __restrict__ hsrc, const int* __restrict__ idx,
    const float* __restrict__ ew, const float* __restrict__ gw,
    float* __restrict__ Chi, float* __restrict__ Clo)
{
    __shared__ int   sidx[256];
    __shared__ float sew[256], sgw[256];
    __shared__ float sH[16][N_HID], sL[16][N_HID];
    int h = blockIdx.y, chunk = blockIdx.x;
    int t = threadIdx.x;
    int ft = t & 63, rg = t >> 6;
    if (t < 256) {
        int base = h * N_ROWS + chunk * 256 + t;
        sidx[t] = idx[base]; sew[t] = ew[base]; sgw[t] = gw[base];
    }
    __syncthreads();
    const float* hb = hsrc + (size_t)h * N_ROWS * N_HID + ft;
    float sh_ = 0.f, sl_ = 0.f;
#pragma unroll
    for (int j = 0; j < 16; j++) {
        int rl = rg * 16 + j;
        float v = hb[(size_t)sidx[rl] * N_HID];
        sh_ += v * sew[rl];
        sl_ += v * sgw[rl];
    }
    sH[rg][ft] = sh_; sL[rg][ft] = sl_;
    __syncthreads();
    if (rg == 0) {
        float a = 0.f, b = 0.f;
#pragma unroll
        for (int r = 0; r < 16; r++) { a += sH[r][ft]; b += sL[r][ft]; }
        Chi[(h * N_HID + ft) * 16 + chunk] = a;
        Clo[(h * N_HID + ft) * 16 + chunk] = b;
    }
}

// ---------------- layer1 featC: final scan, 1024 threads ----------------
__global__ __launch_bounds__(1024) void featC1_kernel(
    const float* __restrict__ hsrc, const int* __restrict__ idx,
    const float* __restrict__ ew, const float* __restrict__ gw,
    const float* __restrict__ Chi, const float* __restrict__ Clo,
    float* __restrict__ Phi, float* __restrict__ Plo)
{
    __shared__ int   sidx[256];
    __shared__ float sew[256], sgw[256];
    __shared__ float sChi[N_HID * 16], sClo[N_HID * 16];   // [ft][chunk]
    __shared__ float sH[16][N_HID], sL[16][N_HID];
    int h = blockIdx.y, chunk = blockIdx.x;
    int t = threadIdx.x;
    int ft = t & 63, rg = t >> 6;
    if (t < 256) {
        int base = h * N_ROWS + chunk * 256 + t;
        sidx[t] = idx[base]; sew[t] = ew[base]; sgw[t] = gw[base];
    }
    sChi[t] = Chi[h * N_HID * 16 + t];
    sClo[t] = Clo[h * N_HID * 16 + t];
    __syncthreads();
    const float* hb = hsrc + (size_t)h * N_ROWS * N_HID + ft;
    float vh[16], vl[16];
    float sh_ = 0.f, sl_ = 0.f;
#pragma unroll
    for (int j = 0; j < 16; j++) {
        int rl = rg * 16 + j;
        float v = hb[(size_t)sidx[rl] * N_HID];
        vh[j] = v * sew[rl];
        vl[j] = v * sgw[rl];
        sh_ += vh[j]; sl_ += vl[j];
    }
    sH[rg][ft] = sh_; sL[rg][ft] = sl_;
    __syncthreads();
    float offh = 0.f, offl = 0.f, totl = 0.f;
#pragma unroll
    for (int c = 0; c < 16; c++) {
        float a = sChi[ft * 16 + c], b = sClo[ft * 16 + c];
        if (c < chunk) { offh += a; offl += b; }
        totl += b;
    }
    for (int r = 0; r < rg; r++) { offh += sH[r][ft]; offl += sL[r][ft]; }
    float* PH = Phi + (size_t)h * KR * N_HID + ft;
    float* PL = Plo + (size_t)h * KR * N_HID + ft;
    float runh = offh, runl = offl;
    int k0 = chunk * 256 + rg * 16;
#pragma unroll
    for (int j = 0; j < 16; j++) {
        PH[(size_t)(k0 + j) * N_HID] = runh;
        PL[(size_t)(k0 + j) * N_HID] = totl - runl;
        runh += vh[j];
        runl += vl[j];
    }
    if (chunk == 15 && rg == 15) {
        PH[(size_t)N_ROWS * N_HID] = runh;
        PL[(size_t)N_ROWS * N_HID] = totl - runl;
    }
}

// ---------------- layer2 featA (old style, F=16) ----------------
template<int F>
__global__ __launch_bounds__(256) void featA_kernel(
    const float* __restrict__ hsrc, const int* __restrict__ idx,
    const float* __restrict__ ew, const float* __restrict__ gw,
    float* __restrict__ Shi, float* __restrict__ Slo)
{
    const int SEGS = 256 / F;
    const int SEGTOT = N_ROWS / F;
    __shared__ int   sidx[256];
    __shared__ float sew[256], sgw[256];
    int h = blockIdx.y, chunk = blockIdx.x;
    int t = threadIdx.x;
    int base = h * N_ROWS + chunk * 256 + t;
    sidx[t] = idx[base];
    sew[t] = ew[base];
    sgw[t] = gw[base];
    __syncthreads();
    int ft = t % F, rg = t / F;
    const float* hb = hsrc + (size_t)h * N_ROWS * F + ft;
    float shi = 0.f, slo = 0.f;
#pragma unroll 4
    for (int j = 0; j < F; j++) {
        int rl = rg * F + j;
        float v = hb[(size_t)sidx[rl] * F];
        shi += v * sew[rl];
        slo += v * sgw[rl];
    }
    int seg = chunk * SEGS + rg;
    Shi[(size_t)(h * F + ft) * SEGTOT + seg] = shi;
    Slo[(size_t)(h * F + ft) * SEGTOT + seg] = slo;
}

template<int F>
__global__ __launch_bounds__(256) void featC_kernel(
    const float* __restrict__ hsrc, const int* __restrict__ idx,
    const float* __restrict__ ew, const float* __restrict__ gw,
    const float* __restrict__ Shi, const float* __restrict__ Slo,
    float* __restrict__ Phi, float* __restrict__ Plo)
{
    const int SEGS = 256 / F;
    const int SEGTOT = N_ROWS / F;
    __shared__ int   sidx[256];
    __shared__ float sew[256], sgw[256];
    __shared__ float sSh[4096], sSl[4096];
    int h = blockIdx.y, chunk = blockIdx.x;
    int t = threadIdx.x;
    int base = h * N_ROWS + chunk * 256 + t;
    sidx[t] = idx[base];
    sew[t] = ew[base];
    sgw[t] = gw[base];
    const float* ShB = Shi + (size_t)h * F * SEGTOT;
    const float* SlB = Slo + (size_t)h * F * SEGTOT;
#pragma unroll
    for (int i = 0; i < 4096 / 256; i++) {
        sSh[t + i * 256] = ShB[t + i * 256];
        sSl[t + i * 256] = SlB[t + i * 256];
    }
    __syncthreads();
    int ft = t % F, rg = t / F;
    int myseg = chunk * SEGS + rg;
    float offh = 0.f, offl = 0.f, totl = 0.f;
    const float* rh = sSh + ft * SEGTOT;
    const float* rl = sSl + ft * SEGTOT;
    for (int s = 0; s < SEGTOT; s++) {
        float a = rh[s], b = rl[s];
        if (s < myseg) { offh += a; offl += b; }
        totl += b;
    }
    const float* hb = hsrc + (size_t)h * N_ROWS * F + ft;
    float* PH = Phi + ((size_t)h * KR) * F + ft;
    float* PL = Plo + ((size_t)h * KR) * F + ft;
    float runh = offh, runl = offl;
    int r0 = chunk * 256 + rg * F;
#pragma unroll 4
    for (int j = 0; j < F; j++) {
        int rl_ = rg * F + j;
        int r = r0 + j;
        float v = hb[(size_t)sidx[rl_] * F];
        PH[(size_t)r * F] = runh;
        PL[(size_t)r * F] = totl - runl;
        runh += v * sew[rl_];
        runl += v * sgw[rl_];
    }
    if (myseg == SEGTOT - 1) {
        PH[(size_t)N_ROWS * F] = runh;
        PL[(size_t)N_ROWS * F] = totl - runl;
    }
}

// ---------------- combine layer1 (Phi[h][k][f] layout) ----------------
__global__ __launch_bounds__(256) void combine1_kernel(
    const float* __restrict__ ssrc, const float* __restrict__ sorted,
    const float* __restrict__ Zhi, const float* __restrict__ Zlo,
    const float* __restrict__ Phi, const float* __restrict__ Plo,
    float* __restrict__ xc)
{
    int h = blockIdx.y;
    __shared__ float ss[N_ROWS];
    const float* sb = sorted + (size_t)h * N_ROWS;
#pragma unroll
    for (int r = 0; r < 4; r++) {
        int off = (threadIdx.x + r * 256) * 4;
        *reinterpret_cast<float4*>(ss + off) = *reinterpret_cast<const float4*>(sb + off);
    }
    __syncthreads();
    int warp = threadIdx.x >> 5, lane = threadIdx.x & 31;
    float M = ss[0];
    const float* ZH = Zhi + (size_t)h * PS;
    const float* ZL = Zlo + (size_t)h * PS;
    const float* PHb = Phi + (size_t)h * KR * N_HID;
    const float* PLb = Plo + (size_t)h * KR * N_HID;
#pragma unroll
    for (int rr = 0; rr < 4; rr++) {
        int i = blockIdx.x * 32 + warp * 4 + rr;
        float s = ssrc[(size_t)h * N_ROWS + i];
        float thr = -s;
        int lo = 0, hi = N_ROWS;
        while (lo < hi) {
            int mid = (lo + hi) >> 1;
            if (ss[mid] >= thr) lo = mid + 1; else hi = mid;
        }
        int k = lo;
        float rho = expf(-0.8f * (s + M));
        float den = (k == 0) ? ZL[0] : (ZH[k] + rho * ZL[k]);
        float inv = 1.f / den;
        const float* ph = PHb + (size_t)k * N_HID;
        const float* pl = PLb + (size_t)k * N_HID;
#pragma unroll
        for (int u = 0; u < 2; u++) {
            int f = lane + 32 * u;
            float num = (k == 0) ? pl[f] : (ph[f] + rho * pl[f]);
            float feat = num * inv;
            float v = feat > 0.f ? feat : expm1f(feat);
            xc[(size_t)i * N_FEAT + h * N_HID + f] = v;
        }
    }
}

// ---------------- GEMM2: h2 = xc @ Wo + fused scores2 epilogue ----------------
__global__ __launch_bounds__(256) void gemm2_kernel(
    const float* __restrict__ xc, const float* __restrict__ Wo,
    const float* __restrict__ ao,
    float* __restrict__ h2, float* __restrict__ ssrc, float* __restrict__ sdst)
{
    __shared__ float xs[16][64];
    __shared__ float ws[64][16];
    int ir = threadIdx.x >> 4, fc = threadIdx.x & 15;
    int row0 = blockIdx.x * 16;
    float acc = 0.f;
    for (int k0 = 0; k0 < N_FEAT; k0 += 64) {
#pragma unroll
        for (int rep = 0; rep < 4; rep++) {
            int t = threadIdx.x + rep * 256;
            int r = t >> 6, kk = t & 63;
            xs[r][kk] = xc[(size_t)(row0 + r) * N_FEAT + k0 + kk];
        }
#pragma unroll
        for (int rep = 0; rep < 4; rep++) {
            int t = threadIdx.x + rep * 256;
            int kk = t >> 4, f = t & 15;
            ws[kk][f] = Wo[(size_t)(k0 + kk) * N_CLASS + f];
        }
        __syncthreads();
#pragma unroll
        for (int kk = 0; kk < 64; kk++) acc += xs[ir][kk] * ws[kk][fc];
        __syncthreads();
    }
    h2[(size_t)(row0 + ir) * N_CLASS + fc] = acc;
    float ps = acc * ao[fc];
    float pd = acc * ao[N_CLASS + fc];
#pragma unroll
    for (int off = 1; off < 16; off <<= 1) {
        ps += __shfl_xor_sync(0xffffffffu, ps, off);
        pd += __shfl_xor_sync(0xffffffffu, pd, off);
    }
    if (fc == 0) {
        ssrc[row0 + ir] = ps;
        sdst[row0 + ir] = pd;
    }
}

// ---------------- combine2 + ELU + log_softmax (Phi2[k][16] layout) ----------------
__global__ __launch_bounds__(256) void combine2_kernel(
    const float* __restrict__ ssrc, const float* __restrict__ sorted,
    const float* __restrict__ Zhi, const float* __restrict__ Zlo,
    const float* __restrict__ Phi, const float* __restrict__ Plo,
    float* __restrict__ out)
{
    __shared__ float ss[N_ROWS];
#pragma unroll
    for (int r = 0; r < 4; r++) {
        int off = (threadIdx.x + r * 256) * 4;
        *reinterpret_cast<float4*>(ss + off) = *reinterpret_cast<const float4*>(sorted + off);
    }
    __syncthreads();
    int warp = threadIdx.x >> 5, lane = threadIdx.x & 31;
    int sub = lane >> 4, f = lane & 15;
    float M = ss[0];
#pragma unroll
    for (int rr = 0; rr < 4; rr++) {
        int i = blockIdx.x * 64 + warp * 8 + rr * 2 + sub;
        float s = ssrc[i];
        float thr = -s;
        int lo = 0, hi = N_ROWS;
        while (lo < hi) {
            int mid = (lo + hi) >> 1;
            if (ss[mid] >= thr) lo = mid + 1; else hi = mid;
        }
        int k = lo;
        float rho = expf(-0.8f * (s + M));
        float den = (k == 0) ? Zlo[0] : (Zhi[k] + rho * Zlo[k]);
        float num = (k == 0) ? Plo[f] : (Phi[(size_t)k * N_CLASS + f] + rho * Plo[(size_t)k * N_CLASS + f]);
        float feat = num / den;
        float v = feat > 0.f ? feat : expm1f(feat);
        float m = v;
#pragma unroll
        for (int off = 8; off; off >>= 1) m = fmaxf(m, __shfl_xor_sync(0xffffffffu, m, off));
        float ex = expf(v - m);
        float ssum = ex;
#pragma unroll
        for (int off = 8; off; off >>= 1) ssum += __shfl_xor_sync(0xffffffffu, ssum, off);
        out[(size_t)i * N_CLASS + f] = v - m - logf(ssum);
    }
}

// ---------------- launch ----------------
extern "C" void kernel_launch(void* const* d_in, const int* in_sizes, int n_in,
                              void* d_out, int out_size)
{
    const float* x  = (const float*)d_in[0];
    const float* Wh = (const float*)d_in[1];
    const float* ah = (const float*)d_in[2];
    const float* Wo = (const float*)d_in[3];
    const float* ao = (const float*)d_in[4];
    float* out = (float*)d_out;

    __nv_bfloat16 *p_xh, *p_xl, *p_whh, *p_whl;
    float *p_h1, *p_ssrc1, *p_sdst1, *p_sorted1, *p_ew1, *p_gw1, *p_Zhi1, *p_Zlo1;
    float *p_Chi1, *p_Clo1, *p_Phi1, *p_Plo1, *p_xc;
    int *p_idx1;
    float *p_h2, *p_ssrc2, *p_sdst2, *p_sorted2, *p_ew2, *p_gw2, *p_Zhi2, *p_Zlo2;
    float *p_Shi2, *p_Slo2, *p_Phi2, *p_Plo2;
    int *p_idx2;

    cudaGetSymbolAddress((void**)&p_xh, g_xh);
    cudaGetSymbolAddress((void**)&p_xl, g_xl);
    cudaGetSymbolAddress((void**)&p_whh, g_whh);
    cudaGetSymbolAddress((void**)&p_whl, g_whl);
    cudaGetSymbolAddress((void**)&p_h1, g_h1);
    cudaGetSymbolAddress((void**)&p_ssrc1, g_ssrc1);
    cudaGetSymbolAddress((void**)&p_sdst1, g_sdst1);
    cudaGetSymbolAddress((void**)&p_sorted1, g_sorted1);
    cudaGetSymbolAddress((void**)&p_idx1, g_idx1);
    cudaGetSymbolAddress((void**)&p_ew1, g_ew1);
    cudaGetSymbolAddress((void**)&p_gw1, g_gw1);
    cudaGetSymbolAddress((void**)&p_Zhi1, g_Zhi1);
    cudaGetSymbolAddress((void**)&p_Zlo1, g_Zlo1);
    cudaGetSymbolAddress((void**)&p_Chi1, g_Chi1);
    cudaGetSymbolAddress((void**)&p_Clo1, g_Clo1);
    cudaGetSymbolAddress((void**)&p_Phi1, g_Phi1);
    cudaGetSymbolAddress((void**)&p_Plo1, g_Plo1);
    cudaGetSymbolAddress((void**)&p_xc, g_xc);
    cudaGetSymbolAddress((void**)&p_h2, g_h2);
    cudaGetSymbolAddress((void**)&p_ssrc2, g_ssrc2);
    cudaGetSymbolAddress((void**)&p_sdst2, g_sdst2);
    cudaGetSymbolAddress((void**)&p_sorted2, g_sorted2);
    cudaGetSymbolAddress((void**)&p_idx2, g_idx2);
    cudaGetSymbolAddress((void**)&p_ew2, g_ew2);
    cudaGetSymbolAddress((void**)&p_gw2, g_gw2);
    cudaGetSymbolAddress((void**)&p_Zhi2, g_Zhi2);
    cudaGetSymbolAddress((void**)&p_Zlo2, g_Zlo2);
    cudaGetSymbolAddress((void**)&p_Shi2, g_Shi2);
    cudaGetSymbolAddress((void**)&p_Slo2, g_Slo2);
    cudaGetSymbolAddress((void**)&p_Phi2, g_Phi2);
    cudaGetSymbolAddress((void**)&p_Plo2, g_Plo2);

    // ---- combined splits ----
    splitall_kernel<<<(NX4 + NW4 + 255) / 256, 256>>>(x, Wh, p_xh, p_xl, p_whh, p_whl);

    // ---- layer 1 ----
    gemm1_mma_kernel<<<dim3(N_ROWS / 128, N_HEADS), 256>>>(p_xh, p_xl, p_whh, p_whl, ah,
                                                           p_h1, p_ssrc1, p_sdst1);
    sortscan_kernel<<<N_HEADS, 1024>>>(p_sdst1, p_sorted1, p_idx1, p_ew1, p_gw1, p_Zhi1, p_Zlo1);
    featA1_kernel<<<dim3(16, N_HEADS), 1024>>>(p_h1, p_idx1, p_ew1, p_gw1, p_Chi1, p_Clo1);
    featC1_kernel<<<dim3(16, N_HEADS), 1024>>>(p_h1, p_idx1, p_ew1, p_gw1,
                                               p_Chi1, p_Clo1, p_Phi1, p_Plo1);
    combine1_kernel<<<dim3(N_ROWS / 32, N_HEADS), 256>>>(p_ssrc1, p_sorted1, p_Zhi1, p_Zlo1,
                                                         p_Phi1, p_Plo1, p_xc);
    // ---- layer 2 ----
    gemm2_kernel<<<N_ROWS / 16, 256>>>(p_xc, Wo, ao, p_h2, p_ssrc2, p_sdst2);
    sortscan_kernel<<<1, 1024>>>(p_sdst2, p_sorted2, p_idx2, p_ew2, p_gw2, p_Zhi2, p_Zlo2);
    featA_kernel<N_CLASS><<<dim3(16, 1), 256>>>(p_h2, p_idx2, p_ew2, p_gw2, p_Shi2, p_Slo2);
    featC_kernel<N_CLASS><<<dim3(16, 1), 256>>>(p_h2, p_idx2, p_ew2, p_gw2,
                                                p_Shi2, p_Slo2, p_Phi2, p_Plo2);
    combine2_kernel<<<N_ROWS / 64, 256>>>(p_ssrc2, p_sorted2, p_Zhi2, p_Zlo2,
                                          p_Phi2, p_Plo2, out);

    (void)in_sizes; (void)n_in; (void)out_size;
}

// round 8
// speedup vs baseline: 1.5149x; 1.0110x over previous
#include <cuda_runtime.h>
#include <cuda_bf16.h>
#include <cstdint>

#define N_ROWS   4096
#define N_FEAT   512
#define N_HID    64
#define N_CLASS  16
#define N_HEADS  8
#define PS       (N_ROWS + 4)
#define KR       (N_ROWS + 1)
#define NB       128            // mega-kernel grid size (all-resident)

// ---------------- scratch ----------------
__device__ __nv_bfloat16 g_xh [N_ROWS*N_FEAT];
__device__ __nv_bfloat16 g_xl [N_ROWS*N_FEAT];
__device__ __nv_bfloat16 g_whh[N_HEADS*N_FEAT*N_HID];
__device__ __nv_bfloat16 g_whl[N_HEADS*N_FEAT*N_HID];

__device__ float g_h1   [N_HEADS*N_ROWS*N_HID];
__device__ float g_ssrc1[N_HEADS*N_ROWS];
__device__ float g_sdst1[N_HEADS*N_ROWS];
__device__ float g_sorted1[N_HEADS*N_ROWS];
__device__ int   g_idx1 [N_HEADS*N_ROWS];
__device__ float g_ew1  [N_HEADS*N_ROWS];
__device__ float g_gw1  [N_HEADS*N_ROWS];
__device__ float g_Zhi1 [N_HEADS*PS];
__device__ float g_Zlo1 [N_HEADS*PS];
__device__ float g_Chi1 [N_HEADS*N_HID*16];
__device__ float g_Clo1 [N_HEADS*N_HID*16];
__device__ float g_Phi1 [N_HEADS*KR*N_HID];
__device__ float g_Plo1 [N_HEADS*KR*N_HID];
__device__ float g_xc   [N_ROWS*N_FEAT];

__device__ float g_h2   [N_ROWS*N_CLASS];
__device__ float g_ssrc2[N_ROWS];
__device__ float g_sdst2[N_ROWS];
__device__ float g_sorted2[N_ROWS];
__device__ int   g_idx2 [N_ROWS];
__device__ float g_ew2  [N_ROWS];
__device__ float g_gw2  [N_ROWS];
__device__ float g_Zhi2 [PS];
__device__ float g_Zlo2 [PS];
__device__ float g_Chi2 [N_CLASS*16];
__device__ float g_Clo2 [N_CLASS*16];
__device__ float g_Phi2 [KR*N_CLASS];
__device__ float g_Plo2 [KR*N_CLASS];

// ---------------- device-wide software barrier ----------------
__device__ unsigned g_cnt;
__device__ volatile unsigned g_gen;

__device__ __forceinline__ void gbar() {
    __threadfence();
    __syncthreads();
    if (threadIdx.x == 0) {
        unsigned old = g_gen;
        if (atomicAdd(&g_cnt, 1u) == NB - 1) {
            g_cnt = 0;
            __threadfence();
            g_gen = old + 1;
        } else {
            while (g_gen == old) { __nanosleep(64); }
        }
    }
    __syncthreads();
    __threadfence();
}

// ---------------- warp-shuffle block exclusive scan (1024 thr) ----------------
__device__ __forceinline__ float blk_exscan32(float v, float* sh, float& total) {
    __syncthreads();
    int lane = threadIdx.x & 31, warp = threadIdx.x >> 5;
    float x = v;
#pragma unroll
    for (int off = 1; off < 32; off <<= 1) {
        float n = __shfl_up_sync(0xffffffffu, x, off);
        if (lane >= off) x += n;
    }
    if (lane == 31) sh[warp] = x;
    __syncthreads();
    if (warp == 0) {
        float w = sh[lane];
#pragma unroll
        for (int off = 1; off < 32; off <<= 1) {
            float n = __shfl_up_sync(0xffffffffu, w, off);
            if (lane >= off) w += n;
        }
        sh[lane] = w;
    }
    __syncthreads();
    float base = warp ? sh[warp - 1] : 0.f;
    total = sh[31];
    return base + x - v;
}

// ---------------- sortscan body (1024 threads of one block) ----------------
__device__ void sortscan_body(int h, const float* __restrict__ sdst,
                              float* __restrict__ sorted, int* __restrict__ idx,
                              float* __restrict__ ew, float* __restrict__ gw,
                              float* __restrict__ Zhi, float* __restrict__ Zlo,
                              unsigned long long* buf, float* sh)
{
    int tid = threadIdx.x;
    float key[4]; int id[4];
    float4 v4 = *reinterpret_cast<const float4*>(sdst + (size_t)h * N_ROWS + tid * 4);
    key[0] = v4.x; key[1] = v4.y; key[2] = v4.z; key[3] = v4.w;
    id[0] = tid * 4; id[1] = tid * 4 + 1; id[2] = tid * 4 + 2; id[3] = tid * 4 + 3;

    for (int k = 2; k <= N_ROWS; k <<= 1) {
        for (int j = k >> 1; j > 0; j >>= 1) {
            if (j == 1) {
#pragma unroll
                for (int q = 0; q < 4; q += 2) {
                    int e = tid * 4 + q;
                    bool desc = ((e & k) == 0);
                    bool sw = desc ? (key[q] < key[q + 1]) : (key[q] > key[q + 1]);
                    if (sw) {
                        float tk = key[q]; key[q] = key[q + 1]; key[q + 1] = tk;
                        int ti = id[q]; id[q] = id[q + 1]; id[q + 1] = ti;
                    }
                }
            } else if (j == 2) {
#pragma unroll
                for (int q = 0; q < 2; q++) {
                    int e = tid * 4 + q;
                    bool desc = ((e & k) == 0);
                    bool sw = desc ? (key[q] < key[q + 2]) : (key[q] > key[q + 2]);
                    if (sw) {
                        float tk = key[q]; key[q] = key[q + 2]; key[q + 2] = tk;
                        int ti = id[q]; id[q] = id[q + 2]; id[q + 2] = ti;
                    }
                }
            } else if (j <= 64) {
                int m = j >> 2;
#pragma unroll
                for (int q = 0; q < 4; q++) {
                    float ok = __shfl_xor_sync(0xffffffffu, key[q], m);
                    int   oi = __shfl_xor_sync(0xffffffffu, id[q], m);
                    int e = tid * 4 + q;
                    bool lower = ((e & j) == 0);
                    bool desc = ((e & k) == 0);
                    float a = lower ? key[q] : ok;
                    float b = lower ? ok : key[q];
                    bool sw = desc ? (a < b) : (a > b);
                    if (sw) { key[q] = ok; id[q] = oi; }
                }
            } else {
                __syncthreads();
#pragma unroll
                for (int q = 0; q < 4; q++) {
                    int e = tid * 4 + q;
                    buf[e] = ((unsigned long long)__float_as_uint(key[q]) << 32)
                             | (unsigned int)id[q];
                }
                __syncthreads();
#pragma unroll
                for (int q = 0; q < 4; q++) {
                    int e = tid * 4 + q;
                    unsigned long long o = buf[e ^ j];
                    float ok = __uint_as_float((unsigned int)(o >> 32));
                    int oi = (int)(unsigned int)(o & 0xffffffffu);
                    bool lower = ((e & j) == 0);
                    bool desc = ((e & k) == 0);
                    float a = lower ? key[q] : ok;
                    float b = lower ? ok : key[q];
                    bool sw = desc ? (a < b) : (a > b);
                    if (sw) { key[q] = ok; id[q] = oi; }
                }
            }
        }
    }
    __syncthreads();

    *reinterpret_cast<float4*>(sorted + (size_t)h * N_ROWS + tid * 4) =
        make_float4(key[0], key[1], key[2], key[3]);
    *reinterpret_cast<int4*>(idx + (size_t)h * N_ROWS + tid * 4) =
        make_int4(id[0], id[1], id[2], id[3]);

    if (tid == 0) sh[36] = key[0];
    __syncthreads();
    float M = sh[36];

    float e4[4], g4[4];
    float se = 0.f, sg = 0.f;
#pragma unroll
    for (int q = 0; q < 4; q++) {
        float xv = key[q] - M;
        e4[q] = expf(xv);
        g4[q] = expf(0.2f * xv);
        se += e4[q]; sg += g4[q];
    }
    *reinterpret_cast<float4*>(ew + (size_t)h * N_ROWS + tid * 4) =
        make_float4(e4[0], e4[1], e4[2], e4[3]);
    *reinterpret_cast<float4*>(gw + (size_t)h * N_ROWS + tid * 4) =
        make_float4(g4[0], g4[1], g4[2], g4[3]);

    float tote, totg;
    float pe = blk_exscan32(se, sh, tote);
    float pg = blk_exscan32(sg, sh, totg);

    float* ZH = Zhi + (size_t)h * PS;
    float* ZL = Zlo + (size_t)h * PS;
    float run = pe;
#pragma unroll
    for (int q = 0; q < 4; q++) { ZH[tid * 4 + q] = run; run += e4[q]; }
    float run2 = pg;
#pragma unroll
    for (int q = 0; q < 4; q++) { ZL[tid * 4 + q] = totg - run2; run2 += g4[q]; }
    if (tid == 1023) { ZH[N_ROWS] = run; ZL[N_ROWS] = 0.f; }
}

// ---------------- combined split fp32 -> bf16 hi/lo ----------------
#define NX4  (N_ROWS * N_FEAT / 4)
#define NW4  (N_HEADS * N_FEAT * N_HID / 4)
__global__ void splitall_kernel(const float* __restrict__ x, const float* __restrict__ Wh,
                                __nv_bfloat16* __restrict__ xh, __nv_bfloat16* __restrict__ xl,
                                __nv_bfloat16* __restrict__ whh, __nv_bfloat16* __restrict__ whl)
{
    int i = blockIdx.x * blockDim.x + threadIdx.x;
    const float* src; __nv_bfloat16 *hi, *lo; int j;
    if (i < NX4) { src = x; hi = xh; lo = xl; j = i; }
    else         { src = Wh; hi = whh; lo = whl; j = i - NX4; if (j >= NW4) return; }
    float4 v = reinterpret_cast<const float4*>(src)[j];
    __nv_bfloat16 h0 = __float2bfloat16_rn(v.x);
    __nv_bfloat16 h1 = __float2bfloat16_rn(v.y);
    __nv_bfloat16 h2 = __float2bfloat16_rn(v.z);
    __nv_bfloat16 h3 = __float2bfloat16_rn(v.w);
    __nv_bfloat16 l0 = __float2bfloat16_rn(v.x - __bfloat162float(h0));
    __nv_bfloat16 l1 = __float2bfloat16_rn(v.y - __bfloat162float(h1));
    __nv_bfloat16 l2 = __float2bfloat16_rn(v.z - __bfloat162float(h2));
    __nv_bfloat16 l3 = __float2bfloat16_rn(v.w - __bfloat162float(h3));
    __nv_bfloat162* hp = reinterpret_cast<__nv_bfloat162*>(hi) + j * 2;
    __nv_bfloat162* lp = reinterpret_cast<__nv_bfloat162*>(lo) + j * 2;
    hp[0] = __nv_bfloat162(h0, h1); hp[1] = __nv_bfloat162(h2, h3);
    lp[0] = __nv_bfloat162(l0, l1); lp[1] = __nv_bfloat162(l2, l3);
}

// ---------------- GEMM1 (bf16 mma + ldmatrix + fused scores) ----------------
__device__ __forceinline__ void mma16816(float* c, const uint32_t* a, const uint32_t* b) {
    asm volatile(
        "mma.sync.aligned.m16n8k16.row.col.f32.bf16.bf16.f32 "
        "{%0,%1,%2,%3}, {%4,%5,%6,%7}, {%8,%9}, {%0,%1,%2,%3};\n"
        : "+f"(c[0]), "+f"(c[1]), "+f"(c[2]), "+f"(c[3])
        : "r"(a[0]), "r"(a[1]), "r"(a[2]), "r"(a[3]), "r"(b[0]), "r"(b[1]));
}
__device__ __forceinline__ void ldmat_x4(uint32_t* r, uint32_t addr) {
    asm volatile("ldmatrix.sync.aligned.m8n8.x4.shared.b16 {%0,%1,%2,%3}, [%4];"
        : "=r"(r[0]), "=r"(r[1]), "=r"(r[2]), "=r"(r[3]) : "r"(addr));
}
__device__ __forceinline__ void ldmat_x4_t(uint32_t* r, uint32_t addr) {
    asm volatile("ldmatrix.sync.aligned.m8n8.x4.trans.shared.b16 {%0,%1,%2,%3}, [%4];"
        : "=r"(r[0]), "=r"(r[1]), "=r"(r[2]), "=r"(r[3]) : "r"(addr));
}

__global__ __launch_bounds__(256) void gemm1_mma_kernel(
    const __nv_bfloat16* __restrict__ xh, const __nv_bfloat16* __restrict__ xl,
    const __nv_bfloat16* __restrict__ whh, const __nv_bfloat16* __restrict__ whl,
    const float* __restrict__ ah,
    float* __restrict__ h1, float* __restrict__ ssrc, float* __restrict__ sdst)
{
    const int BM = 128, BKT = 64, SA = 72, SB = 72;
    __shared__ __nv_bfloat16 As[BM * SA];
    __shared__ __nv_bfloat16 Bs[BKT * SB];
    __shared__ float sred[2][2][BM];
    int h = blockIdx.y;
    int row0 = blockIdx.x * BM;
    int tid = threadIdx.x;
    int wid = tid >> 5, lane = tid & 31;
    int wm = wid & 3, wn = wid >> 2;
    int lr = lane >> 2, lc = lane & 3;
    int idx15 = lane & 15, hi8 = (lane >> 4) << 3;

    uint32_t sa_base = (uint32_t)__cvta_generic_to_shared(As);
    uint32_t sb_base = (uint32_t)__cvta_generic_to_shared(Bs);

    const __nv_bfloat16* Wb0 = whh + (size_t)h * N_FEAT * N_HID;
    const __nv_bfloat16* Wb1 = whl + (size_t)h * N_FEAT * N_HID;
    const __nv_bfloat16* Aph[3] = { xh, xl, xh };
    const __nv_bfloat16* Bph[3] = { Wb0, Wb0, Wb1 };

    float acc[2][4][4];
#pragma unroll
    for (int mm = 0; mm < 2; mm++)
#pragma unroll
        for (int nn = 0; nn < 4; nn++)
#pragma unroll
            for (int q = 0; q < 4; q++) acc[mm][nn][q] = 0.f;

    for (int p = 0; p < 3; p++) {
        const __nv_bfloat16* Ag = Aph[p];
        const __nv_bfloat16* Bg = Bph[p];
        for (int k0 = 0; k0 < N_FEAT; k0 += BKT) {
            __syncthreads();
#pragma unroll
            for (int i = 0; i < 4; i++) {
                int id4 = tid + i * 256;
                int r = id4 >> 3, kk = (id4 & 7) * 8;
                uint4 v = *reinterpret_cast<const uint4*>(
                    Ag + (size_t)(row0 + r) * N_FEAT + k0 + kk);
                *reinterpret_cast<uint4*>(As + r * SA + kk) = v;
            }
#pragma unroll
            for (int i = 0; i < 2; i++) {
                int id4 = tid + i * 256;
                int kk = id4 >> 3, ff = (id4 & 7) * 8;
                uint4 v = *reinterpret_cast<const uint4*>(
                    Bg + (size_t)(k0 + kk) * N_HID + ff);
                *reinterpret_cast<uint4*>(Bs + kk * SB + ff) = v;
            }
            __syncthreads();
#pragma unroll
            for (int ks = 0; ks < 4; ks++) {
                int kb = ks * 16;
                uint32_t afr[2][4];
#pragma unroll
                for (int mm = 0; mm < 2; mm++) {
                    uint32_t addr = sa_base +
                        (uint32_t)((wm * 32 + mm * 16 + idx15) * SA + kb + hi8) * 2u;
                    ldmat_x4(afr[mm], addr);
                }
                uint32_t bfr[4][2];
#pragma unroll
                for (int bp = 0; bp < 2; bp++) {
                    uint32_t bt[4];
                    uint32_t addr = sb_base +
                        (uint32_t)((kb + idx15) * SB + wn * 32 + bp * 16 + hi8) * 2u;
                    ldmat_x4_t(bt, addr);
                    bfr[bp * 2][0] = bt[0]; bfr[bp * 2][1] = bt[1];
                    bfr[bp * 2 + 1][0] = bt[2]; bfr[bp * 2 + 1][1] = bt[3];
                }
#pragma unroll
                for (int mm = 0; mm < 2; mm++)
#pragma unroll
                    for (int nn = 0; nn < 4; nn++)
                        mma16816(acc[mm][nn], afr[mm], bfr[nn]);
            }
        }
    }
#pragma unroll
    for (int mm = 0; mm < 2; mm++)
#pragma unroll
        for (int nn = 0; nn < 4; nn++) {
            int r = row0 + wm * 32 + mm * 16 + lr;
            int c = wn * 32 + nn * 8 + lc * 2;
            float* o = h1 + ((size_t)h * N_ROWS + r) * N_HID + c;
            *reinterpret_cast<float2*>(o) = make_float2(acc[mm][nn][0], acc[mm][nn][1]);
            *reinterpret_cast<float2*>(o + 8 * N_HID) = make_float2(acc[mm][nn][2], acc[mm][nn][3]);
        }

    const float* a = ah + (size_t)h * 2 * N_HID;
#pragma unroll
    for (int mm = 0; mm < 2; mm++) {
        float ps1 = 0.f, pd1 = 0.f, ps2 = 0.f, pd2 = 0.f;
#pragma unroll
        for (int nn = 0; nn < 4; nn++) {
            int c0 = wn * 32 + nn * 8 + lc * 2;
            float a0s = a[c0], a1s = a[c0 + 1];
            float a0d = a[N_HID + c0], a1d = a[N_HID + c0 + 1];
            ps1 += acc[mm][nn][0] * a0s + acc[mm][nn][1] * a1s;
            pd1 += acc[mm][nn][0] * a0d + acc[mm][nn][1] * a1d;
            ps2 += acc[mm][nn][2] * a0s + acc[mm][nn][3] * a1s;
            pd2 += acc[mm][nn][2] * a0d + acc[mm][nn][3] * a1d;
        }
#pragma unroll
        for (int off = 1; off <= 2; off <<= 1) {
            ps1 += __shfl_xor_sync(0xffffffffu, ps1, off);
            pd1 += __shfl_xor_sync(0xffffffffu, pd1, off);
            ps2 += __shfl_xor_sync(0xffffffffu, ps2, off);
            pd2 += __shfl_xor_sync(0xffffffffu, pd2, off);
        }
        if (lc == 0) {
            int rl = wm * 32 + mm * 16 + lr;
            sred[wn][0][rl] = ps1; sred[wn][1][rl] = pd1;
            sred[wn][0][rl + 8] = ps2; sred[wn][1][rl + 8] = pd2;
        }
    }
    __syncthreads();
    if (tid < BM) {
        int gi = h * N_ROWS + row0 + tid;
        ssrc[gi] = sred[0][0][tid] + sred[1][0][tid];
        sdst[gi] = sred[0][1][tid] + sred[1][1][tid];
    }
}

// ---------------- megaL1: sortscan1 + featA1 + featC1 + combine1 ----------------
__global__ __launch_bounds__(1024, 1) void megaL1_kernel(
    const float* __restrict__ sdst, float* __restrict__ sorted, int* __restrict__ idx,
    float* __restrict__ ew, float* __restrict__ gw,
    float* __restrict__ Zhi, float* __restrict__ Zlo,
    const float* __restrict__ h1, float* __restrict__ Chi, float* __restrict__ Clo,
    float* __restrict__ Phi, float* __restrict__ Plo,
    const float* __restrict__ ssrc, float* __restrict__ xc)
{
    __shared__ __align__(16) unsigned char sm[33792];
    int blk = blockIdx.x, t = threadIdx.x;

    // ---- Phase S: per-head sortscan (blocks 0..7) ----
    if (blk < N_HEADS) {
        sortscan_body(blk, sdst, sorted, idx, ew, gw, Zhi, Zlo,
                      (unsigned long long*)sm, (float*)(sm + 32768));
    }
    gbar();

    int h = blk >> 4, chunk = blk & 15;

    // ---- Phase A: featA chunk sums ----
    {
        int* sidx = (int*)sm;
        float* sew = (float*)(sm + 1024);
        float* sgw = (float*)(sm + 2048);
        float (*sH)[N_HID] = (float(*)[N_HID])(sm + 3072);
        float (*sL)[N_HID] = (float(*)[N_HID])(sm + 7168);
        int ft = t & 63, rg = t >> 6;
        if (t < 256) {
            int base = h * N_ROWS + chunk * 256 + t;
            sidx[t] = idx[base]; sew[t] = ew[base]; sgw[t] = gw[base];
        }
        __syncthreads();
        const float* hb = h1 + (size_t)h * N_ROWS * N_HID + ft;
        float sh_ = 0.f, sl_ = 0.f;
#pragma unroll
        for (int j = 0; j < 16; j++) {
            int rl = rg * 16 + j;
            float v = hb[(size_t)sidx[rl] * N_HID];
            sh_ += v * sew[rl];
            sl_ += v * sgw[rl];
        }
        sH[rg][ft] = sh_; sL[rg][ft] = sl_;
        __syncthreads();
        if (rg == 0) {
            float a = 0.f, b = 0.f;
#pragma unroll
            for (int r = 0; r < 16; r++) { a += sH[r][ft]; b += sL[r][ft]; }
            Chi[(h * N_HID + ft) * 16 + chunk] = a;
            Clo[(h * N_HID + ft) * 16 + chunk] = b;
        }
    }
    gbar();

    // ---- Phase C: featC final scan ----
    {
        int* sidx = (int*)sm;
        float* sew = (float*)(sm + 1024);
        float* sgw = (float*)(sm + 2048);
        float* sChi = (float*)(sm + 3072);   // 1024 floats
        float* sClo = (float*)(sm + 7168);
        float (*sH)[N_HID] = (float(*)[N_HID])(sm + 11264);
        float (*sL)[N_HID] = (float(*)[N_HID])(sm + 15360);
        int ft = t & 63, rg = t >> 6;
        if (t < 256) {
            int base = h * N_ROWS + chunk * 256 + t;
            sidx[t] = idx[base]; sew[t] = ew[base]; sgw[t] = gw[base];
        }
        sChi[t] = Chi[h * N_HID * 16 + t];
        sClo[t] = Clo[h * N_HID * 16 + t];
        __syncthreads();
        const float* hb = h1 + (size_t)h * N_ROWS * N_HID + ft;
        float vh[16], vl[16];
        float sh_ = 0.f, sl_ = 0.f;
#pragma unroll
        for (int j = 0; j < 16; j++) {
            int rl = rg * 16 + j;
            float v = hb[(size_t)sidx[rl] * N_HID];
            vh[j] = v * sew[rl];
            vl[j] = v * sgw[rl];
            sh_ += vh[j]; sl_ += vl[j];
        }
        sH[rg][ft] = sh_; sL[rg][ft] = sl_;
        __syncthreads();
        float offh = 0.f, offl = 0.f, totl = 0.f;
#pragma unroll
        for (int c = 0; c < 16; c++) {
            float a = sChi[ft * 16 + c], b = sClo[ft * 16 + c];
            if (c < chunk) { offh += a; offl += b; }
            totl += b;
        }
        for (int r = 0; r < rg; r++) { offh += sH[r][ft]; offl += sL[r][ft]; }
        float* PH = Phi + (size_t)h * KR * N_HID + ft;
        float* PL = Plo + (size_t)h * KR * N_HID + ft;
        float runh = offh, runl = offl;
        int k0 = chunk * 256 + rg * 16;
#pragma unroll
        for (int j = 0; j < 16; j++) {
            PH[(size_t)(k0 + j) * N_HID] = runh;
            PL[(size_t)(k0 + j) * N_HID] = totl - runl;
            runh += vh[j];
            runl += vl[j];
        }
        if (chunk == 15 && rg == 15) {
            PH[(size_t)N_ROWS * N_HID] = runh;
            PL[(size_t)N_ROWS * N_HID] = totl - runl;
        }
    }
    gbar();

    // ---- Phase B: combine1 ----
    {
        float* ss = (float*)sm;
        const float* sb = sorted + (size_t)h * N_ROWS;
        *reinterpret_cast<float4*>(ss + t * 4) = *reinterpret_cast<const float4*>(sb + t * 4);
        __syncthreads();
        int warp = t >> 5, lane = t & 31;
        float M = ss[0];
        const float* ZH = Zhi + (size_t)h * PS;
        const float* ZL = Zlo + (size_t)h * PS;
        const float* PHb = Phi + (size_t)h * KR * N_HID;
        const float* PLb = Plo + (size_t)h * KR * N_HID;
        int i0 = chunk * 256;
#pragma unroll
        for (int rr = 0; rr < 8; rr++) {
            int i = i0 + warp * 8 + rr;
            float s = ssrc[(size_t)h * N_ROWS + i];
            float thr = -s;
            int lo = 0, hi = N_ROWS;
            while (lo < hi) {
                int mid = (lo + hi) >> 1;
                if (ss[mid] >= thr) lo = mid + 1; else hi = mid;
            }
            int k = lo;
            float rho = expf(-0.8f * (s + M));
            float den = (k == 0) ? ZL[0] : (ZH[k] + rho * ZL[k]);
            float inv = 1.f / den;
            const float* ph = PHb + (size_t)k * N_HID;
            const float* pl = PLb + (size_t)k * N_HID;
#pragma unroll
            for (int u = 0; u < 2; u++) {
                int f = lane + 32 * u;
                float num = (k == 0) ? pl[f] : (ph[f] + rho * pl[f]);
                float feat = num * inv;
                float v = feat > 0.f ? feat : expm1f(feat);
                xc[(size_t)i * N_FEAT + h * N_HID + f] = v;
            }
        }
    }
}

// ---------------- megaL2: gemm2+scores2 + sortscan2 + featA2/C2 + combine2 ----------------
__global__ __launch_bounds__(1024, 1) void megaL2_kernel(
    const float* __restrict__ xc, const float* __restrict__ Wo, const float* __restrict__ ao,
    float* __restrict__ h2, float* __restrict__ ssrc, float* __restrict__ sdst,
    float* __restrict__ sorted, int* __restrict__ idx,
    float* __restrict__ ew, float* __restrict__ gw,
    float* __restrict__ Zhi, float* __restrict__ Zlo,
    float* __restrict__ Chi, float* __restrict__ Clo,
    float* __restrict__ Phi, float* __restrict__ Plo,
    float* __restrict__ out)
{
    __shared__ __align__(16) unsigned char sm[33792];
    int blk = blockIdx.x, t = threadIdx.x;

    // ---- Phase G: gemm2 + fused scores2 (32 rows per block) ----
    {
        float (*xs)[64] = (float(*)[64])sm;          // 32x64
        float (*ws)[16] = (float(*)[16])(sm + 8192); // 64x16
        int row0 = blk * 32;
        int ir = t >> 4, fc = t & 15;   // valid for t < 512
        float acc = 0.f;
        for (int k0 = 0; k0 < N_FEAT; k0 += 64) {
            __syncthreads();
#pragma unroll
            for (int rep = 0; rep < 2; rep++) {
                int t2 = t + rep * 1024;
                int r = t2 >> 6, kk = t2 & 63;
                xs[r][kk] = xc[(size_t)(row0 + r) * N_FEAT + k0 + kk];
            }
            {
                int kk = t >> 4, f = t & 15;
                if (kk < 64) ws[kk][f] = Wo[(size_t)(k0 + kk) * N_CLASS + f];
            }
            __syncthreads();
            if (t < 512) {
#pragma unroll
                for (int kk = 0; kk < 64; kk++) acc += xs[ir][kk] * ws[kk][fc];
            }
        }
        if (t < 512) {
            h2[(size_t)(row0 + ir) * N_CLASS + fc] = acc;
            float ps = acc * ao[fc];
            float pd = acc * ao[N_CLASS + fc];
#pragma unroll
            for (int off = 1; off < 16; off <<= 1) {
                ps += __shfl_xor_sync(0xffffffffu, ps, off);
                pd += __shfl_xor_sync(0xffffffffu, pd, off);
            }
            if (fc == 0) {
                ssrc[row0 + ir] = ps;
                sdst[row0 + ir] = pd;
            }
        }
    }
    gbar();

    // ---- Phase S2: sortscan (block 0 only) ----
    if (blk == 0) {
        sortscan_body(0, sdst, sorted, idx, ew, gw, Zhi, Zlo,
                      (unsigned long long*)sm, (float*)(sm + 32768));
    }
    gbar();

    // ---- Phase A2: chunk sums (blocks 0..15) ----
    if (blk < 16) {
        int chunk = blk;
        int* sidx = (int*)sm;
        float* sew = (float*)(sm + 1024);
        float* sgw = (float*)(sm + 2048);
        float (*sH)[N_CLASS] = (float(*)[N_CLASS])(sm + 3072);  // 64x16
        float (*sL)[N_CLASS] = (float(*)[N_CLASS])(sm + 7168);
        if (t < 256) {
            int base = chunk * 256 + t;
            sidx[t] = idx[base]; sew[t] = ew[base]; sgw[t] = gw[base];
        }
        __syncthreads();
        int ft = t & 15, rg = t >> 4;   // 64 groups of 4 rows
        const float* hb = h2 + ft;
        float a = 0.f, b = 0.f;
#pragma unroll
        for (int j = 0; j < 4; j++) {
            int rl = rg * 4 + j;
            float v = hb[(size_t)sidx[rl] * N_CLASS];
            a += v * sew[rl];
            b += v * sgw[rl];
        }
        sH[rg][ft] = a; sL[rg][ft] = b;
        __syncthreads();
        if (t < 16) {
            float sa = 0.f, sb = 0.f;
#pragma unroll
            for (int r = 0; r < 64; r++) { sa += sH[r][t]; sb += sL[r][t]; }
            Chi[t * 16 + chunk] = sa;
            Clo[t * 16 + chunk] = sb;
        }
    }
    gbar();

    // ---- Phase C2: final scan (blocks 0..15) ----
    if (blk < 16) {
        int chunk = blk;
        int* sidx = (int*)sm;
        float* sew = (float*)(sm + 1024);
        float* sgw = (float*)(sm + 2048);
        float (*sH)[N_CLASS] = (float(*)[N_CLASS])(sm + 3072);
        float (*sL)[N_CLASS] = (float(*)[N_CLASS])(sm + 7168);
        float* sChi = (float*)(sm + 11264);  // 256
        float* sClo = (float*)(sm + 12288);  // 256
        if (t < 256) {
            int base = chunk * 256 + t;
            sidx[t] = idx[base]; sew[t] = ew[base]; sgw[t] = gw[base];
            sChi[t] = Chi[t]; sClo[t] = Clo[t];
        }
        __syncthreads();
        int ft = t & 15, rg = t >> 4;
        const float* hb = h2 + ft;
        float vh[4], vl[4];
        float a = 0.f, b = 0.f;
#pragma unroll
        for (int j = 0; j < 4; j++) {
            int rl = rg * 4 + j;
            float v = hb[(size_t)sidx[rl] * N_CLASS];
            vh[j] = v * sew[rl];
            vl[j] = v * sgw[rl];
            a += vh[j]; b += vl[j];
        }
        sH[rg][ft] = a; sL[rg][ft] = b;
        __syncthreads();
        float offh = 0.f, offl = 0.f, totl = 0.f;
#pragma unroll
        for (int c = 0; c < 16; c++) {
            float ca = sChi[ft * 16 + c], cb = sClo[ft * 16 + c];
            if (c < chunk) { offh += ca; offl += cb; }
            totl += cb;
        }
        for (int r = 0; r < rg; r++) { offh += sH[r][ft]; offl += sL[r][ft]; }
        float runh = offh, runl = offl;
        int k0 = chunk * 256 + rg * 4;
#pragma unroll
        for (int j = 0; j < 4; j++) {
            Phi[(size_t)(k0 + j) * N_CLASS + ft] = runh;
            Plo[(size_t)(k0 + j) * N_CLASS + ft] = totl - runl;
            runh += vh[j];
            runl += vl[j];
        }
        if (chunk == 15 && rg == 63) {
            Phi[(size_t)N_ROWS * N_CLASS + ft] = runh;
            Plo[(size_t)N_ROWS * N_CLASS + ft] = totl - runl;
        }
    }
    gbar();

    // ---- Phase B2: combine2 + ELU + log_softmax (blocks 0..63) ----
    if (blk < 64) {
        float* ss = (float*)sm;
        *reinterpret_cast<float4*>(ss + t * 4) = *reinterpret_cast<const float4*>(sorted + t * 4);
        __syncthreads();
        int f = t & 15, il = t >> 4;
        int i = blk * 64 + il;
        float M = ss[0];
        float s = ssrc[i];
        float thr = -s;
        int lo = 0, hi = N_ROWS;
        while (lo < hi) {
            int mid = (lo + hi) >> 1;
            if (ss[mid] >= thr) lo = mid + 1; else hi = mid;
        }
        int k = lo;
        float rho = expf(-0.8f * (s + M));
        float den = (k == 0) ? Zlo[0] : (Zhi[k] + rho * Zlo[k]);
        float num = (k == 0) ? Plo[f]
                             : (Phi[(size_t)k * N_CLASS + f] + rho * Plo[(size_t)k * N_CLASS + f]);
        float feat = num / den;
        float v = feat > 0.f ? feat : expm1f(feat);
        float m = v;
#pragma unroll
        for (int off = 8; off; off >>= 1) m = fmaxf(m, __shfl_xor_sync(0xffffffffu, m, off));
        float ex = expf(v - m);
        float ssum = ex;
#pragma unroll
        for (int off = 8; off; off >>= 1) ssum += __shfl_xor_sync(0xffffffffu, ssum, off);
        out[(size_t)i * N_CLASS + f] = v - m - logf(ssum);
    }
}

// ---------------- launch ----------------
extern "C" void kernel_launch(void* const* d_in, const int* in_sizes, int n_in,
                              void* d_out, int out_size)
{
    const float* x  = (const float*)d_in[0];
    const float* Wh = (const float*)d_in[1];
    const float* ah = (const float*)d_in[2];
    const float* Wo = (const float*)d_in[3];
    const float* ao = (const float*)d_in[4];
    float* out = (float*)d_out;

    __nv_bfloat16 *p_xh, *p_xl, *p_whh, *p_whl;
    float *p_h1, *p_ssrc1, *p_sdst1, *p_sorted1, *p_ew1, *p_gw1, *p_Zhi1, *p_Zlo1;
    float *p_Chi1, *p_Clo1, *p_Phi1, *p_Plo1, *p_xc;
    int *p_idx1;
    float *p_h2, *p_ssrc2, *p_sdst2, *p_sorted2, *p_ew2, *p_gw2, *p_Zhi2, *p_Zlo2;
    float *p_Chi2, *p_Clo2, *p_Phi2, *p_Plo2;
    int *p_idx2;

    cudaGetSymbolAddress((void**)&p_xh, g_xh);
    cudaGetSymbolAddress((void**)&p_xl, g_xl);
    cudaGetSymbolAddress((void**)&p_whh, g_whh);
    cudaGetSymbolAddress((void**)&p_whl, g_whl);
    cudaGetSymbolAddress((void**)&p_h1, g_h1);
    cudaGetSymbolAddress((void**)&p_ssrc1, g_ssrc1);
    cudaGetSymbolAddress((void**)&p_sdst1, g_sdst1);
    cudaGetSymbolAddress((void**)&p_sorted1, g_sorted1);
    cudaGetSymbolAddress((void**)&p_idx1, g_idx1);
    cudaGetSymbolAddress((void**)&p_ew1, g_ew1);
    cudaGetSymbolAddress((void**)&p_gw1, g_gw1);
    cudaGetSymbolAddress((void**)&p_Zhi1, g_Zhi1);
    cudaGetSymbolAddress((void**)&p_Zlo1, g_Zlo1);
    cudaGetSymbolAddress((void**)&p_Chi1, g_Chi1);
    cudaGetSymbolAddress((void**)&p_Clo1, g_Clo1);
    cudaGetSymbolAddress((void**)&p_Phi1, g_Phi1);
    cudaGetSymbolAddress((void**)&p_Plo1, g_Plo1);
    cudaGetSymbolAddress((void**)&p_xc, g_xc);
    cudaGetSymbolAddress((void**)&p_h2, g_h2);
    cudaGetSymbolAddress((void**)&p_ssrc2, g_ssrc2);
    cudaGetSymbolAddress((void**)&p_sdst2, g_sdst2);
    cudaGetSymbolAddress((void**)&p_sorted2, g_sorted2);
    cudaGetSymbolAddress((void**)&p_idx2, g_idx2);
    cudaGetSymbolAddress((void**)&p_ew2, g_ew2);
    cudaGetSymbolAddress((void**)&p_gw2, g_gw2);
    cudaGetSymbolAddress((void**)&p_Zhi2, g_Zhi2);
    cudaGetSymbolAddress((void**)&p_Zlo2, g_Zlo2);
    cudaGetSymbolAddress((void**)&p_Chi2, g_Chi2);
    cudaGetSymbolAddress((void**)&p_Clo2, g_Clo2);
    cudaGetSymbolAddress((void**)&p_Phi2, g_Phi2);
    cudaGetSymbolAddress((void**)&p_Plo2, g_Plo2);

    splitall_kernel<<<(NX4 + NW4 + 255) / 256, 256>>>(x, Wh, p_xh, p_xl, p_whh, p_whl);
    gemm1_mma_kernel<<<dim3(N_ROWS / 128, N_HEADS), 256>>>(p_xh, p_xl, p_whh, p_whl, ah,
                                                           p_h1, p_ssrc1, p_sdst1);
    megaL1_kernel<<<NB, 1024>>>(p_sdst1, p_sorted1, p_idx1, p_ew1, p_gw1, p_Zhi1, p_Zlo1,
                                p_h1, p_Chi1, p_Clo1, p_Phi1, p_Plo1, p_ssrc1, p_xc);
    megaL2_kernel<<<NB, 1024>>>(p_xc, Wo, ao, p_h2, p_ssrc2, p_sdst2,
                                p_sorted2, p_idx2, p_ew2, p_gw2, p_Zhi2, p_Zlo2,
                                p_Chi2, p_Clo2, p_Phi2, p_Plo2, out);

    (void)in_sizes; (void)n_in; (void)out_size;
}

// round 9
// speedup vs baseline: 1.5600x; 1.0298x over previous
#include <cuda_runtime.h>
#include <cuda_bf16.h>
#include <cstdint>

#define N_ROWS   4096
#define N_FEAT   512
#define N_HID    64
#define N_CLASS  16
#define N_HEADS  8
#define PS       (N_ROWS + 4)
#define KR       (N_ROWS + 1)
#define NB       128            // mega-kernel grid size (all-resident)

// ---------------- scratch ----------------
__device__ __nv_bfloat16 g_xh [N_ROWS*N_FEAT];
__device__ __nv_bfloat16 g_xl [N_ROWS*N_FEAT];
__device__ __nv_bfloat16 g_whh[N_HEADS*N_FEAT*N_HID];
__device__ __nv_bfloat16 g_whl[N_HEADS*N_FEAT*N_HID];

__device__ float g_h1   [N_HEADS*N_ROWS*N_HID];
__device__ float g_ssrc1[N_HEADS*N_ROWS];
__device__ float g_sdst1[N_HEADS*N_ROWS];
__device__ float g_sorted1[N_HEADS*N_ROWS];
__device__ int   g_idx1 [N_HEADS*N_ROWS];
__device__ float g_ew1  [N_HEADS*N_ROWS];
__device__ float g_gw1  [N_HEADS*N_ROWS];
__device__ float g_Zhi1 [N_HEADS*PS];
__device__ float g_Zlo1 [N_HEADS*PS];
__device__ float g_Chi1 [N_HEADS*N_HID*16];
__device__ float g_Clo1 [N_HEADS*N_HID*16];
__device__ float g_Phi1 [N_HEADS*KR*N_HID];
__device__ float g_Plo1 [N_HEADS*KR*N_HID];
__device__ float g_xc   [N_ROWS*N_FEAT];

__device__ float g_h2   [N_ROWS*N_CLASS];
__device__ float g_ssrc2[N_ROWS];
__device__ float g_sdst2[N_ROWS];
__device__ float g_sorted2[N_ROWS];
__device__ int   g_idx2 [N_ROWS];
__device__ float g_ew2  [N_ROWS];
__device__ float g_gw2  [N_ROWS];
__device__ float g_Zhi2 [PS];
__device__ float g_Zlo2 [PS];
__device__ float g_Chi2 [N_CLASS*16];
__device__ float g_Clo2 [N_CLASS*16];
__device__ float g_Phi2 [KR*N_CLASS];
__device__ float g_Plo2 [KR*N_CLASS];

// ---------------- device-wide software barrier ----------------
__device__ unsigned g_cnt;
__device__ volatile unsigned g_gen;

__device__ __forceinline__ void gbar() {
    __threadfence();
    __syncthreads();
    if (threadIdx.x == 0) {
        unsigned old = g_gen;
        if (atomicAdd(&g_cnt, 1u) == NB - 1) {
            g_cnt = 0;
            __threadfence();
            g_gen = old + 1;
        } else {
            while (g_gen == old) { __nanosleep(64); }
        }
    }
    __syncthreads();
    __threadfence();
}

// ---------------- warp-shuffle block exclusive scan (1024 thr) ----------------
__device__ __forceinline__ float blk_exscan32(float v, float* sh, float& total) {
    __syncthreads();
    int lane = threadIdx.x & 31, warp = threadIdx.x >> 5;
    float x = v;
#pragma unroll
    for (int off = 1; off < 32; off <<= 1) {
        float n = __shfl_up_sync(0xffffffffu, x, off);
        if (lane >= off) x += n;
    }
    if (lane == 31) sh[warp] = x;
    __syncthreads();
    if (warp == 0) {
        float w = sh[lane];
#pragma unroll
        for (int off = 1; off < 32; off <<= 1) {
            float n = __shfl_up_sync(0xffffffffu, w, off);
            if (lane >= off) w += n;
        }
        sh[lane] = w;
    }
    __syncthreads();
    float base = warp ? sh[warp - 1] : 0.f;
    total = sh[31];
    return base + x - v;
}

// ---------------- sortscan body: chunk-bitonic + rank-merge (keys only) ----------------
// smem: skeys = 4096 floats, grank = 4096 ints (rank in low16, tie counter in high16),
//       sh = 40 floats.
__device__ void sortscan_body(int h, const float* __restrict__ sdst,
                              float* __restrict__ sorted, int* __restrict__ idx,
                              float* __restrict__ ew, float* __restrict__ gw,
                              float* __restrict__ Zhi, float* __restrict__ Zlo,
                              float* skeys, int* grank, float* sh)
{
    int tid = threadIdx.x;
    const float* sd = sdst + (size_t)h * N_ROWS;
    float key[4];
    {
        float4 v4 = *reinterpret_cast<const float4*>(sd + tid * 4);
        key[0] = v4.x; key[1] = v4.y; key[2] = v4.z; key[3] = v4.w;
    }

    // ---- per-512-chunk bitonic sort, descending, keys only ----
    for (int k = 2; k <= 512; k <<= 1) {
        for (int j = k >> 1; j > 0; j >>= 1) {
            if (j == 1) {
#pragma unroll
                for (int q = 0; q < 4; q += 2) {
                    int e = tid * 4 + q;
                    bool desc = ((e & k & 511) == 0);
                    bool sw = desc ? (key[q] < key[q + 1]) : (key[q] > key[q + 1]);
                    if (sw) { float tk = key[q]; key[q] = key[q + 1]; key[q + 1] = tk; }
                }
            } else if (j == 2) {
#pragma unroll
                for (int q = 0; q < 2; q++) {
                    int e = tid * 4 + q;
                    bool desc = ((e & k & 511) == 0);
                    bool sw = desc ? (key[q] < key[q + 2]) : (key[q] > key[q + 2]);
                    if (sw) { float tk = key[q]; key[q] = key[q + 2]; key[q + 2] = tk; }
                }
            } else if (j <= 64) {
                int m = j >> 2;
#pragma unroll
                for (int q = 0; q < 4; q++) {
                    float ok = __shfl_xor_sync(0xffffffffu, key[q], m);
                    int e = tid * 4 + q;
                    bool lower = ((e & j) == 0);
                    bool desc = ((e & k & 511) == 0);
                    float a = lower ? key[q] : ok;
                    float b = lower ? ok : key[q];
                    bool sw = desc ? (a < b) : (a > b);
                    if (sw) key[q] = ok;
                }
            } else {   // j = 128, 256 : smem exchange (within chunk)
                __syncthreads();
#pragma unroll
                for (int q = 0; q < 4; q++) skeys[tid * 4 + q] = key[q];
                __syncthreads();
#pragma unroll
                for (int q = 0; q < 4; q++) {
                    int e = tid * 4 + q;
                    float ok = skeys[e ^ j];
                    bool lower = ((e & j) == 0);
                    bool desc = ((e & k & 511) == 0);
                    float a = lower ? key[q] : ok;
                    float b = lower ? ok : key[q];
                    bool sw = desc ? (a < b) : (a > b);
                    if (sw) key[q] = ok;
                }
            }
        }
    }
    __syncthreads();
    // publish chunk-sorted keys
#pragma unroll
    for (int q = 0; q < 4; q++) skeys[tid * 4 + q] = key[q];
    __syncthreads();

    // ---- global rank via cross-chunk binary searches; scatter sorted ----
#pragma unroll
    for (int q = 0; q < 4; q++) {
        int e = tid * 4 + q;
        int cx = e >> 9, p = e & 511;
        float x = key[q];
        int r = p;
#pragma unroll
        for (int c = 0; c < 8; c++) {
            if (c == cx) continue;
            const float* S = skeys + c * 512;
            int lo = 0, hi = 512;
            if (c < cx) {
                while (lo < hi) { int mid = (lo + hi) >> 1; if (S[mid] >= x) lo = mid + 1; else hi = mid; }
            } else {
                while (lo < hi) { int mid = (lo + hi) >> 1; if (S[mid] > x) lo = mid + 1; else hi = mid; }
            }
            r += lo;
        }
        grank[e] = r;                       // low16 = rank (r < 4096); high16 = 0
        sorted[(size_t)h * N_ROWS + r] = x; // scatter
    }
    __syncthreads();

    // ---- idx recovery: original j claims a tie slot in its own chunk ----
#pragma unroll
    for (int q = 0; q < 4; q++) {
        int j = tid * 4 + q;
        float x = sd[j];
        int c = j >> 9;
        const float* S = skeys + c * 512;
        int lo = 0, hi = 512;
        while (lo < hi) { int mid = (lo + hi) >> 1; if (S[mid] > x) lo = mid + 1; else hi = mid; }
        int off = atomicAdd(&grank[c * 512 + lo], 0x10000) >> 16;
        int rank = grank[c * 512 + lo + off] & 0xFFFF;
        idx[(size_t)h * N_ROWS + rank] = j;
    }
    __syncthreads();

    // ---- scalar scan on final sorted order (reload, coalesced) ----
    {
        float4 v4 = *reinterpret_cast<const float4*>(sorted + (size_t)h * N_ROWS + tid * 4);
        key[0] = v4.x; key[1] = v4.y; key[2] = v4.z; key[3] = v4.w;
    }
    if (tid == 0) sh[36] = key[0];
    __syncthreads();
    float M = sh[36];

    float e4[4], g4[4];
    float se = 0.f, sg = 0.f;
#pragma unroll
    for (int q = 0; q < 4; q++) {
        float xv = key[q] - M;
        e4[q] = expf(xv);
        g4[q] = expf(0.2f * xv);
        se += e4[q]; sg += g4[q];
    }
    *reinterpret_cast<float4*>(ew + (size_t)h * N_ROWS + tid * 4) =
        make_float4(e4[0], e4[1], e4[2], e4[3]);
    *reinterpret_cast<float4*>(gw + (size_t)h * N_ROWS + tid * 4) =
        make_float4(g4[0], g4[1], g4[2], g4[3]);

    float tote, totg;
    float pe = blk_exscan32(se, sh, tote);
    float pg = blk_exscan32(sg, sh, totg);

    float* ZH = Zhi + (size_t)h * PS;
    float* ZL = Zlo + (size_t)h * PS;
    float run = pe;
#pragma unroll
    for (int q = 0; q < 4; q++) { ZH[tid * 4 + q] = run; run += e4[q]; }
    float run2 = pg;
#pragma unroll
    for (int q = 0; q < 4; q++) { ZL[tid * 4 + q] = totg - run2; run2 += g4[q]; }
    if (tid == 1023) { ZH[N_ROWS] = run; ZL[N_ROWS] = 0.f; }
}

// ---------------- combined split fp32 -> bf16 hi/lo ----------------
#define NX4  (N_ROWS * N_FEAT / 4)
#define NW4  (N_HEADS * N_FEAT * N_HID / 4)
__global__ void splitall_kernel(const float* __restrict__ x, const float* __restrict__ Wh,
                                __nv_bfloat16* __restrict__ xh, __nv_bfloat16* __restrict__ xl,
                                __nv_bfloat16* __restrict__ whh, __nv_bfloat16* __restrict__ whl)
{
    int i = blockIdx.x * blockDim.x + threadIdx.x;
    const float* src; __nv_bfloat16 *hi, *lo; int j;
    if (i < NX4) { src = x; hi = xh; lo = xl; j = i; }
    else         { src = Wh; hi = whh; lo = whl; j = i - NX4; if (j >= NW4) return; }
    float4 v = reinterpret_cast<const float4*>(src)[j];
    __nv_bfloat16 h0 = __float2bfloat16_rn(v.x);
    __nv_bfloat16 h1 = __float2bfloat16_rn(v.y);
    __nv_bfloat16 h2 = __float2bfloat16_rn(v.z);
    __nv_bfloat16 h3 = __float2bfloat16_rn(v.w);
    __nv_bfloat16 l0 = __float2bfloat16_rn(v.x - __bfloat162float(h0));
    __nv_bfloat16 l1 = __float2bfloat16_rn(v.y - __bfloat162float(h1));
    __nv_bfloat16 l2 = __float2bfloat16_rn(v.z - __bfloat162float(h2));
    __nv_bfloat16 l3 = __float2bfloat16_rn(v.w - __bfloat162float(h3));
    __nv_bfloat162* hp = reinterpret_cast<__nv_bfloat162*>(hi) + j * 2;
    __nv_bfloat162* lp = reinterpret_cast<__nv_bfloat162*>(lo) + j * 2;
    hp[0] = __nv_bfloat162(h0, h1); hp[1] = __nv_bfloat162(h2, h3);
    lp[0] = __nv_bfloat162(l0, l1); lp[1] = __nv_bfloat162(l2, l3);
}

// ---------------- GEMM1 (bf16 mma + ldmatrix + fused scores) ----------------
__device__ __forceinline__ void mma16816(float* c, const uint32_t* a, const uint32_t* b) {
    asm volatile(
        "mma.sync.aligned.m16n8k16.row.col.f32.bf16.bf16.f32 "
        "{%0,%1,%2,%3}, {%4,%5,%6,%7}, {%8,%9}, {%0,%1,%2,%3};\n"
        : "+f"(c[0]), "+f"(c[1]), "+f"(c[2]), "+f"(c[3])
        : "r"(a[0]), "r"(a[1]), "r"(a[2]), "r"(a[3]), "r"(b[0]), "r"(b[1]));
}
__device__ __forceinline__ void ldmat_x4(uint32_t* r, uint32_t addr) {
    asm volatile("ldmatrix.sync.aligned.m8n8.x4.shared.b16 {%0,%1,%2,%3}, [%4];"
        : "=r"(r[0]), "=r"(r[1]), "=r"(r[2]), "=r"(r[3]) : "r"(addr));
}
__device__ __forceinline__ void ldmat_x4_t(uint32_t* r, uint32_t addr) {
    asm volatile("ldmatrix.sync.aligned.m8n8.x4.trans.shared.b16 {%0,%1,%2,%3}, [%4];"
        : "=r"(r[0]), "=r"(r[1]), "=r"(r[2]), "=r"(r[3]) : "r"(addr));
}

__global__ __launch_bounds__(256) void gemm1_mma_kernel(
    const __nv_bfloat16* __restrict__ xh, const __nv_bfloat16* __restrict__ xl,
    const __nv_bfloat16* __restrict__ whh, const __nv_bfloat16* __restrict__ whl,
    const float* __restrict__ ah,
    float* __restrict__ h1, float* __restrict__ ssrc, float* __restrict__ sdst)
{
    const int BM = 128, BKT = 64, SA = 72, SB = 72;
    __shared__ __nv_bfloat16 As[BM * SA];
    __shared__ __nv_bfloat16 Bs[BKT * SB];
    __shared__ float sred[2][2][BM];
    int h = blockIdx.y;
    int row0 = blockIdx.x * BM;
    int tid = threadIdx.x;
    int wid = tid >> 5, lane = tid & 31;
    int wm = wid & 3, wn = wid >> 2;
    int lr = lane >> 2, lc = lane & 3;
    int idx15 = lane & 15, hi8 = (lane >> 4) << 3;

    uint32_t sa_base = (uint32_t)__cvta_generic_to_shared(As);
    uint32_t sb_base = (uint32_t)__cvta_generic_to_shared(Bs);

    const __nv_bfloat16* Wb0 = whh + (size_t)h * N_FEAT * N_HID;
    const __nv_bfloat16* Wb1 = whl + (size_t)h * N_FEAT * N_HID;
    const __nv_bfloat16* Aph[3] = { xh, xl, xh };
    const __nv_bfloat16* Bph[3] = { Wb0, Wb0, Wb1 };

    float acc[2][4][4];
#pragma unroll
    for (int mm = 0; mm < 2; mm++)
#pragma unroll
        for (int nn = 0; nn < 4; nn++)
#pragma unroll
            for (int q = 0; q < 4; q++) acc[mm][nn][q] = 0.f;

    for (int p = 0; p < 3; p++) {
        const __nv_bfloat16* Ag = Aph[p];
        const __nv_bfloat16* Bg = Bph[p];
        for (int k0 = 0; k0 < N_FEAT; k0 += BKT) {
            __syncthreads();
#pragma unroll
            for (int i = 0; i < 4; i++) {
                int id4 = tid + i * 256;
                int r = id4 >> 3, kk = (id4 & 7) * 8;
                uint4 v = *reinterpret_cast<const uint4*>(
                    Ag + (size_t)(row0 + r) * N_FEAT + k0 + kk);
                *reinterpret_cast<uint4*>(As + r * SA + kk) = v;
            }
#pragma unroll
            for (int i = 0; i < 2; i++) {
                int id4 = tid + i * 256;
                int kk = id4 >> 3, ff = (id4 & 7) * 8;
                uint4 v = *reinterpret_cast<const uint4*>(
                    Bg + (size_t)(k0 + kk) * N_HID + ff);
                *reinterpret_cast<uint4*>(Bs + kk * SB + ff) = v;
            }
            __syncthreads();
#pragma unroll
            for (int ks = 0; ks < 4; ks++) {
                int kb = ks * 16;
                uint32_t afr[2][4];
#pragma unroll
                for (int mm = 0; mm < 2; mm++) {
                    uint32_t addr = sa_base +
                        (uint32_t)((wm * 32 + mm * 16 + idx15) * SA + kb + hi8) * 2u;
                    ldmat_x4(afr[mm], addr);
                }
                uint32_t bfr[4][2];
#pragma unroll
                for (int bp = 0; bp < 2; bp++) {
                    uint32_t bt[4];
                    uint32_t addr = sb_base +
                        (uint32_t)((kb + idx15) * SB + wn * 32 + bp * 16 + hi8) * 2u;
                    ldmat_x4_t(bt, addr);
                    bfr[bp * 2][0] = bt[0]; bfr[bp * 2][1] = bt[1];
                    bfr[bp * 2 + 1][0] = bt[2]; bfr[bp * 2 + 1][1] = bt[3];
                }
#pragma unroll
                for (int mm = 0; mm < 2; mm++)
#pragma unroll
                    for (int nn = 0; nn < 4; nn++)
                        mma16816(acc[mm][nn], afr[mm], bfr[nn]);
            }
        }
    }
#pragma unroll
    for (int mm = 0; mm < 2; mm++)
#pragma unroll
        for (int nn = 0; nn < 4; nn++) {
            int r = row0 + wm * 32 + mm * 16 + lr;
            int c = wn * 32 + nn * 8 + lc * 2;
            float* o = h1 + ((size_t)h * N_ROWS + r) * N_HID + c;
            *reinterpret_cast<float2*>(o) = make_float2(acc[mm][nn][0], acc[mm][nn][1]);
            *reinterpret_cast<float2*>(o + 8 * N_HID) = make_float2(acc[mm][nn][2], acc[mm][nn][3]);
        }

    const float* a = ah + (size_t)h * 2 * N_HID;
#pragma unroll
    for (int mm = 0; mm < 2; mm++) {
        float ps1 = 0.f, pd1 = 0.f, ps2 = 0.f, pd2 = 0.f;
#pragma unroll
        for (int nn = 0; nn < 4; nn++) {
            int c0 = wn * 32 + nn * 8 + lc * 2;
            float a0s = a[c0], a1s = a[c0 + 1];
            float a0d = a[N_HID + c0], a1d = a[N_HID + c0 + 1];
            ps1 += acc[mm][nn][0] * a0s + acc[mm][nn][1] * a1s;
            pd1 += acc[mm][nn][0] * a0d + acc[mm][nn][1] * a1d;
            ps2 += acc[mm][nn][2] * a0s + acc[mm][nn][3] * a1s;
            pd2 += acc[mm][nn][2] * a0d + acc[mm][nn][3] * a1d;
        }
#pragma unroll
        for (int off = 1; off <= 2; off <<= 1) {
            ps1 += __shfl_xor_sync(0xffffffffu, ps1, off);
            pd1 += __shfl_xor_sync(0xffffffffu, pd1, off);
            ps2 += __shfl_xor_sync(0xffffffffu, ps2, off);
            pd2 += __shfl_xor_sync(0xffffffffu, pd2, off);
        }
        if (lc == 0) {
            int rl = wm * 32 + mm * 16 + lr;
            sred[wn][0][rl] = ps1; sred[wn][1][rl] = pd1;
            sred[wn][0][rl + 8] = ps2; sred[wn][1][rl + 8] = pd2;
        }
    }
    __syncthreads();
    if (tid < BM) {
        int gi = h * N_ROWS + row0 + tid;
        ssrc[gi] = sred[0][0][tid] + sred[1][0][tid];
        sdst[gi] = sred[0][1][tid] + sred[1][1][tid];
    }
}

// ---------------- megaL1: sortscan1 + featA1 + featC1 + combine1 ----------------
__global__ __launch_bounds__(1024, 1) void megaL1_kernel(
    const float* __restrict__ sdst, float* __restrict__ sorted, int* __restrict__ idx,
    float* __restrict__ ew, float* __restrict__ gw,
    float* __restrict__ Zhi, float* __restrict__ Zlo,
    const float* __restrict__ h1, float* __restrict__ Chi, float* __restrict__ Clo,
    float* __restrict__ Phi, float* __restrict__ Plo,
    const float* __restrict__ ssrc, float* __restrict__ xc)
{
    __shared__ __align__(16) unsigned char sm[33792];
    int blk = blockIdx.x, t = threadIdx.x;

    // ---- Phase S: per-head sortscan (blocks 0..7) ----
    if (blk < N_HEADS) {
        sortscan_body(blk, sdst, sorted, idx, ew, gw, Zhi, Zlo,
                      (float*)sm, (int*)(sm + 16384), (float*)(sm + 32768));
    }
    gbar();

    int h = blk >> 4, chunk = blk & 15;

    // ---- Phase A: featA chunk sums ----
    {
        int* sidx = (int*)sm;
        float* sew = (float*)(sm + 1024);
        float* sgw = (float*)(sm + 2048);
        float (*sH)[N_HID] = (float(*)[N_HID])(sm + 3072);
        float (*sL)[N_HID] = (float(*)[N_HID])(sm + 7168);
        int ft = t & 63, rg = t >> 6;
        if (t < 256) {
            int base = h * N_ROWS + chunk * 256 + t;
            sidx[t] = idx[base]; sew[t] = ew[base]; sgw[t] = gw[base];
        }
        __syncthreads();
        const float* hb = h1 + (size_t)h * N_ROWS * N_HID + ft;
        float sh_ = 0.f, sl_ = 0.f;
#pragma unroll
        for (int j = 0; j < 16; j++) {
            int rl = rg * 16 + j;
            float v = hb[(size_t)sidx[rl] * N_HID];
            sh_ += v * sew[rl];
            sl_ += v * sgw[rl];
        }
        sH[rg][ft] = sh_; sL[rg][ft] = sl_;
        __syncthreads();
        if (rg == 0) {
            float a = 0.f, b = 0.f;
#pragma unroll
            for (int r = 0; r < 16; r++) { a += sH[r][ft]; b += sL[r][ft]; }
            Chi[(h * N_HID + ft) * 16 + chunk] = a;
            Clo[(h * N_HID + ft) * 16 + chunk] = b;
        }
    }
    gbar();

    // ---- Phase C: featC final scan ----
    {
        int* sidx = (int*)sm;
        float* sew = (float*)(sm + 1024);
        float* sgw = (float*)(sm + 2048);
        float* sChi = (float*)(sm + 3072);
        float* sClo = (float*)(sm + 7168);
        float (*sH)[N_HID] = (float(*)[N_HID])(sm + 11264);
        float (*sL)[N_HID] = (float(*)[N_HID])(sm + 15360);
        int ft = t & 63, rg = t >> 6;
        if (t < 256) {
            int base = h * N_ROWS + chunk * 256 + t;
            sidx[t] = idx[base]; sew[t] = ew[base]; sgw[t] = gw[base];
        }
        sChi[t] = Chi[h * N_HID * 16 + t];
        sClo[t] = Clo[h * N_HID * 16 + t];
        __syncthreads();
        const float* hb = h1 + (size_t)h * N_ROWS * N_HID + ft;
        float vh[16], vl[16];
        float sh_ = 0.f, sl_ = 0.f;
#pragma unroll
        for (int j = 0; j < 16; j++) {
            int rl = rg * 16 + j;
            float v = hb[(size_t)sidx[rl] * N_HID];
            vh[j] = v * sew[rl];
            vl[j] = v * sgw[rl];
            sh_ += vh[j]; sl_ += vl[j];
        }
        sH[rg][ft] = sh_; sL[rg][ft] = sl_;
        __syncthreads();
        float offh = 0.f, offl = 0.f, totl = 0.f;
#pragma unroll
        for (int c = 0; c < 16; c++) {
            float a = sChi[ft * 16 + c], b = sClo[ft * 16 + c];
            if (c < chunk) { offh += a; offl += b; }
            totl += b;
        }
        for (int r = 0; r < rg; r++) { offh += sH[r][ft]; offl += sL[r][ft]; }
        float* PH = Phi + (size_t)h * KR * N_HID + ft;
        float* PL = Plo + (size_t)h * KR * N_HID + ft;
        float runh = offh, runl = offl;
        int k0 = chunk * 256 + rg * 16;
#pragma unroll
        for (int j = 0; j < 16; j++) {
            PH[(size_t)(k0 + j) * N_HID] = runh;
            PL[(size_t)(k0 + j) * N_HID] = totl - runl;
            runh += vh[j];
            runl += vl[j];
        }
        if (chunk == 15 && rg == 15) {
            PH[(size_t)N_ROWS * N_HID] = runh;
            PL[(size_t)N_ROWS * N_HID] = totl - runl;
        }
    }
    gbar();

    // ---- Phase B: combine1 ----
    {
        float* ss = (float*)sm;
        const float* sb = sorted + (size_t)h * N_ROWS;
        *reinterpret_cast<float4*>(ss + t * 4) = *reinterpret_cast<const float4*>(sb + t * 4);
        __syncthreads();
        int warp = t >> 5, lane = t & 31;
        float M = ss[0];
        const float* ZH = Zhi + (size_t)h * PS;
        const float* ZL = Zlo + (size_t)h * PS;
        const float* PHb = Phi + (size_t)h * KR * N_HID;
        const float* PLb = Plo + (size_t)h * KR * N_HID;
        int i0 = chunk * 256;
#pragma unroll
        for (int rr = 0; rr < 8; rr++) {
            int i = i0 + warp * 8 + rr;
            float s = ssrc[(size_t)h * N_ROWS + i];
            float thr = -s;
            int lo = 0, hi = N_ROWS;
            while (lo < hi) {
                int mid = (lo + hi) >> 1;
                if (ss[mid] >= thr) lo = mid + 1; else hi = mid;
            }
            int k = lo;
            float rho = expf(-0.8f * (s + M));
            float den = (k == 0) ? ZL[0] : (ZH[k] + rho * ZL[k]);
            float inv = 1.f / den;
            const float* ph = PHb + (size_t)k * N_HID;
            const float* pl = PLb + (size_t)k * N_HID;
#pragma unroll
            for (int u = 0; u < 2; u++) {
                int f = lane + 32 * u;
                float num = (k == 0) ? pl[f] : (ph[f] + rho * pl[f]);
                float feat = num * inv;
                float v = feat > 0.f ? feat : expm1f(feat);
                xc[(size_t)i * N_FEAT + h * N_HID + f] = v;
            }
        }
    }
}

// ---------------- megaL2: gemm2+scores2 + sortscan2 + featA2/C2 + combine2 ----------------
__global__ __launch_bounds__(1024, 1) void megaL2_kernel(
    const float* __restrict__ xc, const float* __restrict__ Wo, const float* __restrict__ ao,
    float* __restrict__ h2, float* __restrict__ ssrc, float* __restrict__ sdst,
    float* __restrict__ sorted, int* __restrict__ idx,
    float* __restrict__ ew, float* __restrict__ gw,
    float* __restrict__ Zhi, float* __restrict__ Zlo,
    float* __restrict__ Chi, float* __restrict__ Clo,
    float* __restrict__ Phi, float* __restrict__ Plo,
    float* __restrict__ out)
{
    __shared__ __align__(16) unsigned char sm[33792];
    int blk = blockIdx.x, t = threadIdx.x;

    // ---- Phase G: gemm2 + fused scores2 (32 rows per block) ----
    {
        float (*xs)[64] = (float(*)[64])sm;
        float (*ws)[16] = (float(*)[16])(sm + 8192);
        int row0 = blk * 32;
        int ir = t >> 4, fc = t & 15;
        float acc = 0.f;
        for (int k0 = 0; k0 < N_FEAT; k0 += 64) {
            __syncthreads();
#pragma unroll
            for (int rep = 0; rep < 2; rep++) {
                int t2 = t + rep * 1024;
                int r = t2 >> 6, kk = t2 & 63;
                xs[r][kk] = xc[(size_t)(row0 + r) * N_FEAT + k0 + kk];
            }
            {
                int kk = t >> 4, f = t & 15;
                if (kk < 64) ws[kk][f] = Wo[(size_t)(k0 + kk) * N_CLASS + f];
            }
            __syncthreads();
            if (t < 512) {
#pragma unroll
                for (int kk = 0; kk < 64; kk++) acc += xs[ir][kk] * ws[kk][fc];
            }
        }
        if (t < 512) {
            h2[(size_t)(row0 + ir) * N_CLASS + fc] = acc;
            float ps = acc * ao[fc];
            float pd = acc * ao[N_CLASS + fc];
#pragma unroll
            for (int off = 1; off < 16; off <<= 1) {
                ps += __shfl_xor_sync(0xffffffffu, ps, off);
                pd += __shfl_xor_sync(0xffffffffu, pd, off);
            }
            if (fc == 0) {
                ssrc[row0 + ir] = ps;
                sdst[row0 + ir] = pd;
            }
        }
    }
    gbar();

    // ---- Phase S2: sortscan (block 0 only) ----
    if (blk == 0) {
        sortscan_body(0, sdst, sorted, idx, ew, gw, Zhi, Zlo,
                      (float*)sm, (int*)(sm + 16384), (float*)(sm + 32768));
    }
    gbar();

    // ---- Phase A2: chunk sums (blocks 0..15) ----
    if (blk < 16) {
        int chunk = blk;
        int* sidx = (int*)sm;
        float* sew = (float*)(sm + 1024);
        float* sgw = (float*)(sm + 2048);
        float (*sH)[N_CLASS] = (float(*)[N_CLASS])(sm + 3072);
        float (*sL)[N_CLASS] = (float(*)[N_CLASS])(sm + 7168);
        if (t < 256) {
            int base = chunk * 256 + t;
            sidx[t] = idx[base]; sew[t] = ew[base]; sgw[t] = gw[base];
        }
        __syncthreads();
        int ft = t & 15, rg = t >> 4;
        const float* hb = h2 + ft;
        float a = 0.f, b = 0.f;
#pragma unroll
        for (int j = 0; j < 4; j++) {
            int rl = rg * 4 + j;
            float v = hb[(size_t)sidx[rl] * N_CLASS];
            a += v * sew[rl];
            b += v * sgw[rl];
        }
        sH[rg][ft] = a; sL[rg][ft] = b;
        __syncthreads();
        if (t < 16) {
            float sa = 0.f, sb = 0.f;
#pragma unroll
            for (int r = 0; r < 64; r++) { sa += sH[r][t]; sb += sL[r][t]; }
            Chi[t * 16 + chunk] = sa;
            Clo[t * 16 + chunk] = sb;
        }
    }
    gbar();

    // ---- Phase C2: final scan (blocks 0..15) ----
    if (blk < 16) {
        int chunk = blk;
        int* sidx = (int*)sm;
        float* sew = (float*)(sm + 1024);
        float* sgw = (float*)(sm + 2048);
        float (*sH)[N_CLASS] = (float(*)[N_CLASS])(sm + 3072);
        float (*sL)[N_CLASS] = (float(*)[N_CLASS])(sm + 7168);
        float* sChi = (float*)(sm + 11264);
        float* sClo = (float*)(sm + 12288);
        if (t < 256) {
            int base = chunk * 256 + t;
            sidx[t] = idx[base]; sew[t] = ew[base]; sgw[t] = gw[base];
            sChi[t] = Chi[t]; sClo[t] = Clo[t];
        }
        __syncthreads();
        int ft = t & 15, rg = t >> 4;
        const float* hb = h2 + ft;
        float vh[4], vl[4];
        float a = 0.f, b = 0.f;
#pragma unroll
        for (int j = 0; j < 4; j++) {
            int rl = rg * 4 + j;
            float v = hb[(size_t)sidx[rl] * N_CLASS];
            vh[j] = v * sew[rl];
            vl[j] = v * sgw[rl];
            a += vh[j]; b += vl[j];
        }
        sH[rg][ft] = a; sL[rg][ft] = b;
        __syncthreads();
        float offh = 0.f, offl = 0.f, totl = 0.f;
#pragma unroll
        for (int c = 0; c < 16; c++) {
            float ca = sChi[ft * 16 + c], cb = sClo[ft * 16 + c];
            if (c < chunk) { offh += ca; offl += cb; }
            totl += cb;
        }
        for (int r = 0; r < rg; r++) { offh += sH[r][ft]; offl += sL[r][ft]; }
        float runh = offh, runl = offl;
        int k0 = chunk * 256 + rg * 4;
#pragma unroll
        for (int j = 0; j < 4; j++) {
            Phi[(size_t)(k0 + j) * N_CLASS + ft] = runh;
            Plo[(size_t)(k0 + j) * N_CLASS + ft] = totl - runl;
            runh += vh[j];
            runl += vl[j];
        }
        if (chunk == 15 && rg == 63) {
            Phi[(size_t)N_ROWS * N_CLASS + ft] = runh;
            Plo[(size_t)N_ROWS * N_CLASS + ft] = totl - runl;
        }
    }
    gbar();

    // ---- Phase B2: combine2 + ELU + log_softmax (blocks 0..63) ----
    if (blk < 64) {
        float* ss = (float*)sm;
        *reinterpret_cast<float4*>(ss + t * 4) = *reinterpret_cast<const float4*>(sorted + t * 4);
        __syncthreads();
        int f = t & 15, il = t >> 4;
        int i = blk * 64 + il;
        float M = ss[0];
        float s = ssrc[i];
        float thr = -s;
        int lo = 0, hi = N_ROWS;
        while (lo < hi) {
            int mid = (lo + hi) >> 1;
            if (ss[mid] >= thr) lo = mid + 1; else hi = mid;
        }
        int k = lo;
        float rho = expf(-0.8f * (s + M));
        float den = (k == 0) ? Zlo[0] : (Zhi[k] + rho * Zlo[k]);
        float num = (k == 0) ? Plo[f]
                             : (Phi[(size_t)k * N_CLASS + f] + rho * Plo[(size_t)k * N_CLASS + f]);
        float feat = num / den;
        float v = feat > 0.f ? feat : expm1f(feat);
        float m = v;
#pragma unroll
        for (int off = 8; off; off >>= 1) m = fmaxf(m, __shfl_xor_sync(0xffffffffu, m, off));
        float ex = expf(v - m);
        float ssum = ex;
#pragma unroll
        for (int off = 8; off; off >>= 1) ssum += __shfl_xor_sync(0xffffffffu, ssum, off);
        out[(size_t)i * N_CLASS + f] = v - m - logf(ssum);
    }
}

// ---------------- launch ----------------
extern "C" void kernel_launch(void* const* d_in, const int* in_sizes, int n_in,
                              void* d_out, int out_size)
{
    const float* x  = (const float*)d_in[0];
    const float* Wh = (const float*)d_in[1];
    const float* ah = (const float*)d_in[2];
    const float* Wo = (const float*)d_in[3];
    const float* ao = (const float*)d_in[4];
    float* out = (float*)d_out;

    __nv_bfloat16 *p_xh, *p_xl, *p_whh, *p_whl;
    float *p_h1, *p_ssrc1, *p_sdst1, *p_sorted1, *p_ew1, *p_gw1, *p_Zhi1, *p_Zlo1;
    float *p_Chi1, *p_Clo1, *p_Phi1, *p_Plo1, *p_xc;
    int *p_idx1;
    float *p_h2, *p_ssrc2, *p_sdst2, *p_sorted2, *p_ew2, *p_gw2, *p_Zhi2, *p_Zlo2;
    float *p_Chi2, *p_Clo2, *p_Phi2, *p_Plo2;
    int *p_idx2;

    cudaGetSymbolAddress((void**)&p_xh, g_xh);
    cudaGetSymbolAddress((void**)&p_xl, g_xl);
    cudaGetSymbolAddress((void**)&p_whh, g_whh);
    cudaGetSymbolAddress((void**)&p_whl, g_whl);
    cudaGetSymbolAddress((void**)&p_h1, g_h1);
    cudaGetSymbolAddress((void**)&p_ssrc1, g_ssrc1);
    cudaGetSymbolAddress((void**)&p_sdst1, g_sdst1);
    cudaGetSymbolAddress((void**)&p_sorted1, g_sorted1);
    cudaGetSymbolAddress((void**)&p_idx1, g_idx1);
    cudaGetSymbolAddress((void**)&p_ew1, g_ew1);
    cudaGetSymbolAddress((void**)&p_gw1, g_gw1);
    cudaGetSymbolAddress((void**)&p_Zhi1, g_Zhi1);
    cudaGetSymbolAddress((void**)&p_Zlo1, g_Zlo1);
    cudaGetSymbolAddress((void**)&p_Chi1, g_Chi1);
    cudaGetSymbolAddress((void**)&p_Clo1, g_Clo1);
    cudaGetSymbolAddress((void**)&p_Phi1, g_Phi1);
    cudaGetSymbolAddress((void**)&p_Plo1, g_Plo1);
    cudaGetSymbolAddress((void**)&p_xc, g_xc);
    cudaGetSymbolAddress((void**)&p_h2, g_h2);
    cudaGetSymbolAddress((void**)&p_ssrc2, g_ssrc2);
    cudaGetSymbolAddress((void**)&p_sdst2, g_sdst2);
    cudaGetSymbolAddress((void**)&p_sorted2, g_sorted2);
    cudaGetSymbolAddress((void**)&p_idx2, g_idx2);
    cudaGetSymbolAddress((void**)&p_ew2, g_ew2);
    cudaGetSymbolAddress((void**)&p_gw2, g_gw2);
    cudaGetSymbolAddress((void**)&p_Zhi2, g_Zhi2);
    cudaGetSymbolAddress((void**)&p_Zlo2, g_Zlo2);
    cudaGetSymbolAddress((void**)&p_Chi2, g_Chi2);
    cudaGetSymbolAddress((void**)&p_Clo2, g_Clo2);
    cudaGetSymbolAddress((void**)&p_Phi2, g_Phi2);
    cudaGetSymbolAddress((void**)&p_Plo2, g_Plo2);

    splitall_kernel<<<(NX4 + NW4 + 255) / 256, 256>>>(x, Wh, p_xh, p_xl, p_whh, p_whl);
    gemm1_mma_kernel<<<dim3(N_ROWS / 128, N_HEADS), 256>>>(p_xh, p_xl, p_whh, p_whl, ah,
                                                           p_h1, p_ssrc1, p_sdst1);
    megaL1_kernel<<<NB, 1024>>>(p_sdst1, p_sorted1, p_idx1, p_ew1, p_gw1, p_Zhi1, p_Zlo1,
                                p_h1, p_Chi1, p_Clo1, p_Phi1, p_Plo1, p_ssrc1, p_xc);
    megaL2_kernel<<<NB, 1024>>>(p_xc, Wo, ao, p_h2, p_ssrc2, p_sdst2,
                                p_sorted2, p_idx2, p_ew2, p_gw2, p_Zhi2, p_Zlo2,
                                p_Chi2, p_Clo2, p_Phi2, p_Plo2, out);

    (void)in_sizes; (void)n_in; (void)out_size;
}

// round 11
// speedup vs baseline: 1.5986x; 1.0247x over previous
#include <cuda_runtime.h>
#include <cuda_bf16.h>
#include <cstdint>

#define N_ROWS   4096
#define N_FEAT   512
#define N_HID    64
#define N_CLASS  16
#define N_HEADS  8
#define PS       (N_ROWS + 4)
#define KR       (N_ROWS + 1)
#define NB       128            // mega-kernel grid size (all-resident)

// ---------------- scratch ----------------
__device__ __nv_bfloat16 g_xh [N_ROWS*N_FEAT];
__device__ __nv_bfloat16 g_xl [N_ROWS*N_FEAT];
__device__ __nv_bfloat16 g_whh[N_HEADS*N_FEAT*N_HID];
__device__ __nv_bfloat16 g_whl[N_HEADS*N_FEAT*N_HID];

__device__ float g_h1   [N_HEADS*N_ROWS*N_HID];
__device__ float g_ssrc1[N_HEADS*N_ROWS];
__device__ float g_sdst1[N_HEADS*N_ROWS];
__device__ float g_sorted1[N_HEADS*N_ROWS];
__device__ int   g_idx1 [N_HEADS*N_ROWS];
__device__ float g_ew1  [N_HEADS*N_ROWS];
__device__ float g_gw1  [N_HEADS*N_ROWS];
__device__ float g_Zhi1 [N_HEADS*PS];
__device__ float g_Zlo1 [N_HEADS*PS];
__device__ float g_Chi1 [N_HEADS*N_HID*16];
__device__ float g_Clo1 [N_HEADS*N_HID*16];
__device__ float g_Phi1 [N_HEADS*KR*N_HID];
__device__ float g_Plo1 [N_HEADS*KR*N_HID];
__device__ float g_xc   [N_ROWS*N_FEAT];

__device__ float g_h2   [N_ROWS*N_CLASS];
__device__ float g_ssrc2[N_ROWS];
__device__ float g_sdst2[N_ROWS];
__device__ float g_sorted2[N_ROWS];
__device__ int   g_idx2 [N_ROWS];
__device__ float g_ew2  [N_ROWS];
__device__ float g_gw2  [N_ROWS];
__device__ float g_Zhi2 [PS];
__device__ float g_Zlo2 [PS];
__device__ float g_Chi2 [N_CLASS*16];
__device__ float g_Clo2 [N_CLASS*16];
__device__ float g_Phi2 [KR*N_CLASS];
__device__ float g_Plo2 [KR*N_CLASS];

// ---------------- device-wide software barrier (single-thread fences, safe reset order) ----------------
__device__ unsigned g_cnt;
__device__ volatile unsigned g_gen;

__device__ __forceinline__ void gbar() {
    __syncthreads();                      // block-scope: thread 0 observes block's writes
    if (threadIdx.x == 0) {
        __threadfence();                  // gpu-scope release (cumulative for the block)
        unsigned old = g_gen;
        if (atomicAdd(&g_cnt, 1u) == NB - 1) {
            g_cnt = 0;
            __threadfence();              // reset must be visible BEFORE gen bump (deadlock guard)
            g_gen = old + 1;
        } else {
            while (g_gen == old) { __nanosleep(64); }
            __threadfence();              // gpu-scope acquire
        }
    }
    __syncthreads();                      // publish to rest of block
}

// ---------------- warp-shuffle block exclusive scan (1024 thr) ----------------
__device__ __forceinline__ float blk_exscan32(float v, float* sh, float& total) {
    __syncthreads();
    int lane = threadIdx.x & 31, warp = threadIdx.x >> 5;
    float x = v;
#pragma unroll
    for (int off = 1; off < 32; off <<= 1) {
        float n = __shfl_up_sync(0xffffffffu, x, off);
        if (lane >= off) x += n;
    }
    if (lane == 31) sh[warp] = x;
    __syncthreads();
    if (warp == 0) {
        float w = sh[lane];
#pragma unroll
        for (int off = 1; off < 32; off <<= 1) {
            float n = __shfl_up_sync(0xffffffffu, w, off);
            if (lane >= off) w += n;
        }
        sh[lane] = w;
    }
    __syncthreads();
    float base = warp ? sh[warp - 1] : 0.f;
    total = sh[31];
    return base + x - v;
}

// ---------------- sortscan body: chunk-bitonic + rank-merge (keys only) ----------------
__device__ void sortscan_body(int h, const float* __restrict__ sdst,
                              float* __restrict__ sorted, int* __restrict__ idx,
                              float* __restrict__ ew, float* __restrict__ gw,
                              float* __restrict__ Zhi, float* __restrict__ Zlo,
                              float* skeys, int* grank, float* sh)
{
    int tid = threadIdx.x;
    const float* sd = sdst + (size_t)h * N_ROWS;
    float key[4];
    {
        float4 v4 = *reinterpret_cast<const float4*>(sd + tid * 4);
        key[0] = v4.x; key[1] = v4.y; key[2] = v4.z; key[3] = v4.w;
    }

    // ---- per-512-chunk bitonic sort, descending, keys only ----
    for (int k = 2; k <= 512; k <<= 1) {
        for (int j = k >> 1; j > 0; j >>= 1) {
            if (j == 1) {
#pragma unroll
                for (int q = 0; q < 4; q += 2) {
                    int e = tid * 4 + q;
                    bool desc = ((e & k & 511) == 0);
                    bool sw = desc ? (key[q] < key[q + 1]) : (key[q] > key[q + 1]);
                    if (sw) { float tk = key[q]; key[q] = key[q + 1]; key[q + 1] = tk; }
                }
            } else if (j == 2) {
#pragma unroll
                for (int q = 0; q < 2; q++) {
                    int e = tid * 4 + q;
                    bool desc = ((e & k & 511) == 0);
                    bool sw = desc ? (key[q] < key[q + 2]) : (key[q] > key[q + 2]);
                    if (sw) { float tk = key[q]; key[q] = key[q + 2]; key[q + 2] = tk; }
                }
            } else if (j <= 64) {
                int m = j >> 2;
#pragma unroll
                for (int q = 0; q < 4; q++) {
                    float ok = __shfl_xor_sync(0xffffffffu, key[q], m);
                    int e = tid * 4 + q;
                    bool lower = ((e & j) == 0);
                    bool desc = ((e & k & 511) == 0);
                    float a = lower ? key[q] : ok;
                    float b = lower ? ok : key[q];
                    bool sw = desc ? (a < b) : (a > b);
                    if (sw) key[q] = ok;
                }
            } else {   // j = 128, 256
                __syncthreads();
#pragma unroll
                for (int q = 0; q < 4; q++) skeys[tid * 4 + q] = key[q];
                __syncthreads();
#pragma unroll
                for (int q = 0; q < 4; q++) {
                    int e = tid * 4 + q;
                    float ok = skeys[e ^ j];
                    bool lower = ((e & j) == 0);
                    bool desc = ((e & k & 511) == 0);
                    float a = lower ? key[q] : ok;
                    float b = lower ? ok : key[q];
                    bool sw = desc ? (a < b) : (a > b);
                    if (sw) key[q] = ok;
                }
            }
        }
    }
    __syncthreads();
#pragma unroll
    for (int q = 0; q < 4; q++) skeys[tid * 4 + q] = key[q];
    __syncthreads();

    // ---- global rank via cross-chunk binary searches; scatter sorted ----
#pragma unroll
    for (int q = 0; q < 4; q++) {
        int e = tid * 4 + q;
        int cx = e >> 9, p = e & 511;
        float x = key[q];
        int r = p;
#pragma unroll
        for (int c = 0; c < 8; c++) {
            if (c == cx) continue;
            const float* S = skeys + c * 512;
            int lo = 0, hi = 512;
            if (c < cx) {
                while (lo < hi) { int mid = (lo + hi) >> 1; if (S[mid] >= x) lo = mid + 1; else hi = mid; }
            } else {
                while (lo < hi) { int mid = (lo + hi) >> 1; if (S[mid] > x) lo = mid + 1; else hi = mid; }
            }
            r += lo;
        }
        grank[e] = r;
        sorted[(size_t)h * N_ROWS + r] = x;
    }
    __syncthreads();

    // ---- idx recovery ----
#pragma unroll
    for (int q = 0; q < 4; q++) {
        int j = tid * 4 + q;
        float x = sd[j];
        int c = j >> 9;
        const float* S = skeys + c * 512;
        int lo = 0, hi = 512;
        while (lo < hi) { int mid = (lo + hi) >> 1; if (S[mid] > x) lo = mid + 1; else hi = mid; }
        int off = atomicAdd(&grank[c * 512 + lo], 0x10000) >> 16;
        int rank = grank[c * 512 + lo + off] & 0xFFFF;
        idx[(size_t)h * N_ROWS + rank] = j;
    }
    __syncthreads();

    // ---- scalar scan on final sorted order ----
    {
        float4 v4 = *reinterpret_cast<const float4*>(sorted + (size_t)h * N_ROWS + tid * 4);
        key[0] = v4.x; key[1] = v4.y; key[2] = v4.z; key[3] = v4.w;
    }
    if (tid == 0) sh[36] = key[0];
    __syncthreads();
    float M = sh[36];

    float e4[4], g4[4];
    float se = 0.f, sg = 0.f;
#pragma unroll
    for (int q = 0; q < 4; q++) {
        float xv = key[q] - M;
        e4[q] = expf(xv);
        g4[q] = expf(0.2f * xv);
        se += e4[q]; sg += g4[q];
    }
    *reinterpret_cast<float4*>(ew + (size_t)h * N_ROWS + tid * 4) =
        make_float4(e4[0], e4[1], e4[2], e4[3]);
    *reinterpret_cast<float4*>(gw + (size_t)h * N_ROWS + tid * 4) =
        make_float4(g4[0], g4[1], g4[2], g4[3]);

    float tote, totg;
    float pe = blk_exscan32(se, sh, tote);
    float pg = blk_exscan32(sg, sh, totg);

    float* ZH = Zhi + (size_t)h * PS;
    float* ZL = Zlo + (size_t)h * PS;
    float run = pe;
#pragma unroll
    for (int q = 0; q < 4; q++) { ZH[tid * 4 + q] = run; run += e4[q]; }
    float run2 = pg;
#pragma unroll
    for (int q = 0; q < 4; q++) { ZL[tid * 4 + q] = totg - run2; run2 += g4[q]; }
    if (tid == 1023) { ZH[N_ROWS] = run; ZL[N_ROWS] = 0.f; }
}

// ---------------- combined split fp32 -> bf16 hi/lo ----------------
#define NX4  (N_ROWS * N_FEAT / 4)
#define NW4  (N_HEADS * N_FEAT * N_HID / 4)
__global__ void splitall_kernel(const float* __restrict__ x, const float* __restrict__ Wh,
                                __nv_bfloat16* __restrict__ xh, __nv_bfloat16* __restrict__ xl,
                                __nv_bfloat16* __restrict__ whh, __nv_bfloat16* __restrict__ whl)
{
    int i = blockIdx.x * blockDim.x + threadIdx.x;
    const float* src; __nv_bfloat16 *hi, *lo; int j;
    if (i < NX4) { src = x; hi = xh; lo = xl; j = i; }
    else         { src = Wh; hi = whh; lo = whl; j = i - NX4; if (j >= NW4) return; }
    float4 v = reinterpret_cast<const float4*>(src)[j];
    __nv_bfloat16 h0 = __float2bfloat16_rn(v.x);
    __nv_bfloat16 h1 = __float2bfloat16_rn(v.y);
    __nv_bfloat16 h2 = __float2bfloat16_rn(v.z);
    __nv_bfloat16 h3 = __float2bfloat16_rn(v.w);
    __nv_bfloat16 l0 = __float2bfloat16_rn(v.x - __bfloat162float(h0));
    __nv_bfloat16 l1 = __float2bfloat16_rn(v.y - __bfloat162float(h1));
    __nv_bfloat16 l2 = __float2bfloat16_rn(v.z - __bfloat162float(h2));
    __nv_bfloat16 l3 = __float2bfloat16_rn(v.w - __bfloat162float(h3));
    __nv_bfloat162* hp = reinterpret_cast<__nv_bfloat162*>(hi) + j * 2;
    __nv_bfloat162* lp = reinterpret_cast<__nv_bfloat162*>(lo) + j * 2;
    hp[0] = __nv_bfloat162(h0, h1); hp[1] = __nv_bfloat162(h2, h3);
    lp[0] = __nv_bfloat162(l0, l1); lp[1] = __nv_bfloat162(l2, l3);
}

// ---------------- GEMM1 (bf16 mma + ldmatrix + fused scores) ----------------
__device__ __forceinline__ void mma16816(float* c, const uint32_t* a, const uint32_t* b) {
    asm volatile(
        "mma.sync.aligned.m16n8k16.row.col.f32.bf16.bf16.f32 "
        "{%0,%1,%2,%3}, {%4,%5,%6,%7}, {%8,%9}, {%0,%1,%2,%3};\n"
        : "+f"(c[0]), "+f"(c[1]), "+f"(c[2]), "+f"(c[3])
        : "r"(a[0]), "r"(a[1]), "r"(a[2]), "r"(a[3]), "r"(b[0]), "r"(b[1]));
}
__device__ __forceinline__ void ldmat_x4(uint32_t* r, uint32_t addr) {
    asm volatile("ldmatrix.sync.aligned.m8n8.x4.shared.b16 {%0,%1,%2,%3}, [%4];"
        : "=r"(r[0]), "=r"(r[1]), "=r"(r[2]), "=r"(r[3]) : "r"(addr));
}
__device__ __forceinline__ void ldmat_x4_t(uint32_t* r, uint32_t addr) {
    asm volatile("ldmatrix.sync.aligned.m8n8.x4.trans.shared.b16 {%0,%1,%2,%3}, [%4];"
        : "=r"(r[0]), "=r"(r[1]), "=r"(r[2]), "=r"(r[3]) : "r"(addr));
}

__global__ __launch_bounds__(256) void gemm1_mma_kernel(
    const __nv_bfloat16* __restrict__ xh, const __nv_bfloat16* __restrict__ xl,
    const __nv_bfloat16* __restrict__ whh, const __nv_bfloat16* __restrict__ whl,
    const float* __restrict__ ah,
    float* __restrict__ h1, float* __restrict__ ssrc, float* __restrict__ sdst)
{
    const int BM = 128, BKT = 64, SA = 72, SB = 72;
    __shared__ __nv_bfloat16 As[BM * SA];
    __shared__ __nv_bfloat16 Bs[BKT * SB];
    __shared__ float sred[2][2][BM];
    int h = blockIdx.y;
    int row0 = blockIdx.x * BM;
    int tid = threadIdx.x;
    int wid = tid >> 5, lane = tid & 31;
    int wm = wid & 3, wn = wid >> 2;
    int lr = lane >> 2, lc = lane & 3;
    int idx15 = lane & 15, hi8 = (lane >> 4) << 3;

    uint32_t sa_base = (uint32_t)__cvta_generic_to_shared(As);
    uint32_t sb_base = (uint32_t)__cvta_generic_to_shared(Bs);

    const __nv_bfloat16* Wb0 = whh + (size_t)h * N_FEAT * N_HID;
    const __nv_bfloat16* Wb1 = whl + (size_t)h * N_FEAT * N_HID;
    const __nv_bfloat16* Aph[3] = { xh, xl, xh };
    const __nv_bfloat16* Bph[3] = { Wb0, Wb0, Wb1 };

    float acc[2][4][4];
#pragma unroll
    for (int mm = 0; mm < 2; mm++)
#pragma unroll
        for (int nn = 0; nn < 4; nn++)
#pragma unroll
            for (int q = 0; q < 4; q++) acc[mm][nn][q] = 0.f;

    for (int p = 0; p < 3; p++) {
        const __nv_bfloat16* Ag = Aph[p];
        const __nv_bfloat16* Bg = Bph[p];
        for (int k0 = 0; k0 < N_FEAT; k0 += BKT) {
            __syncthreads();
#pragma unroll
            for (int i = 0; i < 4; i++) {
                int id4 = tid + i * 256;
                int r = id4 >> 3, kk = (id4 & 7) * 8;
                uint4 v = *reinterpret_cast<const uint4*>(
                    Ag + (size_t)(row0 + r) * N_FEAT + k0 + kk);
                *reinterpret_cast<uint4*>(As + r * SA + kk) = v;
            }
#pragma unroll
            for (int i = 0; i < 2; i++) {
                int id4 = tid + i * 256;
                int kk = id4 >> 3, ff = (id4 & 7) * 8;
                uint4 v = *reinterpret_cast<const uint4*>(
                    Bg + (size_t)(k0 + kk) * N_HID + ff);
                *reinterpret_cast<uint4*>(Bs + kk * SB + ff) = v;
            }
            __syncthreads();
#pragma unroll
            for (int ks = 0; ks < 4; ks++) {
                int kb = ks * 16;
                uint32_t afr[2][4];
#pragma unroll
                for (int mm = 0; mm < 2; mm++) {
                    uint32_t addr = sa_base +
                        (uint32_t)((wm * 32 + mm * 16 + idx15) * SA + kb + hi8) * 2u;
                    ldmat_x4(afr[mm], addr);
                }
                uint32_t bfr[4][2];
#pragma unroll
                for (int bp = 0; bp < 2; bp++) {
                    uint32_t bt[4];
                    uint32_t addr = sb_base +
                        (uint32_t)((kb + idx15) * SB + wn * 32 + bp * 16 + hi8) * 2u;
                    ldmat_x4_t(bt, addr);
                    bfr[bp * 2][0] = bt[0]; bfr[bp * 2][1] = bt[1];
                    bfr[bp * 2 + 1][0] = bt[2]; bfr[bp * 2 + 1][1] = bt[3];
                }
#pragma unroll
                for (int mm = 0; mm < 2; mm++)
#pragma unroll
                    for (int nn = 0; nn < 4; nn++)
                        mma16816(acc[mm][nn], afr[mm], bfr[nn]);
            }
        }
    }
#pragma unroll
    for (int mm = 0; mm < 2; mm++)
#pragma unroll
        for (int nn = 0; nn < 4; nn++) {
            int r = row0 + wm * 32 + mm * 16 + lr;
            int c = wn * 32 + nn * 8 + lc * 2;
            float* o = h1 + ((size_t)h * N_ROWS + r) * N_HID + c;
            *reinterpret_cast<float2*>(o) = make_float2(acc[mm][nn][0], acc[mm][nn][1]);
            *reinterpret_cast<float2*>(o + 8 * N_HID) = make_float2(acc[mm][nn][2], acc[mm][nn][3]);
        }

    const float* a = ah + (size_t)h * 2 * N_HID;
#pragma unroll
    for (int mm = 0; mm < 2; mm++) {
        float ps1 = 0.f, pd1 = 0.f, ps2 = 0.f, pd2 = 0.f;
#pragma unroll
        for (int nn = 0; nn < 4; nn++) {
            int c0 = wn * 32 + nn * 8 + lc * 2;
            float a0s = a[c0], a1s = a[c0 + 1];
            float a0d = a[N_HID + c0], a1d = a[N_HID + c0 + 1];
            ps1 += acc[mm][nn][0] * a0s + acc[mm][nn][1] * a1s;
            pd1 += acc[mm][nn][0] * a0d + acc[mm][nn][1] * a1d;
            ps2 += acc[mm][nn][2] * a0s + acc[mm][nn][3] * a1s;
            pd2 += acc[mm][nn][2] * a0d + acc[mm][nn][3] * a1d;
        }
#pragma unroll
        for (int off = 1; off <= 2; off <<= 1) {
            ps1 += __shfl_xor_sync(0xffffffffu, ps1, off);
            pd1 += __shfl_xor_sync(0xffffffffu, pd1, off);
            ps2 += __shfl_xor_sync(0xffffffffu, ps2, off);
            pd2 += __shfl_xor_sync(0xffffffffu, pd2, off);
        }
        if (lc == 0) {
            int rl = wm * 32 + mm * 16 + lr;
            sred[wn][0][rl] = ps1; sred[wn][1][rl] = pd1;
            sred[wn][0][rl + 8] = ps2; sred[wn][1][rl + 8] = pd2;
        }
    }
    __syncthreads();
    if (tid < BM) {
        int gi = h * N_ROWS + row0 + tid;
        ssrc[gi] = sred[0][0][tid] + sred[1][0][tid];
        sdst[gi] = sred[0][1][tid] + sred[1][1][tid];
    }
}

// ---------------- megaL1: sortscan1 + featA1 + featC1 + combine1 ----------------
__global__ __launch_bounds__(1024, 1) void megaL1_kernel(
    const float* __restrict__ sdst, float* __restrict__ sorted, int* __restrict__ idx,
    float* __restrict__ ew, float* __restrict__ gw,
    float* __restrict__ Zhi, float* __restrict__ Zlo,
    const float* __restrict__ h1, float* __restrict__ Chi, float* __restrict__ Clo,
    float* __restrict__ Phi, float* __restrict__ Plo,
    const float* __restrict__ ssrc, float* __restrict__ xc)
{
    __shared__ __align__(16) unsigned char sm[33792];
    int blk = blockIdx.x, t = threadIdx.x;

    if (blk < N_HEADS) {
        sortscan_body(blk, sdst, sorted, idx, ew, gw, Zhi, Zlo,
                      (float*)sm, (int*)(sm + 16384), (float*)(sm + 32768));
    }
    gbar();

    int h = blk >> 4, chunk = blk & 15;

    // ---- Phase A ----
    {
        int* sidx = (int*)sm;
        float* sew = (float*)(sm + 1024);
        float* sgw = (float*)(sm + 2048);
        float (*sH)[N_HID] = (float(*)[N_HID])(sm + 3072);
        float (*sL)[N_HID] = (float(*)[N_HID])(sm + 7168);
        int ft = t & 63, rg = t >> 6;
        if (t < 256) {
            int base = h * N_ROWS + chunk * 256 + t;
            sidx[t] = idx[base]; sew[t] = ew[base]; sgw[t] = gw[base];
        }
        __syncthreads();
        const float* hb = h1 + (size_t)h * N_ROWS * N_HID + ft;
        float sh_ = 0.f, sl_ = 0.f;
#pragma unroll
        for (int j = 0; j < 16; j++) {
            int rl = rg * 16 + j;
            float v = hb[(size_t)sidx[rl] * N_HID];
            sh_ += v * sew[rl];
            sl_ += v * sgw[rl];
        }
        sH[rg][ft] = sh_; sL[rg][ft] = sl_;
        __syncthreads();
        if (rg == 0) {
            float a = 0.f, b = 0.f;
#pragma unroll
            for (int r = 0; r < 16; r++) { a += sH[r][ft]; b += sL[r][ft]; }
            Chi[(h * N_HID + ft) * 16 + chunk] = a;
            Clo[(h * N_HID + ft) * 16 + chunk] = b;
        }
    }
    gbar();

    // ---- Phase C ----
    {
        int* sidx = (int*)sm;
        float* sew = (float*)(sm + 1024);
        float* sgw = (float*)(sm + 2048);
        float* sChi = (float*)(sm + 3072);
        float* sClo = (float*)(sm + 7168);
        float (*sH)[N_HID] = (float(*)[N_HID])(sm + 11264);
        float (*sL)[N_HID] = (float(*)[N_HID])(sm + 15360);
        int ft = t & 63, rg = t >> 6;
        if (t < 256) {
            int base = h * N_ROWS + chunk * 256 + t;
            sidx[t] = idx[base]; sew[t] = ew[base]; sgw[t] = gw[base];
        }
        sChi[t] = Chi[h * N_HID * 16 + t];
        sClo[t] = Clo[h * N_HID * 16 + t];
        __syncthreads();
        const float* hb = h1 + (size_t)h * N_ROWS * N_HID + ft;
        float vh[16], vl[16];
        float sh_ = 0.f, sl_ = 0.f;
#pragma unroll
        for (int j = 0; j < 16; j++) {
            int rl = rg * 16 + j;
            float v = hb[(size_t)sidx[rl] * N_HID];
            vh[j] = v * sew[rl];
            vl[j] = v * sgw[rl];
            sh_ += vh[j]; sl_ += vl[j];
        }
        sH[rg][ft] = sh_; sL[rg][ft] = sl_;
        __syncthreads();
        float offh = 0.f, offl = 0.f, totl = 0.f;
#pragma unroll
        for (int c = 0; c < 16; c++) {
            float a = sChi[ft * 16 + c], b = sClo[ft * 16 + c];
            if (c < chunk) { offh += a; offl += b; }
            totl += b;
        }
        for (int r = 0; r < rg; r++) { offh += sH[r][ft]; offl += sL[r][ft]; }
        float* PH = Phi + (size_t)h * KR * N_HID + ft;
        float* PL = Plo + (size_t)h * KR * N_HID + ft;
        float runh = offh, runl = offl;
        int k0 = chunk * 256 + rg * 16;
#pragma unroll
        for (int j = 0; j < 16; j++) {
            PH[(size_t)(k0 + j) * N_HID] = runh;
            PL[(size_t)(k0 + j) * N_HID] = totl - runl;
            runh += vh[j];
            runl += vl[j];
        }
        if (chunk == 15 && rg == 15) {
            PH[(size_t)N_ROWS * N_HID] = runh;
            PL[(size_t)N_ROWS * N_HID] = totl - runl;
        }
    }
    gbar();

    // ---- Phase B: combine1 ----
    {
        float* ss = (float*)sm;
        const float* sb = sorted + (size_t)h * N_ROWS;
        *reinterpret_cast<float4*>(ss + t * 4) = *reinterpret_cast<const float4*>(sb + t * 4);
        __syncthreads();
        int warp = t >> 5, lane = t & 31;
        float M = ss[0];
        const float* ZH = Zhi + (size_t)h * PS;
        const float* ZL = Zlo + (size_t)h * PS;
        const float* PHb = Phi + (size_t)h * KR * N_HID;
        const float* PLb = Plo + (size_t)h * KR * N_HID;
        int i0 = chunk * 256;
#pragma unroll
        for (int rr = 0; rr < 8; rr++) {
            int i = i0 + warp * 8 + rr;
            float s = ssrc[(size_t)h * N_ROWS + i];
            float thr = -s;
            int lo = 0, hi = N_ROWS;
            while (lo < hi) {
                int mid = (lo + hi) >> 1;
                if (ss[mid] >= thr) lo = mid + 1; else hi = mid;
            }
            int k = lo;
            float rho = expf(-0.8f * (s + M));
            float den = (k == 0) ? ZL[0] : (ZH[k] + rho * ZL[k]);
            float inv = 1.f / den;
            const float* ph = PHb + (size_t)k * N_HID;
            const float* pl = PLb + (size_t)k * N_HID;
#pragma unroll
            for (int u = 0; u < 2; u++) {
                int f = lane + 32 * u;
                float num = (k == 0) ? pl[f] : (ph[f] + rho * pl[f]);
                float feat = num * inv;
                float v = feat > 0.f ? feat : expm1f(feat);
                xc[(size_t)i * N_FEAT + h * N_HID + f] = v;
            }
        }
    }
}

// ---------------- megaL2 ----------------
__global__ __launch_bounds__(1024, 1) void megaL2_kernel(
    const float* __restrict__ xc, const float* __restrict__ Wo, const float* __restrict__ ao,
    float* __restrict__ h2, float* __restrict__ ssrc, float* __restrict__ sdst,
    float* __restrict__ sorted, int* __restrict__ idx,
    float* __restrict__ ew, float* __restrict__ gw,
    float* __restrict__ Zhi, float* __restrict__ Zlo,
    float* __restrict__ Chi, float* __restrict__ Clo,
    float* __restrict__ Phi, float* __restrict__ Plo,
    float* __restrict__ out)
{
    __shared__ __align__(16) unsigned char sm[33792];
    int blk = blockIdx.x, t = threadIdx.x;

    // ---- Phase G: gemm2 + fused scores2 ----
    {
        float (*xs)[64] = (float(*)[64])sm;
        float (*ws)[16] = (float(*)[16])(sm + 8192);
        int row0 = blk * 32;
        int ir = t >> 4, fc = t & 15;
        float acc = 0.f;
        for (int k0 = 0; k0 < N_FEAT; k0 += 64) {
            __syncthreads();
#pragma unroll
            for (int rep = 0; rep < 2; rep++) {
                int t2 = t + rep * 1024;
                int r = t2 >> 6, kk = t2 & 63;
                xs[r][kk] = xc[(size_t)(row0 + r) * N_FEAT + k0 + kk];
            }
            {
                int kk = t >> 4, f = t & 15;
                if (kk < 64) ws[kk][f] = Wo[(size_t)(k0 + kk) * N_CLASS + f];
            }
            __syncthreads();
            if (t < 512) {
#pragma unroll
                for (int kk = 0; kk < 64; kk++) acc += xs[ir][kk] * ws[kk][fc];
            }
        }
        if (t < 512) {
            h2[(size_t)(row0 + ir) * N_CLASS + fc] = acc;
            float ps = acc * ao[fc];
            float pd = acc * ao[N_CLASS + fc];
#pragma unroll
            for (int off = 1; off < 16; off <<= 1) {
                ps += __shfl_xor_sync(0xffffffffu, ps, off);
                pd += __shfl_xor_sync(0xffffffffu, pd, off);
            }
            if (fc == 0) {
                ssrc[row0 + ir] = ps;
                sdst[row0 + ir] = pd;
            }
        }
    }
    gbar();

    if (blk == 0) {
        sortscan_body(0, sdst, sorted, idx, ew, gw, Zhi, Zlo,
                      (float*)sm, (int*)(sm + 16384), (float*)(sm + 32768));
    }
    gbar();

    // ---- Phase A2 ----
    if (blk < 16) {
        int chunk = blk;
        int* sidx = (int*)sm;
        float* sew = (float*)(sm + 1024);
        float* sgw = (float*)(sm + 2048);
        float (*sH)[N_CLASS] = (float(*)[N_CLASS])(sm + 3072);
        float (*sL)[N_CLASS] = (float(*)[N_CLASS])(sm + 7168);
        if (t < 256) {
            int base = chunk * 256 + t;
            sidx[t] = idx[base]; sew[t] = ew[base]; sgw[t] = gw[base];
        }
        __syncthreads();
        int ft = t & 15, rg = t >> 4;
        const float* hb = h2 + ft;
        float a = 0.f, b = 0.f;
#pragma unroll
        for (int j = 0; j < 4; j++) {
            int rl = rg * 4 + j;
            float v = hb[(size_t)sidx[rl] * N_CLASS];
            a += v * sew[rl];
            b += v * sgw[rl];
        }
        sH[rg][ft] = a; sL[rg][ft] = b;
        __syncthreads();
        if (t < 16) {
            float sa = 0.f, sb = 0.f;
#pragma unroll
            for (int r = 0; r < 64; r++) { sa += sH[r][t]; sb += sL[r][t]; }
            Chi[t * 16 + chunk] = sa;
            Clo[t * 16 + chunk] = sb;
        }
    }
    gbar();

    // ---- Phase C2 ----
    if (blk < 16) {
        int chunk = blk;
        int* sidx = (int*)sm;
        float* sew = (float*)(sm + 1024);
        float* sgw = (float*)(sm + 2048);
        float (*sH)[N_CLASS] = (float(*)[N_CLASS])(sm + 3072);
        float (*sL)[N_CLASS] = (float(*)[N_CLASS])(sm + 7168);
        float* sChi = (float*)(sm + 11264);
        float* sClo = (float*)(sm + 12288);
        if (t < 256) {
            int base = chunk * 256 + t;
            sidx[t] = idx[base]; sew[t] = ew[base]; sgw[t] = gw[base];
            sChi[t] = Chi[t]; sClo[t] = Clo[t];
        }
        __syncthreads();
        int ft = t & 15, rg = t >> 4;
        const float* hb = h2 + ft;
        float vh[4], vl[4];
        float a = 0.f, b = 0.f;
#pragma unroll
        for (int j = 0; j < 4; j++) {
            int rl = rg * 4 + j;
            float v = hb[(size_t)sidx[rl] * N_CLASS];
            vh[j] = v * sew[rl];
            vl[j] = v * sgw[rl];
            a += vh[j]; b += vl[j];
        }
        sH[rg][ft] = a; sL[rg][ft] = b;
        __syncthreads();
        float offh = 0.f, offl = 0.f, totl = 0.f;
#pragma unroll
        for (int c = 0; c < 16; c++) {
            float ca = sChi[ft * 16 + c], cb = sClo[ft * 16 + c];
            if (c < chunk) { offh += ca; offl += cb; }
            totl += cb;
        }
        for (int r = 0; r < rg; r++) { offh += sH[r][ft]; offl += sL[r][ft]; }
        float runh = offh, runl = offl;
        int k0 = chunk * 256 + rg * 4;
#pragma unroll
        for (int j = 0; j < 4; j++) {
            Phi[(size_t)(k0 + j) * N_CLASS + ft] = runh;
            Plo[(size_t)(k0 + j) * N_CLASS + ft] = totl - runl;
            runh += vh[j];
            runl += vl[j];
        }
        if (chunk == 15 && rg == 63) {
            Phi[(size_t)N_ROWS * N_CLASS + ft] = runh;
            Plo[(size_t)N_ROWS * N_CLASS + ft] = totl - runl;
        }
    }
    gbar();

    // ---- Phase B2 ----
    if (blk < 64) {
        float* ss = (float*)sm;
        *reinterpret_cast<float4*>(ss + t * 4) = *reinterpret_cast<const float4*>(sorted + t * 4);
        __syncthreads();
        int f = t & 15, il = t >> 4;
        int i = blk * 64 + il;
        float M = ss[0];
        float s = ssrc[i];
        float thr = -s;
        int lo = 0, hi = N_ROWS;
        while (lo < hi) {
            int mid = (lo + hi) >> 1;
            if (ss[mid] >= thr) lo = mid + 1; else hi = mid;
        }
        int k = lo;
        float rho = expf(-0.8f * (s + M));
        float den = (k == 0) ? Zlo[0] : (Zhi[k] + rho * Zlo[k]);
        float num = (k == 0) ? Plo[f]
                             : (Phi[(size_t)k * N_CLASS + f] + rho * Plo[(size_t)k * N_CLASS + f]);
        float feat = num / den;
        float v = feat > 0.f ? feat : expm1f(feat);
        float m = v;
#pragma unroll
        for (int off = 8; off; off >>= 1) m = fmaxf(m, __shfl_xor_sync(0xffffffffu, m, off));
        float ex = expf(v - m);
        float ssum = ex;
#pragma unroll
        for (int off = 8; off; off >>= 1) ssum += __shfl_xor_sync(0xffffffffu, ssum, off);
        out[(size_t)i * N_CLASS + f] = v - m - logf(ssum);
    }
}

// ---------------- launch ----------------
extern "C" void kernel_launch(void* const* d_in, const int* in_sizes, int n_in,
                              void* d_out, int out_size)
{
    const float* x  = (const float*)d_in[0];
    const float* Wh = (const float*)d_in[1];
    const float* ah = (const float*)d_in[2];
    const float* Wo = (const float*)d_in[3];
    const float* ao = (const float*)d_in[4];
    float* out = (float*)d_out;

    __nv_bfloat16 *p_xh, *p_xl, *p_whh, *p_whl;
    float *p_h1, *p_ssrc1, *p_sdst1, *p_sorted1, *p_ew1, *p_gw1, *p_Zhi1, *p_Zlo1;
    float *p_Chi1, *p_Clo1, *p_Phi1, *p_Plo1, *p_xc;
    int *p_idx1;
    float *p_h2, *p_ssrc2, *p_sdst2, *p_sorted2, *p_ew2, *p_gw2, *p_Zhi2, *p_Zlo2;
    float *p_Chi2, *p_Clo2, *p_Phi2, *p_Plo2;
    int *p_idx2;

    cudaGetSymbolAddress((void**)&p_xh, g_xh);
    cudaGetSymbolAddress((void**)&p_xl, g_xl);
    cudaGetSymbolAddress((void**)&p_whh, g_whh);
    cudaGetSymbolAddress((void**)&p_whl, g_whl);
    cudaGetSymbolAddress((void**)&p_h1, g_h1);
    cudaGetSymbolAddress((void**)&p_ssrc1, g_ssrc1);
    cudaGetSymbolAddress((void**)&p_sdst1, g_sdst1);
    cudaGetSymbolAddress((void**)&p_sorted1, g_sorted1);
    cudaGetSymbolAddress((void**)&p_idx1, g_idx1);
    cudaGetSymbolAddress((void**)&p_ew1, g_ew1);
    cudaGetSymbolAddress((void**)&p_gw1, g_gw1);
    cudaGetSymbolAddress((void**)&p_Zhi1, g_Zhi1);
    cudaGetSymbolAddress((void**)&p_Zlo1, g_Zlo1);
    cudaGetSymbolAddress((void**)&p_Chi1, g_Chi1);
    cudaGetSymbolAddress((void**)&p_Clo1, g_Clo1);
    cudaGetSymbolAddress((void**)&p_Phi1, g_Phi1);
    cudaGetSymbolAddress((void**)&p_Plo1, g_Plo1);
    cudaGetSymbolAddress((void**)&p_xc, g_xc);
    cudaGetSymbolAddress((void**)&p_h2, g_h2);
    cudaGetSymbolAddress((void**)&p_ssrc2, g_ssrc2);
    cudaGetSymbolAddress((void**)&p_sdst2, g_sdst2);
    cudaGetSymbolAddress((void**)&p_sorted2, g_sorted2);
    cudaGetSymbolAddress((void**)&p_idx2, g_idx2);
    cudaGetSymbolAddress((void**)&p_ew2, g_ew2);
    cudaGetSymbolAddress((void**)&p_gw2, g_gw2);
    cudaGetSymbolAddress((void**)&p_Zhi2, g_Zhi2);
    cudaGetSymbolAddress((void**)&p_Zlo2, g_Zlo2);
    cudaGetSymbolAddress((void**)&p_Chi2, g_Chi2);
    cudaGetSymbolAddress((void**)&p_Clo2, g_Clo2);
    cudaGetSymbolAddress((void**)&p_Phi2, g_Phi2);
    cudaGetSymbolAddress((void**)&p_Plo2, g_Plo2);

    splitall_kernel<<<(NX4 + NW4 + 255) / 256, 256>>>(x, Wh, p_xh, p_xl, p_whh, p_whl);
    gemm1_mma_kernel<<<dim3(N_ROWS / 128, N_HEADS), 256>>>(p_xh, p_xl, p_whh, p_whl, ah,
                                                           p_h1, p_ssrc1, p_sdst1);
    megaL1_kernel<<<NB, 1024>>>(p_sdst1, p_sorted1, p_idx1, p_ew1, p_gw1, p_Zhi1, p_Zlo1,
                                p_h1, p_Chi1, p_Clo1, p_Phi1, p_Plo1, p_ssrc1, p_xc);
    megaL2_kernel<<<NB, 1024>>>(p_xc, Wo, ao, p_h2, p_ssrc2, p_sdst2,
                                p_sorted2, p_idx2, p_ew2, p_gw2, p_Zhi2, p_Zlo2,
                                p_Chi2, p_Clo2, p_Phi2, p_Plo2, out);

    (void)in_sizes; (void)n_in; (void)out_size;
}

// round 12
// speedup vs baseline: 2.1567x; 1.3491x over previous
#include <cuda_runtime.h>
#include <cuda_bf16.h>
#include <cstdint>

#define N_ROWS   4096
#define N_FEAT   512
#define N_HID    64
#define N_CLASS  16
#define N_HEADS  8
#define PS       (N_ROWS + 4)
#define KR       (N_ROWS + 1)
#define NB       128            // mega-kernel grid size (all-resident)

// ---------------- scratch ----------------
__device__ __nv_bfloat16 g_xh [N_ROWS*N_FEAT];
__device__ __nv_bfloat16 g_xl [N_ROWS*N_FEAT];
__device__ __nv_bfloat16 g_whh[N_HEADS*N_FEAT*N_HID];
__device__ __nv_bfloat16 g_whl[N_HEADS*N_FEAT*N_HID];

__device__ float g_h1   [N_HEADS*N_ROWS*N_HID];
__device__ float g_ssrc1[N_HEADS*N_ROWS];
__device__ float g_sdst1[N_HEADS*N_ROWS];
__device__ float g_csort1[N_HEADS*N_ROWS];
__device__ float g_sorted1[N_HEADS*N_ROWS];
__device__ int   g_idx1 [N_HEADS*N_ROWS];
__device__ float g_ew1  [N_HEADS*N_ROWS];
__device__ float g_gw1  [N_HEADS*N_ROWS];
__device__ float g_Zhi1 [N_HEADS*PS];
__device__ float g_Zlo1 [N_HEADS*PS];
__device__ float g_Chi1 [N_HEADS*N_HID*16];
__device__ float g_Clo1 [N_HEADS*N_HID*16];
__device__ float g_Phi1 [N_HEADS*KR*N_HID];
__device__ float g_Plo1 [N_HEADS*KR*N_HID];
__device__ float g_xc   [N_ROWS*N_FEAT];

__device__ float g_h2   [N_ROWS*N_CLASS];
__device__ float g_ssrc2[N_ROWS];
__device__ float g_sdst2[N_ROWS];
__device__ float g_csort2[N_ROWS];
__device__ float g_sorted2[N_ROWS];
__device__ int   g_idx2 [N_ROWS];
__device__ float g_ew2  [N_ROWS];
__device__ float g_gw2  [N_ROWS];
__device__ float g_Zhi2 [PS];
__device__ float g_Zlo2 [PS];
__device__ float g_Chi2 [N_CLASS*16];
__device__ float g_Clo2 [N_CLASS*16];
__device__ float g_Phi2 [KR*N_CLASS];
__device__ float g_Plo2 [KR*N_CLASS];

// ---------------- device-wide software barrier ----------------
__device__ unsigned g_cnt;
__device__ volatile unsigned g_gen;

__device__ __forceinline__ void gbar() {
    __syncthreads();
    if (threadIdx.x == 0) {
        __threadfence();
        unsigned old = g_gen;
        if (atomicAdd(&g_cnt, 1u) == NB - 1) {
            g_cnt = 0;
            __threadfence();
            g_gen = old + 1;
        } else {
            while (g_gen == old) { __nanosleep(64); }
            __threadfence();
        }
    }
    __syncthreads();
}

// ---------------- warp-shuffle block exclusive scan (1024 thr) ----------------
__device__ __forceinline__ float blk_exscan32(float v, float* sh, float& total) {
    __syncthreads();
    int lane = threadIdx.x & 31, warp = threadIdx.x >> 5;
    float x = v;
#pragma unroll
    for (int off = 1; off < 32; off <<= 1) {
        float n = __shfl_up_sync(0xffffffffu, x, off);
        if (lane >= off) x += n;
    }
    if (lane == 31) sh[warp] = x;
    __syncthreads();
    if (warp == 0) {
        float w = sh[lane];
#pragma unroll
        for (int off = 1; off < 32; off <<= 1) {
            float n = __shfl_up_sync(0xffffffffu, w, off);
            if (lane >= off) w += n;
        }
        sh[lane] = w;
    }
    __syncthreads();
    float base = warp ? sh[warp - 1] : 0.f;
    total = sh[31];
    return base + x - v;
}

// ---------------- S_a: sort one 512-chunk (descending), 1 elem/thread ----------------
__device__ void sortchunk_body(int h, int c, const float* __restrict__ sdst,
                               float* __restrict__ csort, float* sk)
{
    int tid = threadIdx.x;
    float key = 0.f;
    if (tid < 512) key = sdst[(size_t)h * N_ROWS + c * 512 + tid];
    for (int k = 2; k <= 512; k <<= 1) {
        for (int j = k >> 1; j > 0; j >>= 1) {
            if (j >= 32) {
                __syncthreads();
                if (tid < 512) sk[tid] = key;
                __syncthreads();
                if (tid < 512) {
                    float ok = sk[tid ^ j];
                    bool lower = (tid & j) == 0;
                    bool desc = ((tid & k & 511) == 0);
                    float a = lower ? key : ok, b = lower ? ok : key;
                    if (desc ? (a < b) : (a > b)) key = ok;
                }
            } else {
                if (tid < 512) {
                    float ok = __shfl_xor_sync(0xffffffffu, key, j);
                    bool lower = (tid & j) == 0;
                    bool desc = ((tid & k & 511) == 0);
                    float a = lower ? key : ok, b = lower ? ok : key;
                    if (desc ? (a < b) : (a > b)) key = ok;
                }
            }
        }
    }
    __syncthreads();
    if (tid < 512) csort[(size_t)h * N_ROWS + c * 512 + tid] = key;
}

// ---------------- S_b: rank own chunk + scatter sorted + idx recovery ----------------
// smem: skeys = 4096 floats (16KB), grank = 512 ints (rank low16, tie counter high16)
__device__ void rank_body(int h, int c, const float* __restrict__ sdst,
                          const float* __restrict__ csort,
                          float* __restrict__ sorted, int* __restrict__ idx,
                          float* skeys, int* grank)
{
    int tid = threadIdx.x;
#pragma unroll
    for (int i = 0; i < 4; i++) skeys[tid + i * 1024] = csort[(size_t)h * N_ROWS + tid + i * 1024];
    __syncthreads();
    if (tid < 512) {
        float x = skeys[c * 512 + tid];
        int r = tid;
#pragma unroll
        for (int cc = 0; cc < 8; cc++) {
            if (cc == c) continue;
            const float* S = skeys + cc * 512;
            int lo = 0, hi = 512;
            if (cc < c) {
                while (lo < hi) { int mid = (lo + hi) >> 1; if (S[mid] >= x) lo = mid + 1; else hi = mid; }
            } else {
                while (lo < hi) { int mid = (lo + hi) >> 1; if (S[mid] > x) lo = mid + 1; else hi = mid; }
            }
            r += lo;
        }
        grank[tid] = r;
        sorted[(size_t)h * N_ROWS + r] = x;
    }
    __syncthreads();
    if (tid < 512) {
        int j = c * 512 + tid;
        float x = sdst[(size_t)h * N_ROWS + j];
        const float* S = skeys + c * 512;
        int lo = 0, hi = 512;
        while (lo < hi) { int mid = (lo + hi) >> 1; if (S[mid] > x) lo = mid + 1; else hi = mid; }
        int off = atomicAdd(&grank[lo], 0x10000) >> 16;
        int rank = grank[lo + off] & 0xFFFF;
        idx[(size_t)h * N_ROWS + rank] = j;
    }
    __syncthreads();
}

// ---------------- S_c: scalar scan on sorted order ----------------
__device__ void scan_body(int h, const float* __restrict__ sorted,
                          float* __restrict__ ew, float* __restrict__ gw,
                          float* __restrict__ Zhi, float* __restrict__ Zlo, float* sh)
{
    int tid = threadIdx.x;
    float key[4];
    float4 v4 = *reinterpret_cast<const float4*>(sorted + (size_t)h * N_ROWS + tid * 4);
    key[0] = v4.x; key[1] = v4.y; key[2] = v4.z; key[3] = v4.w;
    if (tid == 0) sh[36] = key[0];
    __syncthreads();
    float M = sh[36];

    float e4[4], g4[4];
    float se = 0.f, sg = 0.f;
#pragma unroll
    for (int q = 0; q < 4; q++) {
        float xv = key[q] - M;
        e4[q] = expf(xv);
        g4[q] = expf(0.2f * xv);
        se += e4[q]; sg += g4[q];
    }
    *reinterpret_cast<float4*>(ew + (size_t)h * N_ROWS + tid * 4) =
        make_float4(e4[0], e4[1], e4[2], e4[3]);
    *reinterpret_cast<float4*>(gw + (size_t)h * N_ROWS + tid * 4) =
        make_float4(g4[0], g4[1], g4[2], g4[3]);

    float tote, totg;
    float pe = blk_exscan32(se, sh, tote);
    float pg = blk_exscan32(sg, sh, totg);

    float* ZH = Zhi + (size_t)h * PS;
    float* ZL = Zlo + (size_t)h * PS;
    float run = pe;
#pragma unroll
    for (int q = 0; q < 4; q++) { ZH[tid * 4 + q] = run; run += e4[q]; }
    float run2 = pg;
#pragma unroll
    for (int q = 0; q < 4; q++) { ZL[tid * 4 + q] = totg - run2; run2 += g4[q]; }
    if (tid == 1023) { ZH[N_ROWS] = run; ZL[N_ROWS] = 0.f; }
}

// ---------------- combined split fp32 -> bf16 hi/lo ----------------
#define NX4  (N_ROWS * N_FEAT / 4)
#define NW4  (N_HEADS * N_FEAT * N_HID / 4)
__global__ void splitall_kernel(const float* __restrict__ x, const float* __restrict__ Wh,
                                __nv_bfloat16* __restrict__ xh, __nv_bfloat16* __restrict__ xl,
                                __nv_bfloat16* __restrict__ whh, __nv_bfloat16* __restrict__ whl)
{
    int i = blockIdx.x * blockDim.x + threadIdx.x;
    const float* src; __nv_bfloat16 *hi, *lo; int j;
    if (i < NX4) { src = x; hi = xh; lo = xl; j = i; }
    else         { src = Wh; hi = whh; lo = whl; j = i - NX4; if (j >= NW4) return; }
    float4 v = reinterpret_cast<const float4*>(src)[j];
    __nv_bfloat16 h0 = __float2bfloat16_rn(v.x);
    __nv_bfloat16 h1 = __float2bfloat16_rn(v.y);
    __nv_bfloat16 h2 = __float2bfloat16_rn(v.z);
    __nv_bfloat16 h3 = __float2bfloat16_rn(v.w);
    __nv_bfloat16 l0 = __float2bfloat16_rn(v.x - __bfloat162float(h0));
    __nv_bfloat16 l1 = __float2bfloat16_rn(v.y - __bfloat162float(h1));
    __nv_bfloat16 l2 = __float2bfloat16_rn(v.z - __bfloat162float(h2));
    __nv_bfloat16 l3 = __float2bfloat16_rn(v.w - __bfloat162float(h3));
    __nv_bfloat162* hp = reinterpret_cast<__nv_bfloat162*>(hi) + j * 2;
    __nv_bfloat162* lp = reinterpret_cast<__nv_bfloat162*>(lo) + j * 2;
    hp[0] = __nv_bfloat162(h0, h1); hp[1] = __nv_bfloat162(h2, h3);
    lp[0] = __nv_bfloat162(l0, l1); lp[1] = __nv_bfloat162(l2, l3);
}

// ---------------- GEMM1 (bf16 mma + ldmatrix + fused scores) ----------------
__device__ __forceinline__ void mma16816(float* c, const uint32_t* a, const uint32_t* b) {
    asm volatile(
        "mma.sync.aligned.m16n8k16.row.col.f32.bf16.bf16.f32 "
        "{%0,%1,%2,%3}, {%4,%5,%6,%7}, {%8,%9}, {%0,%1,%2,%3};\n"
        : "+f"(c[0]), "+f"(c[1]), "+f"(c[2]), "+f"(c[3])
        : "r"(a[0]), "r"(a[1]), "r"(a[2]), "r"(a[3]), "r"(b[0]), "r"(b[1]));
}
__device__ __forceinline__ void ldmat_x4(uint32_t* r, uint32_t addr) {
    asm volatile("ldmatrix.sync.aligned.m8n8.x4.shared.b16 {%0,%1,%2,%3}, [%4];"
        : "=r"(r[0]), "=r"(r[1]), "=r"(r[2]), "=r"(r[3]) : "r"(addr));
}
__device__ __forceinline__ void ldmat_x4_t(uint32_t* r, uint32_t addr) {
    asm volatile("ldmatrix.sync.aligned.m8n8.x4.trans.shared.b16 {%0,%1,%2,%3}, [%4];"
        : "=r"(r[0]), "=r"(r[1]), "=r"(r[2]), "=r"(r[3]) : "r"(addr));
}

__global__ __launch_bounds__(256) void gemm1_mma_kernel(
    const __nv_bfloat16* __restrict__ xh, const __nv_bfloat16* __restrict__ xl,
    const __nv_bfloat16* __restrict__ whh, const __nv_bfloat16* __restrict__ whl,
    const float* __restrict__ ah,
    float* __restrict__ h1, float* __restrict__ ssrc, float* __restrict__ sdst)
{
    const int BM = 128, BKT = 64, SA = 72, SB = 72;
    __shared__ __nv_bfloat16 As[BM * SA];
    __shared__ __nv_bfloat16 Bs[BKT * SB];
    __shared__ float sred[2][2][BM];
    int h = blockIdx.y;
    int row0 = blockIdx.x * BM;
    int tid = threadIdx.x;
    int wid = tid >> 5, lane = tid & 31;
    int wm = wid & 3, wn = wid >> 2;
    int lr = lane >> 2, lc = lane & 3;
    int idx15 = lane & 15, hi8 = (lane >> 4) << 3;

    uint32_t sa_base = (uint32_t)__cvta_generic_to_shared(As);
    uint32_t sb_base = (uint32_t)__cvta_generic_to_shared(Bs);

    const __nv_bfloat16* Wb0 = whh + (size_t)h * N_FEAT * N_HID;
    const __nv_bfloat16* Wb1 = whl + (size_t)h * N_FEAT * N_HID;
    const __nv_bfloat16* Aph[3] = { xh, xl, xh };
    const __nv_bfloat16* Bph[3] = { Wb0, Wb0, Wb1 };

    float acc[2][4][4];
#pragma unroll
    for (int mm = 0; mm < 2; mm++)
#pragma unroll
        for (int nn = 0; nn < 4; nn++)
#pragma unroll
            for (int q = 0; q < 4; q++) acc[mm][nn][q] = 0.f;

    for (int p = 0; p < 3; p++) {
        const __nv_bfloat16* Ag = Aph[p];
        const __nv_bfloat16* Bg = Bph[p];
        for (int k0 = 0; k0 < N_FEAT; k0 += BKT) {
            __syncthreads();
#pragma unroll
            for (int i = 0; i < 4; i++) {
                int id4 = tid + i * 256;
                int r = id4 >> 3, kk = (id4 & 7) * 8;
                uint4 v = *reinterpret_cast<const uint4*>(
                    Ag + (size_t)(row0 + r) * N_FEAT + k0 + kk);
                *reinterpret_cast<uint4*>(As + r * SA + kk) = v;
            }
#pragma unroll
            for (int i = 0; i < 2; i++) {
                int id4 = tid + i * 256;
                int kk = id4 >> 3, ff = (id4 & 7) * 8;
                uint4 v = *reinterpret_cast<const uint4*>(
                    Bg + (size_t)(k0 + kk) * N_HID + ff);
                *reinterpret_cast<uint4*>(Bs + kk * SB + ff) = v;
            }
            __syncthreads();
#pragma unroll
            for (int ks = 0; ks < 4; ks++) {
                int kb = ks * 16;
                uint32_t afr[2][4];
#pragma unroll
                for (int mm = 0; mm < 2; mm++) {
                    uint32_t addr = sa_base +
                        (uint32_t)((wm * 32 + mm * 16 + idx15) * SA + kb + hi8) * 2u;
                    ldmat_x4(afr[mm], addr);
                }
                uint32_t bfr[4][2];
#pragma unroll
                for (int bp = 0; bp < 2; bp++) {
                    uint32_t bt[4];
                    uint32_t addr = sb_base +
                        (uint32_t)((kb + idx15) * SB + wn * 32 + bp * 16 + hi8) * 2u;
                    ldmat_x4_t(bt, addr);
                    bfr[bp * 2][0] = bt[0]; bfr[bp * 2][1] = bt[1];
                    bfr[bp * 2 + 1][0] = bt[2]; bfr[bp * 2 + 1][1] = bt[3];
                }
#pragma unroll
                for (int mm = 0; mm < 2; mm++)
#pragma unroll
                    for (int nn = 0; nn < 4; nn++)
                        mma16816(acc[mm][nn], afr[mm], bfr[nn]);
            }
        }
    }
#pragma unroll
    for (int mm = 0; mm < 2; mm++)
#pragma unroll
        for (int nn = 0; nn < 4; nn++) {
            int r = row0 + wm * 32 + mm * 16 + lr;
            int c = wn * 32 + nn * 8 + lc * 2;
            float* o = h1 + ((size_t)h * N_ROWS + r) * N_HID + c;
            *reinterpret_cast<float2*>(o) = make_float2(acc[mm][nn][0], acc[mm][nn][1]);
            *reinterpret_cast<float2*>(o + 8 * N_HID) = make_float2(acc[mm][nn][2], acc[mm][nn][3]);
        }

    const float* a = ah + (size_t)h * 2 * N_HID;
#pragma unroll
    for (int mm = 0; mm < 2; mm++) {
        float ps1 = 0.f, pd1 = 0.f, ps2 = 0.f, pd2 = 0.f;
#pragma unroll
        for (int nn = 0; nn < 4; nn++) {
            int c0 = wn * 32 + nn * 8 + lc * 2;
            float a0s = a[c0], a1s = a[c0 + 1];
            float a0d = a[N_HID + c0], a1d = a[N_HID + c0 + 1];
            ps1 += acc[mm][nn][0] * a0s + acc[mm][nn][1] * a1s;
            pd1 += acc[mm][nn][0] * a0d + acc[mm][nn][1] * a1d;
            ps2 += acc[mm][nn][2] * a0s + acc[mm][nn][3] * a1s;
            pd2 += acc[mm][nn][2] * a0d + acc[mm][nn][3] * a1d;
        }
#pragma unroll
        for (int off = 1; off <= 2; off <<= 1) {
            ps1 += __shfl_xor_sync(0xffffffffu, ps1, off);
            pd1 += __shfl_xor_sync(0xffffffffu, pd1, off);
            ps2 += __shfl_xor_sync(0xffffffffu, ps2, off);
            pd2 += __shfl_xor_sync(0xffffffffu, pd2, off);
        }
        if (lc == 0) {
            int rl = wm * 32 + mm * 16 + lr;
            sred[wn][0][rl] = ps1; sred[wn][1][rl] = pd1;
            sred[wn][0][rl + 8] = ps2; sred[wn][1][rl + 8] = pd2;
        }
    }
    __syncthreads();
    if (tid < BM) {
        int gi = h * N_ROWS + row0 + tid;
        ssrc[gi] = sred[0][0][tid] + sred[1][0][tid];
        sdst[gi] = sred[0][1][tid] + sred[1][1][tid];
    }
}

// ---------------- megaL1 ----------------
__global__ __launch_bounds__(1024, 1) void megaL1_kernel(
    const float* __restrict__ sdst, float* __restrict__ csort,
    float* __restrict__ sorted, int* __restrict__ idx,
    float* __restrict__ ew, float* __restrict__ gw,
    float* __restrict__ Zhi, float* __restrict__ Zlo,
    const float* __restrict__ h1, float* __restrict__ Chi, float* __restrict__ Clo,
    float* __restrict__ Phi, float* __restrict__ Plo,
    const float* __restrict__ ssrc, float* __restrict__ xc)
{
    __shared__ __align__(16) unsigned char sm[33792];
    int blk = blockIdx.x, t = threadIdx.x;

    // ---- S_a: chunk sorts (64 blocks) ----
    if (blk < 64) sortchunk_body(blk >> 3, blk & 7, sdst, csort, (float*)sm);
    gbar();
    // ---- S_b: rank + scatter + idx (64 blocks) ----
    if (blk < 64) rank_body(blk >> 3, blk & 7, sdst, csort, sorted, idx,
                            (float*)sm, (int*)(sm + 16384));
    gbar();
    // ---- S_c: scalar scans (8 blocks) ----
    if (blk < N_HEADS) scan_body(blk, sorted, ew, gw, Zhi, Zlo, (float*)(sm + 32768));
    gbar();

    int h = blk >> 4, chunk = blk & 15;

    // ---- Phase A ----
    {
        int* sidx = (int*)sm;
        float* sew = (float*)(sm + 1024);
        float* sgw = (float*)(sm + 2048);
        float (*sH)[N_HID] = (float(*)[N_HID])(sm + 3072);
        float (*sL)[N_HID] = (float(*)[N_HID])(sm + 7168);
        int ft = t & 63, rg = t >> 6;
        if (t < 256) {
            int base = h * N_ROWS + chunk * 256 + t;
            sidx[t] = idx[base]; sew[t] = ew[base]; sgw[t] = gw[base];
        }
        __syncthreads();
        const float* hb = h1 + (size_t)h * N_ROWS * N_HID + ft;
        float sh_ = 0.f, sl_ = 0.f;
#pragma unroll
        for (int j = 0; j < 16; j++) {
            int rl = rg * 16 + j;
            float v = hb[(size_t)sidx[rl] * N_HID];
            sh_ += v * sew[rl];
            sl_ += v * sgw[rl];
        }
        sH[rg][ft] = sh_; sL[rg][ft] = sl_;
        __syncthreads();
        if (rg == 0) {
            float a = 0.f, b = 0.f;
#pragma unroll
            for (int r = 0; r < 16; r++) { a += sH[r][ft]; b += sL[r][ft]; }
            Chi[(h * N_HID + ft) * 16 + chunk] = a;
            Clo[(h * N_HID + ft) * 16 + chunk] = b;
        }
    }
    gbar();

    // ---- Phase C ----
    {
        int* sidx = (int*)sm;
        float* sew = (float*)(sm + 1024);
        float* sgw = (float*)(sm + 2048);
        float* sChi = (float*)(sm + 3072);
        float* sClo = (float*)(sm + 7168);
        float (*sH)[N_HID] = (float(*)[N_HID])(sm + 11264);
        float (*sL)[N_HID] = (float(*)[N_HID])(sm + 15360);
        int ft = t & 63, rg = t >> 6;
        if (t < 256) {
            int base = h * N_ROWS + chunk * 256 + t;
            sidx[t] = idx[base]; sew[t] = ew[base]; sgw[t] = gw[base];
        }
        sChi[t] = Chi[h * N_HID * 16 + t];
        sClo[t] = Clo[h * N_HID * 16 + t];
        __syncthreads();
        const float* hb = h1 + (size_t)h * N_ROWS * N_HID + ft;
        float vh[16], vl[16];
        float sh_ = 0.f, sl_ = 0.f;
#pragma unroll
        for (int j = 0; j < 16; j++) {
            int rl = rg * 16 + j;
            float v = hb[(size_t)sidx[rl] * N_HID];
            vh[j] = v * sew[rl];
            vl[j] = v * sgw[rl];
            sh_ += vh[j]; sl_ += vl[j];
        }
        sH[rg][ft] = sh_; sL[rg][ft] = sl_;
        __syncthreads();
        float offh = 0.f, offl = 0.f, totl = 0.f;
#pragma unroll
        for (int c = 0; c < 16; c++) {
            float a = sChi[ft * 16 + c], b = sClo[ft * 16 + c];
            if (c < chunk) { offh += a; offl += b; }
            totl += b;
        }
        for (int r = 0; r < rg; r++) { offh += sH[r][ft]; offl += sL[r][ft]; }
        float* PH = Phi + (size_t)h * KR * N_HID + ft;
        float* PL = Plo + (size_t)h * KR * N_HID + ft;
        float runh = offh, runl = offl;
        int k0 = chunk * 256 + rg * 16;
#pragma unroll
        for (int j = 0; j < 16; j++) {
            PH[(size_t)(k0 + j) * N_HID] = runh;
            PL[(size_t)(k0 + j) * N_HID] = totl - runl;
            runh += vh[j];
            runl += vl[j];
        }
        if (chunk == 15 && rg == 15) {
            PH[(size_t)N_ROWS * N_HID] = runh;
            PL[(size_t)N_ROWS * N_HID] = totl - runl;
        }
    }
    gbar();

    // ---- Phase B: combine1 ----
    {
        float* ss = (float*)sm;
        const float* sb = sorted + (size_t)h * N_ROWS;
        *reinterpret_cast<float4*>(ss + t * 4) = *reinterpret_cast<const float4*>(sb + t * 4);
        __syncthreads();
        int warp = t >> 5, lane = t & 31;
        float M = ss[0];
        const float* ZH = Zhi + (size_t)h * PS;
        const float* ZL = Zlo + (size_t)h * PS;
        const float* PHb = Phi + (size_t)h * KR * N_HID;
        const float* PLb = Plo + (size_t)h * KR * N_HID;
        int i0 = chunk * 256;
#pragma unroll
        for (int rr = 0; rr < 8; rr++) {
            int i = i0 + warp * 8 + rr;
            float s = ssrc[(size_t)h * N_ROWS + i];
            float thr = -s;
            int lo = 0, hi = N_ROWS;
            while (lo < hi) {
                int mid = (lo + hi) >> 1;
                if (ss[mid] >= thr) lo = mid + 1; else hi = mid;
            }
            int k = lo;
            float rho = expf(-0.8f * (s + M));
            float den = (k == 0) ? ZL[0] : (ZH[k] + rho * ZL[k]);
            float inv = 1.f / den;
            const float* ph = PHb + (size_t)k * N_HID;
            const float* pl = PLb + (size_t)k * N_HID;
#pragma unroll
            for (int u = 0; u < 2; u++) {
                int f = lane + 32 * u;
                float num = (k == 0) ? pl[f] : (ph[f] + rho * pl[f]);
                float feat = num * inv;
                float v = feat > 0.f ? feat : expm1f(feat);
                xc[(size_t)i * N_FEAT + h * N_HID + f] = v;
            }
        }
    }
}

// ---------------- megaL2 ----------------
__global__ __launch_bounds__(1024, 1) void megaL2_kernel(
    const float* __restrict__ xc, const float* __restrict__ Wo, const float* __restrict__ ao,
    float* __restrict__ h2, float* __restrict__ ssrc, float* __restrict__ sdst,
    float* __restrict__ csort, float* __restrict__ sorted, int* __restrict__ idx,
    float* __restrict__ ew, float* __restrict__ gw,
    float* __restrict__ Zhi, float* __restrict__ Zlo,
    float* __restrict__ Chi, float* __restrict__ Clo,
    float* __restrict__ Phi, float* __restrict__ Plo,
    float* __restrict__ out)
{
    __shared__ __align__(16) unsigned char sm[33792];
    int blk = blockIdx.x, t = threadIdx.x;

    // ---- Phase G: gemm2 + fused scores2 ----
    {
        float (*xs)[64] = (float(*)[64])sm;
        float (*ws)[16] = (float(*)[16])(sm + 8192);
        int row0 = blk * 32;
        int ir = t >> 4, fc = t & 15;
        float acc = 0.f;
        for (int k0 = 0; k0 < N_FEAT; k0 += 64) {
            __syncthreads();
#pragma unroll
            for (int rep = 0; rep < 2; rep++) {
                int t2 = t + rep * 1024;
                int r = t2 >> 6, kk = t2 & 63;
                xs[r][kk] = xc[(size_t)(row0 + r) * N_FEAT + k0 + kk];
            }
            {
                int kk = t >> 4, f = t & 15;
                if (kk < 64) ws[kk][f] = Wo[(size_t)(k0 + kk) * N_CLASS + f];
            }
            __syncthreads();
            if (t < 512) {
#pragma unroll
                for (int kk = 0; kk < 64; kk++) acc += xs[ir][kk] * ws[kk][fc];
            }
        }
        if (t < 512) {
            h2[(size_t)(row0 + ir) * N_CLASS + fc] = acc;
            float ps = acc * ao[fc];
            float pd = acc * ao[N_CLASS + fc];
#pragma unroll
            for (int off = 1; off < 16; off <<= 1) {
                ps += __shfl_xor_sync(0xffffffffu, ps, off);
                pd += __shfl_xor_sync(0xffffffffu, pd, off);
            }
            if (fc == 0) {
                ssrc[row0 + ir] = ps;
                sdst[row0 + ir] = pd;
            }
        }
    }
    gbar();

    if (blk < 8) sortchunk_body(0, blk, sdst, csort, (float*)sm);
    gbar();
    if (blk < 8) rank_body(0, blk, sdst, csort, sorted, idx,
                           (float*)sm, (int*)(sm + 16384));
    gbar();
    if (blk == 0) scan_body(0, sorted, ew, gw, Zhi, Zlo, (float*)(sm + 32768));
    gbar();

    // ---- Phase A2 ----
    if (blk < 16) {
        int chunk = blk;
        int* sidx = (int*)sm;
        float* sew = (float*)(sm + 1024);
        float* sgw = (float*)(sm + 2048);
        float (*sH)[N_CLASS] = (float(*)[N_CLASS])(sm + 3072);
        float (*sL)[N_CLASS] = (float(*)[N_CLASS])(sm + 7168);
        if (t < 256) {
            int base = chunk * 256 + t;
            sidx[t] = idx[base]; sew[t] = ew[base]; sgw[t] = gw[base];
        }
        __syncthreads();
        int ft = t & 15, rg = t >> 4;
        const float* hb = h2 + ft;
        float a = 0.f, b = 0.f;
#pragma unroll
        for (int j = 0; j < 4; j++) {
            int rl = rg * 4 + j;
            float v = hb[(size_t)sidx[rl] * N_CLASS];
            a += v * sew[rl];
            b += v * sgw[rl];
        }
        sH[rg][ft] = a; sL[rg][ft] = b;
        __syncthreads();
        if (t < 16) {
            float sa = 0.f, sb = 0.f;
#pragma unroll
            for (int r = 0; r < 64; r++) { sa += sH[r][t]; sb += sL[r][t]; }
            Chi[t * 16 + chunk] = sa;
            Clo[t * 16 + chunk] = sb;
        }
    }
    gbar();

    // ---- Phase C2 ----
    if (blk < 16) {
        int chunk = blk;
        int* sidx = (int*)sm;
        float* sew = (float*)(sm + 1024);
        float* sgw = (float*)(sm + 2048);
        float (*sH)[N_CLASS] = (float(*)[N_CLASS])(sm + 3072);
        float (*sL)[N_CLASS] = (float(*)[N_CLASS])(sm + 7168);
        float* sChi = (float*)(sm + 11264);
        float* sClo = (float*)(sm + 12288);
        if (t < 256) {
            int base = chunk * 256 + t;
            sidx[t] = idx[base]; sew[t] = ew[base]; sgw[t] = gw[base];
            sChi[t] = Chi[t]; sClo[t] = Clo[t];
        }
        __syncthreads();
        int ft = t & 15, rg = t >> 4;
        const float* hb = h2 + ft;
        float vh[4], vl[4];
        float a = 0.f, b = 0.f;
#pragma unroll
        for (int j = 0; j < 4; j++) {
            int rl = rg * 4 + j;
            float v = hb[(size_t)sidx[rl] * N_CLASS];
            vh[j] = v * sew[rl];
            vl[j] = v * sgw[rl];
            a += vh[j]; b += vl[j];
        }
        sH[rg][ft] = a; sL[rg][ft] = b;
        __syncthreads();
        float offh = 0.f, offl = 0.f, totl = 0.f;
#pragma unroll
        for (int c = 0; c < 16; c++) {
            float ca = sChi[ft * 16 + c], cb = sClo[ft * 16 + c];
            if (c < chunk) { offh += ca; offl += cb; }
            totl += cb;
        }
        for (int r = 0; r < rg; r++) { offh += sH[r][ft]; offl += sL[r][ft]; }
        float runh = offh, runl = offl;
        int k0 = chunk * 256 + rg * 4;
#pragma unroll
        for (int j = 0; j < 4; j++) {
            Phi[(size_t)(k0 + j) * N_CLASS + ft] = runh;
            Plo[(size_t)(k0 + j) * N_CLASS + ft] = totl - runl;
            runh += vh[j];
            runl += vl[j];
        }
        if (chunk == 15 && rg == 63) {
            Phi[(size_t)N_ROWS * N_CLASS + ft] = runh;
            Plo[(size_t)N_ROWS * N_CLASS + ft] = totl - runl;
        }
    }
    gbar();

    // ---- Phase B2 ----
    if (blk < 64) {
        float* ss = (float*)sm;
        *reinterpret_cast<float4*>(ss + t * 4) = *reinterpret_cast<const float4*>(sorted + t * 4);
        __syncthreads();
        int f = t & 15, il = t >> 4;
        int i = blk * 64 + il;
        float M = ss[0];
        float s = ssrc[i];
        float thr = -s;
        int lo = 0, hi = N_ROWS;
        while (lo < hi) {
            int mid = (lo + hi) >> 1;
            if (ss[mid] >= thr) lo = mid + 1; else hi = mid;
        }
        int k = lo;
        float rho = expf(-0.8f * (s + M));
        float den = (k == 0) ? Zlo[0] : (Zhi[k] + rho * Zlo[k]);
        float num = (k == 0) ? Plo[f]
                             : (Phi[(size_t)k * N_CLASS + f] + rho * Plo[(size_t)k * N_CLASS + f]);
        float feat = num / den;
        float v = feat > 0.f ? feat : expm1f(feat);
        float m = v;
#pragma unroll
        for (int off = 8; off; off >>= 1) m = fmaxf(m, __shfl_xor_sync(0xffffffffu, m, off));
        float ex = expf(v - m);
        float ssum = ex;
#pragma unroll
        for (int off = 8; off; off >>= 1) ssum += __shfl_xor_sync(0xffffffffu, ssum, off);
        out[(size_t)i * N_CLASS + f] = v - m - logf(ssum);
    }
}

// ---------------- launch ----------------
extern "C" void kernel_launch(void* const* d_in, const int* in_sizes, int n_in,
                              void* d_out, int out_size)
{
    const float* x  = (const float*)d_in[0];
    const float* Wh = (const float*)d_in[1];
    const float* ah = (const float*)d_in[2];
    const float* Wo = (const float*)d_in[3];
    const float* ao = (const float*)d_in[4];
    float* out = (float*)d_out;

    __nv_bfloat16 *p_xh, *p_xl, *p_whh, *p_whl;
    float *p_h1, *p_ssrc1, *p_sdst1, *p_csort1, *p_sorted1, *p_ew1, *p_gw1, *p_Zhi1, *p_Zlo1;
    float *p_Chi1, *p_Clo1, *p_Phi1, *p_Plo1, *p_xc;
    int *p_idx1;
    float *p_h2, *p_ssrc2, *p_sdst2, *p_csort2, *p_sorted2, *p_ew2, *p_gw2, *p_Zhi2, *p_Zlo2;
    float *p_Chi2, *p_Clo2, *p_Phi2, *p_Plo2;
    int *p_idx2;

    cudaGetSymbolAddress((void**)&p_xh, g_xh);
    cudaGetSymbolAddress((void**)&p_xl, g_xl);
    cudaGetSymbolAddress((void**)&p_whh, g_whh);
    cudaGetSymbolAddress((void**)&p_whl, g_whl);
    cudaGetSymbolAddress((void**)&p_h1, g_h1);
    cudaGetSymbolAddress((void**)&p_ssrc1, g_ssrc1);
    cudaGetSymbolAddress((void**)&p_sdst1, g_sdst1);
    cudaGetSymbolAddress((void**)&p_csort1, g_csort1);
    cudaGetSymbolAddress((void**)&p_sorted1, g_sorted1);
    cudaGetSymbolAddress((void**)&p_idx1, g_idx1);
    cudaGetSymbolAddress((void**)&p_ew1, g_ew1);
    cudaGetSymbolAddress((void**)&p_gw1, g_gw1);
    cudaGetSymbolAddress((void**)&p_Zhi1, g_Zhi1);
    cudaGetSymbolAddress((void**)&p_Zlo1, g_Zlo1);
    cudaGetSymbolAddress((void**)&p_Chi1, g_Chi1);
    cudaGetSymbolAddress((void**)&p_Clo1, g_Clo1);
    cudaGetSymbolAddress((void**)&p_Phi1, g_Phi1);
    cudaGetSymbolAddress((void**)&p_Plo1, g_Plo1);
    cudaGetSymbolAddress((void**)&p_xc, g_xc);
    cudaGetSymbolAddress((void**)&p_h2, g_h2);
    cudaGetSymbolAddress((void**)&p_ssrc2, g_ssrc2);
    cudaGetSymbolAddress((void**)&p_sdst2, g_sdst2);
    cudaGetSymbolAddress((void**)&p_csort2, g_csort2);
    cudaGetSymbolAddress((void**)&p_sorted2, g_sorted2);
    cudaGetSymbolAddress((void**)&p_idx2, g_idx2);
    cudaGetSymbolAddress((void**)&p_ew2, g_ew2);
    cudaGetSymbolAddress((void**)&p_gw2, g_gw2);
    cudaGetSymbolAddress((void**)&p_Zhi2, g_Zhi2);
    cudaGetSymbolAddress((void**)&p_Zlo2, g_Zlo2);
    cudaGetSymbolAddress((void**)&p_Chi2, g_Chi2);
    cudaGetSymbolAddress((void**)&p_Clo2, g_Clo2);
    cudaGetSymbolAddress((void**)&p_Phi2, g_Phi2);
    cudaGetSymbolAddress((void**)&p_Plo2, g_Plo2);

    splitall_kernel<<<(NX4 + NW4 + 255) / 256, 256>>>(x, Wh, p_xh, p_xl, p_whh, p_whl);
    gemm1_mma_kernel<<<dim3(N_ROWS / 128, N_HEADS), 256>>>(p_xh, p_xl, p_whh, p_whl, ah,
                                                           p_h1, p_ssrc1, p_sdst1);
    megaL1_kernel<<<NB, 1024>>>(p_sdst1, p_csort1, p_sorted1, p_idx1, p_ew1, p_gw1,
                                p_Zhi1, p_Zlo1, p_h1, p_Chi1, p_Clo1, p_Phi1, p_Plo1,
                                p_ssrc1, p_xc);
    megaL2_kernel<<<NB, 1024>>>(p_xc, Wo, ao, p_h2, p_ssrc2, p_sdst2,
                                p_csort2, p_sorted2, p_idx2, p_ew2, p_gw2, p_Zhi2, p_Zlo2,
                                p_Chi2, p_Clo2, p_Phi2, p_Plo2, out);

    (void)in_sizes; (void)n_in; (void)out_size;
}

// round 13
// speedup vs baseline: 2.2964x; 1.0648x over previous
#include <cuda_runtime.h>
#include <cuda_bf16.h>
#include <cstdint>

#define N_ROWS   4096
#define N_FEAT   512
#define N_HID    64
#define N_CLASS  16
#define N_HEADS  8
#define PS       (N_ROWS + 4)
#define KR       (N_ROWS + 1)
#define NB       128            // mega-kernel grid size (all-resident)

// ---------------- scratch ----------------
__device__ __nv_bfloat16 g_xh [N_ROWS*N_FEAT];
__device__ __nv_bfloat16 g_xl [N_ROWS*N_FEAT];
__device__ __nv_bfloat16 g_whh[N_HEADS*N_FEAT*N_HID];
__device__ __nv_bfloat16 g_whl[N_HEADS*N_FEAT*N_HID];

__device__ float g_h1   [N_HEADS*N_ROWS*N_HID];
__device__ float g_ssrc1[N_HEADS*N_ROWS];
__device__ float g_sdst1[N_HEADS*N_ROWS];
__device__ float g_csort1[N_HEADS*N_ROWS];
__device__ float g_sorted1[N_HEADS*N_ROWS];
__device__ int   g_idx1 [N_HEADS*N_ROWS];
__device__ float g_Zhi1 [N_HEADS*PS];
__device__ float g_Zlo1 [N_HEADS*PS];
__device__ float g_Ze1  [N_HEADS*16];
__device__ float g_Zg1  [N_HEADS*16];
__device__ float g_Chi1 [N_HEADS*N_HID*16];
__device__ float g_Clo1 [N_HEADS*N_HID*16];
__device__ float g_Phi1 [N_HEADS*KR*N_HID];
__device__ float g_Plo1 [N_HEADS*KR*N_HID];
__device__ float g_xc   [N_ROWS*N_FEAT];

__device__ float g_h2   [N_ROWS*N_CLASS];
__device__ float g_ssrc2[N_ROWS];
__device__ float g_sdst2[N_ROWS];
__device__ float g_csort2[N_ROWS];
__device__ float g_sorted2[N_ROWS];
__device__ int   g_idx2 [N_ROWS];
__device__ float g_Zhi2 [PS];
__device__ float g_Zlo2 [PS];
__device__ float g_Ze2  [16];
__device__ float g_Zg2  [16];
__device__ float g_Chi2 [N_CLASS*16];
__device__ float g_Clo2 [N_CLASS*16];
__device__ float g_Phi2 [KR*N_CLASS];
__device__ float g_Plo2 [KR*N_CLASS];

// ---------------- device-wide software barrier ----------------
__device__ unsigned g_cnt;
__device__ volatile unsigned g_gen;

__device__ __forceinline__ void gbar() {
    __syncthreads();
    if (threadIdx.x == 0) {
        __threadfence();
        unsigned old = g_gen;
        if (atomicAdd(&g_cnt, 1u) == NB - 1) {
            g_cnt = 0;
            __threadfence();
            g_gen = old + 1;
        } else {
            while (g_gen == old) { __nanosleep(64); }
            __threadfence();
        }
    }
    __syncthreads();
}

// ---------------- S_a: sort one 512-chunk (descending), 1 elem/thread ----------------
__device__ void sortchunk_body(int h, int c, const float* __restrict__ sdst,
                               float* __restrict__ csort, float* sk)
{
    int tid = threadIdx.x;
    float key = 0.f;
    if (tid < 512) key = sdst[(size_t)h * N_ROWS + c * 512 + tid];
    for (int k = 2; k <= 512; k <<= 1) {
        for (int j = k >> 1; j > 0; j >>= 1) {
            if (j >= 32) {
                __syncthreads();
                if (tid < 512) sk[tid] = key;
                __syncthreads();
                if (tid < 512) {
                    float ok = sk[tid ^ j];
                    bool lower = (tid & j) == 0;
                    bool desc = ((tid & k & 511) == 0);
                    float a = lower ? key : ok, b = lower ? ok : key;
                    if (desc ? (a < b) : (a > b)) key = ok;
                }
            } else {
                if (tid < 512) {
                    float ok = __shfl_xor_sync(0xffffffffu, key, j);
                    bool lower = (tid & j) == 0;
                    bool desc = ((tid & k & 511) == 0);
                    float a = lower ? key : ok, b = lower ? ok : key;
                    if (desc ? (a < b) : (a > b)) key = ok;
                }
            }
        }
    }
    __syncthreads();
    if (tid < 512) csort[(size_t)h * N_ROWS + c * 512 + tid] = key;
}

// ---------------- S_b: rank own chunk + scatter sorted + idx recovery ----------------
__device__ void rank_body(int h, int c, const float* __restrict__ sdst,
                          const float* __restrict__ csort,
                          float* __restrict__ sorted, int* __restrict__ idx,
                          float* skeys, int* grank)
{
    int tid = threadIdx.x;
#pragma unroll
    for (int i = 0; i < 4; i++) skeys[tid + i * 1024] = csort[(size_t)h * N_ROWS + tid + i * 1024];
    __syncthreads();
    if (tid < 512) {
        float x = skeys[c * 512 + tid];
        int r = tid;
#pragma unroll
        for (int cc = 0; cc < 8; cc++) {
            if (cc == c) continue;
            const float* S = skeys + cc * 512;
            int lo = 0, hi = 512;
            if (cc < c) {
                while (lo < hi) { int mid = (lo + hi) >> 1; if (S[mid] >= x) lo = mid + 1; else hi = mid; }
            } else {
                while (lo < hi) { int mid = (lo + hi) >> 1; if (S[mid] > x) lo = mid + 1; else hi = mid; }
            }
            r += lo;
        }
        grank[tid] = r;
        sorted[(size_t)h * N_ROWS + r] = x;
    }
    __syncthreads();
    if (tid < 512) {
        int j = c * 512 + tid;
        float x = sdst[(size_t)h * N_ROWS + j];
        const float* S = skeys + c * 512;
        int lo = 0, hi = 512;
        while (lo < hi) { int mid = (lo + hi) >> 1; if (S[mid] > x) lo = mid + 1; else hi = mid; }
        int off = atomicAdd(&grank[lo], 0x10000) >> 16;
        int rank = grank[lo + off] & 0xFFFF;
        idx[(size_t)h * N_ROWS + rank] = j;
    }
    __syncthreads();
}

// ---------------- combined split fp32 -> bf16 hi/lo ----------------
#define NX4  (N_ROWS * N_FEAT / 4)
#define NW4  (N_HEADS * N_FEAT * N_HID / 4)
__global__ void splitall_kernel(const float* __restrict__ x, const float* __restrict__ Wh,
                                __nv_bfloat16* __restrict__ xh, __nv_bfloat16* __restrict__ xl,
                                __nv_bfloat16* __restrict__ whh, __nv_bfloat16* __restrict__ whl)
{
    int i = blockIdx.x * blockDim.x + threadIdx.x;
    const float* src; __nv_bfloat16 *hi, *lo; int j;
    if (i < NX4) { src = x; hi = xh; lo = xl; j = i; }
    else         { src = Wh; hi = whh; lo = whl; j = i - NX4; if (j >= NW4) return; }
    float4 v = reinterpret_cast<const float4*>(src)[j];
    __nv_bfloat16 h0 = __float2bfloat16_rn(v.x);
    __nv_bfloat16 h1 = __float2bfloat16_rn(v.y);
    __nv_bfloat16 h2 = __float2bfloat16_rn(v.z);
    __nv_bfloat16 h3 = __float2bfloat16_rn(v.w);
    __nv_bfloat16 l0 = __float2bfloat16_rn(v.x - __bfloat162float(h0));
    __nv_bfloat16 l1 = __float2bfloat16_rn(v.y - __bfloat162float(h1));
    __nv_bfloat16 l2 = __float2bfloat16_rn(v.z - __bfloat162float(h2));
    __nv_bfloat16 l3 = __float2bfloat16_rn(v.w - __bfloat162float(h3));
    __nv_bfloat162* hp = reinterpret_cast<__nv_bfloat162*>(hi) + j * 2;
    __nv_bfloat162* lp = reinterpret_cast<__nv_bfloat162*>(lo) + j * 2;
    hp[0] = __nv_bfloat162(h0, h1); hp[1] = __nv_bfloat162(h2, h3);
    lp[0] = __nv_bfloat162(l0, l1); lp[1] = __nv_bfloat162(l2, l3);
}

// ---------------- GEMM1 (bf16 mma + ldmatrix + fused scores) ----------------
__device__ __forceinline__ void mma16816(float* c, const uint32_t* a, const uint32_t* b) {
    asm volatile(
        "mma.sync.aligned.m16n8k16.row.col.f32.bf16.bf16.f32 "
        "{%0,%1,%2,%3}, {%4,%5,%6,%7}, {%8,%9}, {%0,%1,%2,%3};\n"
        : "+f"(c[0]), "+f"(c[1]), "+f"(c[2]), "+f"(c[3])
        : "r"(a[0]), "r"(a[1]), "r"(a[2]), "r"(a[3]), "r"(b[0]), "r"(b[1]));
}
__device__ __forceinline__ void ldmat_x4(uint32_t* r, uint32_t addr) {
    asm volatile("ldmatrix.sync.aligned.m8n8.x4.shared.b16 {%0,%1,%2,%3}, [%4];"
        : "=r"(r[0]), "=r"(r[1]), "=r"(r[2]), "=r"(r[3]) : "r"(addr));
}
__device__ __forceinline__ void ldmat_x4_t(uint32_t* r, uint32_t addr) {
    asm volatile("ldmatrix.sync.aligned.m8n8.x4.trans.shared.b16 {%0,%1,%2,%3}, [%4];"
        : "=r"(r[0]), "=r"(r[1]), "=r"(r[2]), "=r"(r[3]) : "r"(addr));
}

__global__ __launch_bounds__(256) void gemm1_mma_kernel(
    const __nv_bfloat16* __restrict__ xh, const __nv_bfloat16* __restrict__ xl,
    const __nv_bfloat16* __restrict__ whh, const __nv_bfloat16* __restrict__ whl,
    const float* __restrict__ ah,
    float* __restrict__ h1, float* __restrict__ ssrc, float* __restrict__ sdst)
{
    const int BM = 128, BKT = 64, SA = 72, SB = 72;
    __shared__ __nv_bfloat16 As[BM * SA];
    __shared__ __nv_bfloat16 Bs[BKT * SB];
    __shared__ float sred[2][2][BM];
    int h = blockIdx.y;
    int row0 = blockIdx.x * BM;
    int tid = threadIdx.x;
    int wid = tid >> 5, lane = tid & 31;
    int wm = wid & 3, wn = wid >> 2;
    int lr = lane >> 2, lc = lane & 3;
    int idx15 = lane & 15, hi8 = (lane >> 4) << 3;

    uint32_t sa_base = (uint32_t)__cvta_generic_to_shared(As);
    uint32_t sb_base = (uint32_t)__cvta_generic_to_shared(Bs);

    const __nv_bfloat16* Wb0 = whh + (size_t)h * N_FEAT * N_HID;
    const __nv_bfloat16* Wb1 = whl + (size_t)h * N_FEAT * N_HID;
    const __nv_bfloat16* Aph[3] = { xh, xl, xh };
    const __nv_bfloat16* Bph[3] = { Wb0, Wb0, Wb1 };

    float acc[2][4][4];
#pragma unroll
    for (int mm = 0; mm < 2; mm++)
#pragma unroll
        for (int nn = 0; nn < 4; nn++)
#pragma unroll
            for (int q = 0; q < 4; q++) acc[mm][nn][q] = 0.f;

    for (int p = 0; p < 3; p++) {
        const __nv_bfloat16* Ag = Aph[p];
        const __nv_bfloat16* Bg = Bph[p];
        for (int k0 = 0; k0 < N_FEAT; k0 += BKT) {
            __syncthreads();
#pragma unroll
            for (int i = 0; i < 4; i++) {
                int id4 = tid + i * 256;
                int r = id4 >> 3, kk = (id4 & 7) * 8;
                uint4 v = *reinterpret_cast<const uint4*>(
                    Ag + (size_t)(row0 + r) * N_FEAT + k0 + kk);
                *reinterpret_cast<uint4*>(As + r * SA + kk) = v;
            }
#pragma unroll
            for (int i = 0; i < 2; i++) {
                int id4 = tid + i * 256;
                int kk = id4 >> 3, ff = (id4 & 7) * 8;
                uint4 v = *reinterpret_cast<const uint4*>(
                    Bg + (size_t)(k0 + kk) * N_HID + ff);
                *reinterpret_cast<uint4*>(Bs + kk * SB + ff) = v;
            }
            __syncthreads();
#pragma unroll
            for (int ks = 0; ks < 4; ks++) {
                int kb = ks * 16;
                uint32_t afr[2][4];
#pragma unroll
                for (int mm = 0; mm < 2; mm++) {
                    uint32_t addr = sa_base +
                        (uint32_t)((wm * 32 + mm * 16 + idx15) * SA + kb + hi8) * 2u;
                    ldmat_x4(afr[mm], addr);
                }
                uint32_t bfr[4][2];
#pragma unroll
                for (int bp = 0; bp < 2; bp++) {
                    uint32_t bt[4];
                    uint32_t addr = sb_base +
                        (uint32_t)((kb + idx15) * SB + wn * 32 + bp * 16 + hi8) * 2u;
                    ldmat_x4_t(bt, addr);
                    bfr[bp * 2][0] = bt[0]; bfr[bp * 2][1] = bt[1];
                    bfr[bp * 2 + 1][0] = bt[2]; bfr[bp * 2 + 1][1] = bt[3];
                }
#pragma unroll
                for (int mm = 0; mm < 2; mm++)
#pragma unroll
                    for (int nn = 0; nn < 4; nn++)
                        mma16816(acc[mm][nn], afr[mm], bfr[nn]);
            }
        }
    }
#pragma unroll
    for (int mm = 0; mm < 2; mm++)
#pragma unroll
        for (int nn = 0; nn < 4; nn++) {
            int r = row0 + wm * 32 + mm * 16 + lr;
            int c = wn * 32 + nn * 8 + lc * 2;
            float* o = h1 + ((size_t)h * N_ROWS + r) * N_HID + c;
            *reinterpret_cast<float2*>(o) = make_float2(acc[mm][nn][0], acc[mm][nn][1]);
            *reinterpret_cast<float2*>(o + 8 * N_HID) = make_float2(acc[mm][nn][2], acc[mm][nn][3]);
        }

    const float* a = ah + (size_t)h * 2 * N_HID;
#pragma unroll
    for (int mm = 0; mm < 2; mm++) {
        float ps1 = 0.f, pd1 = 0.f, ps2 = 0.f, pd2 = 0.f;
#pragma unroll
        for (int nn = 0; nn < 4; nn++) {
            int c0 = wn * 32 + nn * 8 + lc * 2;
            float a0s = a[c0], a1s = a[c0 + 1];
            float a0d = a[N_HID + c0], a1d = a[N_HID + c0 + 1];
            ps1 += acc[mm][nn][0] * a0s + acc[mm][nn][1] * a1s;
            pd1 += acc[mm][nn][0] * a0d + acc[mm][nn][1] * a1d;
            ps2 += acc[mm][nn][2] * a0s + acc[mm][nn][3] * a1s;
            pd2 += acc[mm][nn][2] * a0d + acc[mm][nn][3] * a1d;
        }
#pragma unroll
        for (int off = 1; off <= 2; off <<= 1) {
            ps1 += __shfl_xor_sync(0xffffffffu, ps1, off);
            pd1 += __shfl_xor_sync(0xffffffffu, pd1, off);
            ps2 += __shfl_xor_sync(0xffffffffu, ps2, off);
            pd2 += __shfl_xor_sync(0xffffffffu, pd2, off);
        }
        if (lc == 0) {
            int rl = wm * 32 + mm * 16 + lr;
            sred[wn][0][rl] = ps1; sred[wn][1][rl] = pd1;
            sred[wn][0][rl + 8] = ps2; sred[wn][1][rl + 8] = pd2;
        }
    }
    __syncthreads();
    if (tid < BM) {
        int gi = h * N_ROWS + row0 + tid;
        ssrc[gi] = sred[0][0][tid] + sred[1][0][tid];
        sdst[gi] = sred[0][1][tid] + sred[1][1][tid];
    }
}

// ---------------- megaL1 ----------------
__global__ __launch_bounds__(1024, 1) void megaL1_kernel(
    const float* __restrict__ sdst, float* __restrict__ csort,
    float* __restrict__ sorted, int* __restrict__ idx,
    float* __restrict__ Zhi, float* __restrict__ Zlo,
    float* __restrict__ Ze, float* __restrict__ Zg,
    const float* __restrict__ h1, float* __restrict__ Chi, float* __restrict__ Clo,
    float* __restrict__ Phi, float* __restrict__ Plo,
    const float* __restrict__ ssrc, float* __restrict__ xc)
{
    __shared__ __align__(16) unsigned char sm[33792];
    int blk = blockIdx.x, t = threadIdx.x;

    if (blk < 64) sortchunk_body(blk >> 3, blk & 7, sdst, csort, (float*)sm);
    gbar();
    if (blk < 64) rank_body(blk >> 3, blk & 7, sdst, csort, sorted, idx,
                            (float*)sm, (int*)(sm + 16384));
    gbar();

    int h = blk >> 4, chunk = blk & 15;
    float M = sorted[(size_t)h * N_ROWS];

    // ---- Phase A: featA chunk sums + Z chunk sums ----
    {
        int* sidx = (int*)sm;
        float* sew = (float*)(sm + 1024);
        float* sgw = (float*)(sm + 2048);
        float (*sH)[N_HID] = (float(*)[N_HID])(sm + 3072);
        float (*sL)[N_HID] = (float(*)[N_HID])(sm + 7168);
        int ft = t & 63, rg = t >> 6;
        if (t < 256) {
            int base = h * N_ROWS + chunk * 256 + t;
            sidx[t] = idx[base];
            float v = sorted[base] - M;
            sew[t] = expf(v); sgw[t] = expf(0.2f * v);
        }
        __syncthreads();
        const float* hb = h1 + (size_t)h * N_ROWS * N_HID + ft;
        float sh_ = 0.f, sl_ = 0.f;
#pragma unroll
        for (int j = 0; j < 16; j++) {
            int rl = rg * 16 + j;
            float v = hb[(size_t)sidx[rl] * N_HID];
            sh_ += v * sew[rl];
            sl_ += v * sgw[rl];
        }
        sH[rg][ft] = sh_; sL[rg][ft] = sl_;
        __syncthreads();
        if (rg == 0) {
            float a = 0.f, b = 0.f;
#pragma unroll
            for (int r = 0; r < 16; r++) { a += sH[r][ft]; b += sL[r][ft]; }
            Chi[(h * N_HID + ft) * 16 + chunk] = a;
            Clo[(h * N_HID + ft) * 16 + chunk] = b;
        }
        if (t < 32) {
            float za = 0.f, zb = 0.f;
#pragma unroll
            for (int i = 0; i < 8; i++) { za += sew[t + i * 32]; zb += sgw[t + i * 32]; }
#pragma unroll
            for (int off = 16; off; off >>= 1) {
                za += __shfl_xor_sync(0xffffffffu, za, off);
                zb += __shfl_xor_sync(0xffffffffu, zb, off);
            }
            if (t == 0) { Ze[h * 16 + chunk] = za; Zg[h * 16 + chunk] = zb; }
        }
    }
    gbar();

    // ---- Phase C: featC final scan + Z prefix ----
    {
        int* sidx = (int*)sm;
        float* sew = (float*)(sm + 1024);
        float* sgw = (float*)(sm + 2048);
        float* sChi = (float*)(sm + 3072);
        float* sClo = (float*)(sm + 7168);
        float (*sH)[N_HID] = (float(*)[N_HID])(sm + 11264);
        float (*sL)[N_HID] = (float(*)[N_HID])(sm + 15360);
        float* sZe = (float*)(sm + 19456);
        float* sZg = (float*)(sm + 19520);
        float* segZ = (float*)(sm + 19584);
        float* segG = (float*)(sm + 19648);
        int ft = t & 63, rg = t >> 6;
        if (t < 256) {
            int base = h * N_ROWS + chunk * 256 + t;
            sidx[t] = idx[base];
            float v = sorted[base] - M;
            sew[t] = expf(v); sgw[t] = expf(0.2f * v);
        }
        if (t < 16) { sZe[t] = Ze[h * 16 + t]; sZg[t] = Zg[h * 16 + t]; }
        sChi[t] = Chi[h * N_HID * 16 + t];
        sClo[t] = Clo[h * N_HID * 16 + t];
        __syncthreads();
        const float* hb = h1 + (size_t)h * N_ROWS * N_HID + ft;
        float vh[16], vl[16];
        float sh_ = 0.f, sl_ = 0.f;
#pragma unroll
        for (int j = 0; j < 16; j++) {
            int rl = rg * 16 + j;
            float v = hb[(size_t)sidx[rl] * N_HID];
            vh[j] = v * sew[rl];
            vl[j] = v * sgw[rl];
            sh_ += vh[j]; sl_ += vl[j];
        }
        sH[rg][ft] = sh_; sL[rg][ft] = sl_;
        if (ft == 0) {
            float sz = 0.f, sg_ = 0.f;
#pragma unroll
            for (int j = 0; j < 16; j++) { sz += sew[rg * 16 + j]; sg_ += sgw[rg * 16 + j]; }
            segZ[rg] = sz; segG[rg] = sg_;
        }
        __syncthreads();
        float offh = 0.f, offl = 0.f, totl = 0.f;
#pragma unroll
        for (int c = 0; c < 16; c++) {
            float a = sChi[ft * 16 + c], b = sClo[ft * 16 + c];
            if (c < chunk) { offh += a; offl += b; }
            totl += b;
        }
        for (int r = 0; r < rg; r++) { offh += sH[r][ft]; offl += sL[r][ft]; }
        float* PH = Phi + (size_t)h * KR * N_HID + ft;
        float* PL = Plo + (size_t)h * KR * N_HID + ft;
        float runh = offh, runl = offl;
        int k0 = chunk * 256 + rg * 16;
#pragma unroll
        for (int j = 0; j < 16; j++) {
            PH[(size_t)(k0 + j) * N_HID] = runh;
            PL[(size_t)(k0 + j) * N_HID] = totl - runl;
            runh += vh[j];
            runl += vl[j];
        }
        if (chunk == 15 && rg == 15) {
            PH[(size_t)N_ROWS * N_HID] = runh;
            PL[(size_t)N_ROWS * N_HID] = totl - runl;
        }
        if (ft == 0) {
            float offZ = 0.f, offG = 0.f, totG = 0.f;
#pragma unroll
            for (int c = 0; c < 16; c++) {
                float a = sZe[c], b = sZg[c];
                if (c < chunk) { offZ += a; offG += b; }
                totG += b;
            }
            for (int r = 0; r < rg; r++) { offZ += segZ[r]; offG += segG[r]; }
            float* ZH = Zhi + (size_t)h * PS;
            float* ZL = Zlo + (size_t)h * PS;
            float runZ = offZ, runG = offG;
#pragma unroll
            for (int j = 0; j < 16; j++) {
                ZH[k0 + j] = runZ;
                ZL[k0 + j] = totG - runG;
                runZ += sew[rg * 16 + j];
                runG += sgw[rg * 16 + j];
            }
            if (chunk == 15 && rg == 15) { ZH[N_ROWS] = runZ; ZL[N_ROWS] = 0.f; }
        }
    }
    gbar();

    // ---- Phase B: combine1 ----
    {
        float* ss = (float*)sm;
        const float* sb = sorted + (size_t)h * N_ROWS;
        *reinterpret_cast<float4*>(ss + t * 4) = *reinterpret_cast<const float4*>(sb + t * 4);
        __syncthreads();
        int warp = t >> 5, lane = t & 31;
        const float* ZH = Zhi + (size_t)h * PS;
        const float* ZL = Zlo + (size_t)h * PS;
        const float* PHb = Phi + (size_t)h * KR * N_HID;
        const float* PLb = Plo + (size_t)h * KR * N_HID;
        int i0 = chunk * 256;
#pragma unroll
        for (int rr = 0; rr < 8; rr++) {
            int i = i0 + warp * 8 + rr;
            float s = ssrc[(size_t)h * N_ROWS + i];
            float thr = -s;
            int lo = 0, hi = N_ROWS;
            while (lo < hi) {
                int mid = (lo + hi) >> 1;
                if (ss[mid] >= thr) lo = mid + 1; else hi = mid;
            }
            int k = lo;
            float rho = expf(-0.8f * (s + M));
            float den = (k == 0) ? ZL[0] : (ZH[k] + rho * ZL[k]);
            float inv = 1.f / den;
            const float* ph = PHb + (size_t)k * N_HID;
            const float* pl = PLb + (size_t)k * N_HID;
#pragma unroll
            for (int u = 0; u < 2; u++) {
                int f = lane + 32 * u;
                float num = (k == 0) ? pl[f] : (ph[f] + rho * pl[f]);
                float feat = num * inv;
                float v = feat > 0.f ? feat : expm1f(feat);
                xc[(size_t)i * N_FEAT + h * N_HID + f] = v;
            }
        }
    }
}

// ---------------- megaL2 ----------------
__global__ __launch_bounds__(1024, 1) void megaL2_kernel(
    const float* __restrict__ xc, const float* __restrict__ Wo, const float* __restrict__ ao,
    float* __restrict__ h2, float* __restrict__ ssrc, float* __restrict__ sdst,
    float* __restrict__ csort, float* __restrict__ sorted, int* __restrict__ idx,
    float* __restrict__ Zhi, float* __restrict__ Zlo,
    float* __restrict__ Ze, float* __restrict__ Zg,
    float* __restrict__ Chi, float* __restrict__ Clo,
    float* __restrict__ Phi, float* __restrict__ Plo,
    float* __restrict__ out)
{
    __shared__ __align__(16) unsigned char sm[33792];
    int blk = blockIdx.x, t = threadIdx.x;

    // ---- Phase G: gemm2 + fused scores2 ----
    {
        float (*xs)[64] = (float(*)[64])sm;
        float (*ws)[16] = (float(*)[16])(sm + 8192);
        int row0 = blk * 32;
        int ir = t >> 4, fc = t & 15;
        float acc = 0.f;
        for (int k0 = 0; k0 < N_FEAT; k0 += 64) {
            __syncthreads();
#pragma unroll
            for (int rep = 0; rep < 2; rep++) {
                int t2 = t + rep * 1024;
                int r = t2 >> 6, kk = t2 & 63;
                xs[r][kk] = xc[(size_t)(row0 + r) * N_FEAT + k0 + kk];
            }
            {
                int kk = t >> 4, f = t & 15;
                if (kk < 64) ws[kk][f] = Wo[(size_t)(k0 + kk) * N_CLASS + f];
            }
            __syncthreads();
            if (t < 512) {
#pragma unroll
                for (int kk = 0; kk < 64; kk++) acc += xs[ir][kk] * ws[kk][fc];
            }
        }
        if (t < 512) {
            h2[(size_t)(row0 + ir) * N_CLASS + fc] = acc;
            float ps = acc * ao[fc];
            float pd = acc * ao[N_CLASS + fc];
#pragma unroll
            for (int off = 1; off < 16; off <<= 1) {
                ps += __shfl_xor_sync(0xffffffffu, ps, off);
                pd += __shfl_xor_sync(0xffffffffu, pd, off);
            }
            if (fc == 0) {
                ssrc[row0 + ir] = ps;
                sdst[row0 + ir] = pd;
            }
        }
    }
    gbar();

    if (blk < 8) sortchunk_body(0, blk, sdst, csort, (float*)sm);
    gbar();
    if (blk < 8) rank_body(0, blk, sdst, csort, sorted, idx,
                           (float*)sm, (int*)(sm + 16384));
    gbar();

    float M = sorted[0];

    // ---- Phase A2: chunk sums + Z chunk sums (blocks 0..15) ----
    if (blk < 16) {
        int chunk = blk;
        int* sidx = (int*)sm;
        float* sew = (float*)(sm + 1024);
        float* sgw = (float*)(sm + 2048);
        float (*sH)[N_CLASS] = (float(*)[N_CLASS])(sm + 3072);
        float (*sL)[N_CLASS] = (float(*)[N_CLASS])(sm + 7168);
        if (t < 256) {
            int base = chunk * 256 + t;
            sidx[t] = idx[base];
            float v = sorted[base] - M;
            sew[t] = expf(v); sgw[t] = expf(0.2f * v);
        }
        __syncthreads();
        int ft = t & 15, rg = t >> 4;
        const float* hb = h2 + ft;
        float a = 0.f, b = 0.f;
#pragma unroll
        for (int j = 0; j < 4; j++) {
            int rl = rg * 4 + j;
            float v = hb[(size_t)sidx[rl] * N_CLASS];
            a += v * sew[rl];
            b += v * sgw[rl];
        }
        sH[rg][ft] = a; sL[rg][ft] = b;
        __syncthreads();
        if (t < 16) {
            float sa = 0.f, sb = 0.f;
#pragma unroll
            for (int r = 0; r < 64; r++) { sa += sH[r][t]; sb += sL[r][t]; }
            Chi[t * 16 + chunk] = sa;
            Clo[t * 16 + chunk] = sb;
        }
        if (t < 32) {
            float za = 0.f, zb = 0.f;
#pragma unroll
            for (int i = 0; i < 8; i++) { za += sew[t + i * 32]; zb += sgw[t + i * 32]; }
#pragma unroll
            for (int off = 16; off; off >>= 1) {
                za += __shfl_xor_sync(0xffffffffu, za, off);
                zb += __shfl_xor_sync(0xffffffffu, zb, off);
            }
            if (t == 0) { Ze[chunk] = za; Zg[chunk] = zb; }
        }
    }
    gbar();

    // ---- Phase C2: final scan + Z prefix (blocks 0..15) ----
    if (blk < 16) {
        int chunk = blk;
        int* sidx = (int*)sm;
        float* sew = (float*)(sm + 1024);
        float* sgw = (float*)(sm + 2048);
        float (*sH)[N_CLASS] = (float(*)[N_CLASS])(sm + 3072);
        float (*sL)[N_CLASS] = (float(*)[N_CLASS])(sm + 7168);
        float* sChi = (float*)(sm + 11264);
        float* sClo = (float*)(sm + 12288);
        float* sZe = (float*)(sm + 13312);
        float* sZg = (float*)(sm + 13376);
        float* segZ = (float*)(sm + 13440);
        float* segG = (float*)(sm + 13696);
        if (t < 256) {
            int base = chunk * 256 + t;
            sidx[t] = idx[base];
            float v = sorted[base] - M;
            sew[t] = expf(v); sgw[t] = expf(0.2f * v);
            sChi[t] = Chi[t]; sClo[t] = Clo[t];
        }
        if (t < 16) { sZe[t] = Ze[t]; sZg[t] = Zg[t]; }
        __syncthreads();
        int ft = t & 15, rg = t >> 4;
        const float* hb = h2 + ft;
        float vh[4], vl[4];
        float a = 0.f, b = 0.f;
#pragma unroll
        for (int j = 0; j < 4; j++) {
            int rl = rg * 4 + j;
            float v = hb[(size_t)sidx[rl] * N_CLASS];
            vh[j] = v * sew[rl];
            vl[j] = v * sgw[rl];
            a += vh[j]; b += vl[j];
        }
        sH[rg][ft] = a; sL[rg][ft] = b;
        if (ft == 0) {
            float sz = 0.f, sg_ = 0.f;
#pragma unroll
            for (int j = 0; j < 4; j++) { sz += sew[rg * 4 + j]; sg_ += sgw[rg * 4 + j]; }
            segZ[rg] = sz; segG[rg] = sg_;
        }
        __syncthreads();
        float offh = 0.f, offl = 0.f, totl = 0.f;
#pragma unroll
        for (int c = 0; c < 16; c++) {
            float ca = sChi[ft * 16 + c], cb = sClo[ft * 16 + c];
            if (c < chunk) { offh += ca; offl += cb; }
            totl += cb;
        }
        for (int r = 0; r < rg; r++) { offh += sH[r][ft]; offl += sL[r][ft]; }
        float runh = offh, runl = offl;
        int k0 = chunk * 256 + rg * 4;
#pragma unroll
        for (int j = 0; j < 4; j++) {
            Phi[(size_t)(k0 + j) * N_CLASS + ft] = runh;
            Plo[(size_t)(k0 + j) * N_CLASS + ft] = totl - runl;
            runh += vh[j];
            runl += vl[j];
        }
        if (chunk == 15 && rg == 63) {
            Phi[(size_t)N_ROWS * N_CLASS + ft] = runh;
            Plo[(size_t)N_ROWS * N_CLASS + ft] = totl - runl;
        }
        if (ft == 0) {
            float offZ = 0.f, offG = 0.f, totG = 0.f;
#pragma unroll
            for (int c = 0; c < 16; c++) {
                float ca = sZe[c], cb = sZg[c];
                if (c < chunk) { offZ += ca; offG += cb; }
                totG += cb;
            }
            for (int r = 0; r < rg; r++) { offZ += segZ[r]; offG += segG[r]; }
            float runZ = offZ, runG = offG;
#pragma unroll
            for (int j = 0; j < 4; j++) {
                Zhi[k0 + j] = runZ;
                Zlo[k0 + j] = totG - runG;
                runZ += sew[rg * 4 + j];
                runG += sgw[rg * 4 + j];
            }
            if (chunk == 15 && rg == 63) { Zhi[N_ROWS] = runZ; Zlo[N_ROWS] = 0.f; }
        }
    }
    gbar();

    // ---- Phase B2 ----
    if (blk < 64) {
        float* ss = (float*)sm;
        *reinterpret_cast<float4*>(ss + t * 4) = *reinterpret_cast<const float4*>(sorted + t * 4);
        __syncthreads();
        int f = t & 15, il = t >> 4;
        int i = blk * 64 + il;
        float s = ssrc[i];
        float thr = -s;
        int lo = 0, hi = N_ROWS;
        while (lo < hi) {
            int mid = (lo + hi) >> 1;
            if (ss[mid] >= thr) lo = mid + 1; else hi = mid;
        }
        int k = lo;
        float rho = expf(-0.8f * (s + M));
        float den = (k == 0) ? Zlo[0] : (Zhi[k] + rho * Zlo[k]);
        float num = (k == 0) ? Plo[f]
                             : (Phi[(size_t)k * N_CLASS + f] + rho * Plo[(size_t)k * N_CLASS + f]);
        float feat = num / den;
        float v = feat > 0.f ? feat : expm1f(feat);
        float m = v;
#pragma unroll
        for (int off = 8; off; off >>= 1) m = fmaxf(m, __shfl_xor_sync(0xffffffffu, m, off));
        float ex = expf(v - m);
        float ssum = ex;
#pragma unroll
        for (int off = 8; off; off >>= 1) ssum += __shfl_xor_sync(0xffffffffu, ssum, off);
        out[(size_t)i * N_CLASS + f] = v - m - logf(ssum);
    }
}

// ---------------- launch ----------------
extern "C" void kernel_launch(void* const* d_in, const int* in_sizes, int n_in,
                              void* d_out, int out_size)
{
    const float* x  = (const float*)d_in[0];
    const float* Wh = (const float*)d_in[1];
    const float* ah = (const float*)d_in[2];
    const float* Wo = (const float*)d_in[3];
    const float* ao = (const float*)d_in[4];
    float* out = (float*)d_out;

    __nv_bfloat16 *p_xh, *p_xl, *p_whh, *p_whl;
    float *p_h1, *p_ssrc1, *p_sdst1, *p_csort1, *p_sorted1, *p_Zhi1, *p_Zlo1, *p_Ze1, *p_Zg1;
    float *p_Chi1, *p_Clo1, *p_Phi1, *p_Plo1, *p_xc;
    int *p_idx1;
    float *p_h2, *p_ssrc2, *p_sdst2, *p_csort2, *p_sorted2, *p_Zhi2, *p_Zlo2, *p_Ze2, *p_Zg2;
    float *p_Chi2, *p_Clo2, *p_Phi2, *p_Plo2;
    int *p_idx2;

    cudaGetSymbolAddress((void**)&p_xh, g_xh);
    cudaGetSymbolAddress((void**)&p_xl, g_xl);
    cudaGetSymbolAddress((void**)&p_whh, g_whh);
    cudaGetSymbolAddress((void**)&p_whl, g_whl);
    cudaGetSymbolAddress((void**)&p_h1, g_h1);
    cudaGetSymbolAddress((void**)&p_ssrc1, g_ssrc1);
    cudaGetSymbolAddress((void**)&p_sdst1, g_sdst1);
    cudaGetSymbolAddress((void**)&p_csort1, g_csort1);
    cudaGetSymbolAddress((void**)&p_sorted1, g_sorted1);
    cudaGetSymbolAddress((void**)&p_idx1, g_idx1);
    cudaGetSymbolAddress((void**)&p_Zhi1, g_Zhi1);
    cudaGetSymbolAddress((void**)&p_Zlo1, g_Zlo1);
    cudaGetSymbolAddress((void**)&p_Ze1, g_Ze1);
    cudaGetSymbolAddress((void**)&p_Zg1, g_Zg1);
    cudaGetSymbolAddress((void**)&p_Chi1, g_Chi1);
    cudaGetSymbolAddress((void**)&p_Clo1, g_Clo1);
    cudaGetSymbolAddress((void**)&p_Phi1, g_Phi1);
    cudaGetSymbolAddress((void**)&p_Plo1, g_Plo1);
    cudaGetSymbolAddress((void**)&p_xc, g_xc);
    cudaGetSymbolAddress((void**)&p_h2, g_h2);
    cudaGetSymbolAddress((void**)&p_ssrc2, g_ssrc2);
    cudaGetSymbolAddress((void**)&p_sdst2, g_sdst2);
    cudaGetSymbolAddress((void**)&p_csort2, g_csort2);
    cudaGetSymbolAddress((void**)&p_sorted2, g_sorted2);
    cudaGetSymbolAddress((void**)&p_idx2, g_idx2);
    cudaGetSymbolAddress((void**)&p_Zhi2, g_Zhi2);
    cudaGetSymbolAddress((void**)&p_Zlo2, g_Zlo2);
    cudaGetSymbolAddress((void**)&p_Ze2, g_Ze2);
    cudaGetSymbolAddress((void**)&p_Zg2, g_Zg2);
    cudaGetSymbolAddress((void**)&p_Chi2, g_Chi2);
    cudaGetSymbolAddress((void**)&p_Clo2, g_Clo2);
    cudaGetSymbolAddress((void**)&p_Phi2, g_Phi2);
    cudaGetSymbolAddress((void**)&p_Plo2, g_Plo2);

    splitall_kernel<<<(NX4 + NW4 + 255) / 256, 256>>>(x, Wh, p_xh, p_xl, p_whh, p_whl);
    gemm1_mma_kernel<<<dim3(N_ROWS / 128, N_HEADS), 256>>>(p_xh, p_xl, p_whh, p_whl, ah,
                                                           p_h1, p_ssrc1, p_sdst1);
    megaL1_kernel<<<NB, 1024>>>(p_sdst1, p_csort1, p_sorted1, p_idx1,
                                p_Zhi1, p_Zlo1, p_Ze1, p_Zg1,
                                p_h1, p_Chi1, p_Clo1, p_Phi1, p_Plo1, p_ssrc1, p_xc);
    megaL2_kernel<<<NB, 1024>>>(p_xc, Wo, ao, p_h2, p_ssrc2, p_sdst2,
                                p_csort2, p_sorted2, p_idx2,
                                p_Zhi2, p_Zlo2, p_Ze2, p_Zg2,
                                p_Chi2, p_Clo2, p_Phi2, p_Plo2, out);

    (void)in_sizes; (void)n_in; (void)out_size;
}